// round 1
// baseline (speedup 1.0000x reference)
#include <cuda_runtime.h>
#include <math.h>

// ----------------------------------------------------------------------------
// AttModule: content/style cross-attention over bilateral-grid features.
//   c,s:  [2,16,256,256]   grid: [2,272,8,64,64] -> [2,2176,64,64]
//   out:  rs [2,2176,4096] = conv2176(grid) @ softmax(c1^T s1)^T
// Heavy stages: sr conv as implicit GEMM (M=2176,N=4096,K=2176*9) and
// rs GEMM (M=2176,N=4096,K=4096). fp32 baseline this round.
// ----------------------------------------------------------------------------

#define HW    4096          // 64*64 pixels
#define GC    2176          // grid channels
#define GP    66            // padded image side
#define GPP   (GP*GP)       // 4356

// ---- scratch (__device__ globals; no runtime allocation allowed) ----
static __device__ float d_h1[2*16*128*128];                 //   2 MB  branch temp
static __device__ float d_c1[2*16*HW];                      // 512 KB
static __device__ float d_s1[2*16*HW];                      // 512 KB
static __device__ float d_A  [(size_t)2*HW*HW];             // 134 MB  affinity / cs
static __device__ float d_pad[(size_t)2*GC*GPP];            //  76 MB  reflect-padded grid
static __device__ float d_Wt [(size_t)9*GC*GC];             // 170 MB  wsr as [tap][c][g]
static __device__ float d_sr [(size_t)2*GC*HW];             //  71 MB  conv output

// ----------------------------------------------------------------------------
// Small 16->16 3x3 conv, reflect pad 1, stride s, optional ReLU. Direct.
// ----------------------------------------------------------------------------
__global__ void conv16_kernel(const float* __restrict__ in,
                              const float* __restrict__ w,
                              const float* __restrict__ b,
                              float* __restrict__ out,
                              int Hin, int Hout, int stride, int relu)
{
    int idx = blockIdx.x * blockDim.x + threadIdx.x;
    int total = 2 * 16 * Hout * Hout;
    if (idx >= total) return;
    int ox = idx % Hout;
    int oy = (idx / Hout) % Hout;
    int oc = (idx / (Hout * Hout)) % 16;
    int n  = idx / (Hout * Hout * 16);

    const float* wp = w + oc * 16 * 9;
    const float* ip = in + (size_t)n * 16 * Hin * Hin;

    int iy[3], ix[3];
#pragma unroll
    for (int k = 0; k < 3; k++) {
        int y = oy * stride - 1 + k;
        iy[k] = (y < 0) ? 1 : ((y >= Hin) ? Hin - 2 : y);
        int x = ox * stride - 1 + k;
        ix[k] = (x < 0) ? 1 : ((x >= Hin) ? Hin - 2 : x);
    }

    float acc = b[oc];
    for (int ic = 0; ic < 16; ic++) {
        const float* ipc = ip + (size_t)ic * Hin * Hin;
        const float* wpc = wp + ic * 9;
#pragma unroll
        for (int ky = 0; ky < 3; ky++) {
            const float* row = ipc + (size_t)iy[ky] * Hin;
#pragma unroll
            for (int kx = 0; kx < 3; kx++)
                acc += wpc[ky * 3 + kx] * __ldg(row + ix[kx]);
        }
    }
    out[idx] = relu ? fmaxf(acc, 0.f) : acc;
}

// ----------------------------------------------------------------------------
// Affinity: A[n,i,j] = sum_c c1[n,c,i] * s1[n,c,j]   (K=16, write-bound)
// ----------------------------------------------------------------------------
__global__ void affinity_kernel(const float* __restrict__ c1,
                                const float* __restrict__ s1,
                                float* __restrict__ A)
{
    int j = blockIdx.x * 32 + threadIdx.x;
    int i = blockIdx.y * 8  + threadIdx.y;
    int n = blockIdx.z;
    const float* cp = c1 + (size_t)n * 16 * HW + i;
    const float* sp = s1 + (size_t)n * 16 * HW + j;
    float acc = 0.f;
#pragma unroll
    for (int k = 0; k < 16; k++)
        acc += cp[(size_t)k * HW] * sp[(size_t)k * HW];
    A[((size_t)n * HW + i) * HW + j] = acc;
}

// ----------------------------------------------------------------------------
// Row softmax over j (4096 per row), in place. One block per row.
// ----------------------------------------------------------------------------
__global__ void softmax_kernel(float* __restrict__ A)
{
    float* p = A + (size_t)blockIdx.x * HW;
    __shared__ float red[256];
    int t = threadIdx.x;

    float m = -INFINITY;
    for (int j = t; j < HW; j += 256) m = fmaxf(m, p[j]);
    red[t] = m; __syncthreads();
    for (int s = 128; s > 0; s >>= 1) {
        if (t < s) red[t] = fmaxf(red[t], red[t + s]);
        __syncthreads();
    }
    m = red[0]; __syncthreads();

    float sum = 0.f;
    for (int j = t; j < HW; j += 256) {
        float e = __expf(p[j] - m);
        p[j] = e;
        sum += e;
    }
    red[t] = sum; __syncthreads();
    for (int s = 128; s > 0; s >>= 1) {
        if (t < s) red[t] += red[t + s];
        __syncthreads();
    }
    float inv = 1.f / red[0];
    for (int j = t; j < HW; j += 256) p[j] *= inv;
}

// ----------------------------------------------------------------------------
// Reflect-pad grid [2,2176,64,64] -> [2,2176,66,66]
// ----------------------------------------------------------------------------
__global__ void pad_kernel(const float* __restrict__ g)
{
    size_t idx = (size_t)blockIdx.x * blockDim.x + threadIdx.x;
    size_t total = (size_t)2 * GC * GPP;
    if (idx >= total) return;
    int x  = (int)(idx % GP);
    int y  = (int)((idx / GP) % GP);
    size_t ch = idx / GPP;                 // fused n*GC + c
    int sy = y - 1; sy = (sy < 0) ? 1 : ((sy > 63) ? 62 : sy);
    int sx = x - 1; sx = (sx < 0) ? 1 : ((sx > 63) ? 62 : sx);
    d_pad[idx] = g[ch * HW + (size_t)sy * 64 + sx];
}

// ----------------------------------------------------------------------------
// Weight permute: wsr[g][c][tap] -> Wt[tap][c][g]  (coalesced both sides)
// Block handles a 32g x 32c x 9tap chunk via shared memory.
// ----------------------------------------------------------------------------
__global__ void wtrans_kernel(const float* __restrict__ wsr)
{
    __shared__ float sm[32][289];          // [g_local][c_local*9 + tap]
    int c0 = blockIdx.x * 32;
    int g0 = blockIdx.y * 32;
    int tid = threadIdx.x;

    // load: each g-row is 288 contiguous floats (32 c * 9 taps)
    for (int r = tid; r < 32 * 288; r += 256) {
        int gl  = r / 288;
        int off = r % 288;
        sm[gl][off] = wsr[((size_t)(g0 + gl) * GC + c0) * 9 + off];
    }
    __syncthreads();

    // store: Wt[tap][c0+cl][g0+gl], gl fastest -> coalesced
    for (int w = tid; w < 32 * 32 * 9; w += 256) {
        int gl  = w & 31;
        int cl  = (w >> 5) & 31;
        int tap = w >> 10;
        d_Wt[((size_t)tap * GC + c0 + cl) * GC + g0 + gl] = sm[gl][cl * 9 + tap];
    }
}

// ----------------------------------------------------------------------------
// sr conv as implicit GEMM:
//   sr[n,g,p] = bsr[g] + sum_tap sum_c Wt[tap][c][g] * pad[n,c,py+kh,px+kw]
// 128x128 tile per block, BK=8, 256 threads, 8x8 per thread (2x 4-wide halves)
// ----------------------------------------------------------------------------
__global__ __launch_bounds__(256) void conv_gemm_kernel(const float* __restrict__ bsr)
{
    const int n  = blockIdx.z;
    const int m0 = blockIdx.y * 128;
    const int p0 = blockIdx.x * 128;
    const int tid = threadIdx.x;
    const int tx = tid & 15;
    const int ty = tid >> 4;

    __shared__ float As[8][132];
    __shared__ float Bs[8][132];

    float acc[8][8];
#pragma unroll
    for (int i = 0; i < 8; i++)
#pragma unroll
        for (int j = 0; j < 8; j++) acc[i][j] = 0.f;

    const int lk = tid >> 5;          // 0..7  (k row within tile)
    const int lm = (tid & 31) * 4;    // 0..124 (4-wide column chunk)

    const float* padn = d_pad + (size_t)n * GC * GPP;
    const int p  = p0 + lm;
    const int py = p >> 6;
    const int px = p & 63;

    for (int tap = 0; tap < 9; tap++) {
        const int kh = tap / 3, kw = tap % 3;
        const float* Wtap  = d_Wt + (size_t)tap * GC * GC + m0;
        const float* Bbase = padn + (size_t)(py + kh) * GP + (px + kw);

        for (int c0 = 0; c0 < GC; c0 += 8) {
            const float* ap = Wtap + (size_t)(c0 + lk) * GC + lm;
            *(float4*)&As[lk][lm] = *(const float4*)ap;
            const float* bp = Bbase + (size_t)(c0 + lk) * GPP;
            Bs[lk][lm + 0] = bp[0];
            Bs[lk][lm + 1] = bp[1];
            Bs[lk][lm + 2] = bp[2];
            Bs[lk][lm + 3] = bp[3];
            __syncthreads();

#pragma unroll
            for (int kk = 0; kk < 8; kk++) {
                float4 a0 = *(float4*)&As[kk][ty * 4];
                float4 a1 = *(float4*)&As[kk][64 + ty * 4];
                float4 b0 = *(float4*)&Bs[kk][tx * 4];
                float4 b1 = *(float4*)&Bs[kk][64 + tx * 4];
                float a[8] = {a0.x, a0.y, a0.z, a0.w, a1.x, a1.y, a1.z, a1.w};
                float b[8] = {b0.x, b0.y, b0.z, b0.w, b1.x, b1.y, b1.z, b1.w};
#pragma unroll
                for (int i = 0; i < 8; i++)
#pragma unroll
                    for (int j = 0; j < 8; j++)
                        acc[i][j] += a[i] * b[j];
            }
            __syncthreads();
        }
    }

#pragma unroll
    for (int i = 0; i < 8; i++) {
        int m = m0 + ((i < 4) ? (ty * 4 + i) : (64 + ty * 4 + i - 4));
        float bias = bsr[m];
#pragma unroll
        for (int j = 0; j < 8; j++) {
            int pp = p0 + ((j < 4) ? (tx * 4 + j) : (64 + tx * 4 + j - 4));
            d_sr[((size_t)n * GC + m) * HW + pp] = acc[i][j] + bias;
        }
    }
}

// ----------------------------------------------------------------------------
// rs GEMM: out[n,g,i] = sum_j sr[n,g,j] * cs[n,i,j]   (both operands K-major)
// Same 128x128/BK=8 tiling; tiles transposed into SMEM on load.
// ----------------------------------------------------------------------------
__global__ __launch_bounds__(256) void rs_gemm_kernel(float* __restrict__ out)
{
    const int n  = blockIdx.z;
    const int m0 = blockIdx.y * 128;
    const int p0 = blockIdx.x * 128;
    const int tid = threadIdx.x;
    const int tx = tid & 15;
    const int ty = tid >> 4;

    __shared__ float As[8][132];
    __shared__ float Bs[8][132];

    float acc[8][8];
#pragma unroll
    for (int i = 0; i < 8; i++)
#pragma unroll
        for (int j = 0; j < 8; j++) acc[i][j] = 0.f;

    const int lr  = tid >> 1;         // 0..127 tile row
    const int lk4 = (tid & 1) * 4;    // 0 or 4

    const float* aP = d_sr + (size_t)n * GC * HW + (size_t)(m0 + lr) * HW + lk4;
    const float* bP = d_A  + (size_t)n * HW * HW + (size_t)(p0 + lr) * HW + lk4;

    for (int k0 = 0; k0 < HW; k0 += 8) {
        float4 av = *(const float4*)(aP + k0);
        float4 bv = *(const float4*)(bP + k0);
        As[lk4 + 0][lr] = av.x; As[lk4 + 1][lr] = av.y;
        As[lk4 + 2][lr] = av.z; As[lk4 + 3][lr] = av.w;
        Bs[lk4 + 0][lr] = bv.x; Bs[lk4 + 1][lr] = bv.y;
        Bs[lk4 + 2][lr] = bv.z; Bs[lk4 + 3][lr] = bv.w;
        __syncthreads();

#pragma unroll
        for (int kk = 0; kk < 8; kk++) {
            float4 a0 = *(float4*)&As[kk][ty * 4];
            float4 a1 = *(float4*)&As[kk][64 + ty * 4];
            float4 b0 = *(float4*)&Bs[kk][tx * 4];
            float4 b1 = *(float4*)&Bs[kk][64 + tx * 4];
            float a[8] = {a0.x, a0.y, a0.z, a0.w, a1.x, a1.y, a1.z, a1.w};
            float b[8] = {b0.x, b0.y, b0.z, b0.w, b1.x, b1.y, b1.z, b1.w};
#pragma unroll
            for (int i = 0; i < 8; i++)
#pragma unroll
                for (int j = 0; j < 8; j++)
                    acc[i][j] += a[i] * b[j];
        }
        __syncthreads();
    }

#pragma unroll
    for (int i = 0; i < 8; i++) {
        int m = m0 + ((i < 4) ? (ty * 4 + i) : (64 + ty * 4 + i - 4));
#pragma unroll
        for (int j = 0; j < 8; j++) {
            int pp = p0 + ((j < 4) ? (tx * 4 + j) : (64 + tx * 4 + j - 4));
            out[((size_t)n * GC + m) * HW + pp] = acc[i][j];
        }
    }
}

// ----------------------------------------------------------------------------
// launch
// ----------------------------------------------------------------------------
extern "C" void kernel_launch(void* const* d_in, const int* in_sizes, int n_in,
                              void* d_out, int out_size)
{
    const float* c    = (const float*)d_in[0];
    const float* s    = (const float*)d_in[1];
    const float* grid = (const float*)d_in[2];
    const float* wc1  = (const float*)d_in[3];
    const float* bc1  = (const float*)d_in[4];
    const float* wc2  = (const float*)d_in[5];
    const float* bc2  = (const float*)d_in[6];
    const float* ws1  = (const float*)d_in[7];
    const float* bs1  = (const float*)d_in[8];
    const float* ws2  = (const float*)d_in[9];
    const float* bs2  = (const float*)d_in[10];
    const float* wsr  = (const float*)d_in[11];
    const float* bsr  = (const float*)d_in[12];
    float* out = (float*)d_out;

    float *h1, *c1, *s1, *A;
    cudaGetSymbolAddress((void**)&h1, d_h1);
    cudaGetSymbolAddress((void**)&c1, d_c1);
    cudaGetSymbolAddress((void**)&s1, d_s1);
    cudaGetSymbolAddress((void**)&A,  d_A);

    // content branch
    conv16_kernel<<<(2*16*128*128 + 255) / 256, 256>>>(c,  wc1, bc1, h1, 256, 128, 2, 1);
    conv16_kernel<<<(2*16*64*64   + 255) / 256, 256>>>(h1, wc2, bc2, c1, 128, 64,  2, 0);
    // style branch (reuses h1 sequentially on the same stream)
    conv16_kernel<<<(2*16*128*128 + 255) / 256, 256>>>(s,  ws1, bs1, h1, 256, 128, 2, 1);
    conv16_kernel<<<(2*16*64*64   + 255) / 256, 256>>>(h1, ws2, bs2, s1, 128, 64,  2, 0);

    // affinity + softmax
    {
        dim3 b(32, 8), g(HW / 32, HW / 8, 2);
        affinity_kernel<<<g, b>>>(c1, s1, A);
    }
    softmax_kernel<<<2 * HW, 256>>>(A);

    // grid padding + weight permute
    pad_kernel<<<(int)(((size_t)2 * GC * GPP + 255) / 256), 256>>>(grid);
    {
        dim3 g(GC / 32, GC / 32);
        wtrans_kernel<<<g, 256>>>(wsr);
    }

    // heavy GEMMs
    {
        dim3 g(HW / 128, GC / 128, 2);
        conv_gemm_kernel<<<g, 256>>>(bsr);
        rs_gemm_kernel<<<g, 256>>>(out);
    }
}

// round 5
// speedup vs baseline: 2.1587x; 2.1587x over previous
#include <cuda_runtime.h>
#include <cuda_bf16.h>
#include <math.h>
#include <stdint.h>

// ============================================================================
// AttModule on B200 via legacy tensor cores (mma.sync bf16, sm_100-safe PTX).
//   GEMM1: sr[n,g,p] = sum_k wsr[g,k]*im2col[n,p,k] + bsr[g]   K=19584
//   GEMM2: out[n,g,i] = sum_j sr[n,g,j]*cs[n,i,j]              K=4096
// Both: D[m][nn] = sum_k A[m,k]*B[nn,k]; bf16 hi/lo split (3 MMA variants),
// fp32 accum. tcgen05 unavailable (harness compiles compute_100 virtual arch).
// ============================================================================

#define HW    4096
#define GC    2176
#define KC1   19584         // 2176*9
#define TILEB 10240         // 128 rows * 80B (32 bf16 padded to 40)
#define STGB  (4*TILEB)     // Ah,Al,Bh,Bl
#define NSTG  3
#define SMEM_DYN (NSTG*STGB)   // 122880; epilogue reuses as float[128][129]

// ---------------- scratch ----------------------------------------------------
static __device__ float          d_h1[2*16*128*128];
static __device__ float          d_c1[2*16*HW];
static __device__ float          d_s1[2*16*HW];
static __device__ float          d_A  [(size_t)2*HW*HW];
static __device__ __nv_bfloat16  d_csh[(size_t)2*HW*HW];
static __device__ __nv_bfloat16  d_csl[(size_t)2*HW*HW];
static __device__ __nv_bfloat16  d_imh[(size_t)2*HW*KC1];
static __device__ __nv_bfloat16  d_iml[(size_t)2*HW*KC1];
static __device__ __nv_bfloat16  d_wh [(size_t)GC*KC1];
static __device__ __nv_bfloat16  d_wl [(size_t)GC*KC1];
static __device__ __nv_bfloat16  d_srh[(size_t)2*GC*HW];
static __device__ __nv_bfloat16  d_srl[(size_t)2*GC*HW];

// ---------------- PTX helpers ------------------------------------------------
__device__ __forceinline__ uint32_t smem_u32(const void* p) {
    uint32_t a;
    asm("{ .reg .u64 t; cvta.to.shared.u64 t, %1; cvt.u32.u64 %0, t; }"
        : "=r"(a) : "l"(p));
    return a;
}

#define CP16(d, s) \
    asm volatile("cp.async.cg.shared.global [%0], [%1], 16;" :: "r"(d), "l"(s))
#define CP_COMMIT() asm volatile("cp.async.commit_group;" ::: "memory")
#define CP_WAIT2()  asm volatile("cp.async.wait_group 2;" ::: "memory")

#define LDSM4(r, addr) \
    asm volatile("ldmatrix.sync.aligned.m8n8.x4.shared.b16 {%0,%1,%2,%3}, [%4];" \
        : "=r"((r)[0]), "=r"((r)[1]), "=r"((r)[2]), "=r"((r)[3]) : "r"(addr))

#define MMA16816(d, a, b0, b1) \
    asm volatile("mma.sync.aligned.m16n8k16.row.col.f32.bf16.bf16.f32 " \
        "{%0,%1,%2,%3}, {%4,%5,%6,%7}, {%8,%9}, {%0,%1,%2,%3};" \
        : "+f"((d)[0]), "+f"((d)[1]), "+f"((d)[2]), "+f"((d)[3]) \
        : "r"((a)[0]), "r"((a)[1]), "r"((a)[2]), "r"((a)[3]), "r"(b0), "r"(b1))

__device__ __forceinline__ void split_bf16(float v, __nv_bfloat16& h, __nv_bfloat16& l) {
    h = __float2bfloat16(v);
    l = __float2bfloat16(v - __bfloat162float(h));
}

// ============================================================================
// prep kernels
// ============================================================================
__global__ void conv16_kernel(const float* __restrict__ in,
                              const float* __restrict__ w,
                              const float* __restrict__ b,
                              float* __restrict__ out,
                              int Hin, int Hout, int stride, int relu)
{
    int idx = blockIdx.x * blockDim.x + threadIdx.x;
    int total = 2 * 16 * Hout * Hout;
    if (idx >= total) return;
    int ox = idx % Hout;
    int oy = (idx / Hout) % Hout;
    int oc = (idx / (Hout * Hout)) % 16;
    int n  = idx / (Hout * Hout * 16);

    const float* wp = w + oc * 16 * 9;
    const float* ip = in + (size_t)n * 16 * Hin * Hin;

    int iy[3], ix[3];
#pragma unroll
    for (int k = 0; k < 3; k++) {
        int y = oy * stride - 1 + k;
        iy[k] = (y < 0) ? 1 : ((y >= Hin) ? Hin - 2 : y);
        int x = ox * stride - 1 + k;
        ix[k] = (x < 0) ? 1 : ((x >= Hin) ? Hin - 2 : x);
    }

    float acc = b[oc];
    for (int ic = 0; ic < 16; ic++) {
        const float* ipc = ip + (size_t)ic * Hin * Hin;
        const float* wpc = wp + ic * 9;
#pragma unroll
        for (int ky = 0; ky < 3; ky++) {
            const float* row = ipc + (size_t)iy[ky] * Hin;
#pragma unroll
            for (int kx = 0; kx < 3; kx++)
                acc += wpc[ky * 3 + kx] * __ldg(row + ix[kx]);
        }
    }
    out[idx] = relu ? fmaxf(acc, 0.f) : acc;
}

__global__ void affinity_kernel(const float* __restrict__ c1,
                                const float* __restrict__ s1,
                                float* __restrict__ A)
{
    int j = blockIdx.x * 32 + threadIdx.x;
    int i = blockIdx.y * 8  + threadIdx.y;
    int n = blockIdx.z;
    const float* cp = c1 + (size_t)n * 16 * HW + i;
    const float* sp = s1 + (size_t)n * 16 * HW + j;
    float acc = 0.f;
#pragma unroll
    for (int k = 0; k < 16; k++)
        acc += cp[(size_t)k * HW] * sp[(size_t)k * HW];
    A[((size_t)n * HW + i) * HW + j] = acc;
}

__global__ void softmax_kernel(float* __restrict__ A,
                               __nv_bfloat16* __restrict__ ch,
                               __nv_bfloat16* __restrict__ cl)
{
    float* p = A + (size_t)blockIdx.x * HW;
    __shared__ float red[256];
    int t = threadIdx.x;

    float m = -INFINITY;
    for (int j = t; j < HW; j += 256) m = fmaxf(m, p[j]);
    red[t] = m; __syncthreads();
    for (int s = 128; s > 0; s >>= 1) {
        if (t < s) red[t] = fmaxf(red[t], red[t + s]);
        __syncthreads();
    }
    m = red[0]; __syncthreads();

    float sum = 0.f;
    for (int j = t; j < HW; j += 256) {
        float e = __expf(p[j] - m);
        p[j] = e;
        sum += e;
    }
    red[t] = sum; __syncthreads();
    for (int s = 128; s > 0; s >>= 1) {
        if (t < s) red[t] += red[t + s];
        __syncthreads();
    }
    float inv = 1.f / red[0];
    size_t base = (size_t)blockIdx.x * HW;
    for (int j = t; j < HW; j += 256) {
        float v = p[j] * inv;
        __nv_bfloat16 h, l;
        split_bf16(v, h, l);
        ch[base + j] = h;
        cl[base + j] = l;
    }
}

__global__ void split_kernel(const float* __restrict__ in,
                             __nv_bfloat16* __restrict__ oh,
                             __nv_bfloat16* __restrict__ ol, long n)
{
    long i = (long)blockIdx.x * blockDim.x + threadIdx.x;
    if (i >= n) return;
    __nv_bfloat16 h, l;
    split_bf16(in[i], h, l);
    oh[i] = h; ol[i] = l;
}

__global__ void im2col_kernel(const float* __restrict__ g)
{
    long idx = (long)blockIdx.x * blockDim.x + threadIdx.x;
    if (idx >= (long)2 * HW * KC1) return;
    int k = (int)(idx % KC1);
    long pn = idx / KC1;
    int p = (int)(pn & 4095);
    int n = (int)(pn >> 12);
    int c = k / 9;
    int tap = k - c * 9;
    int ky = tap / 3, kx = tap - ky * 3;
    int py = p >> 6, px = p & 63;
    int sy = py + ky - 1; sy = (sy < 0) ? 1 : ((sy > 63) ? 62 : sy);
    int sx = px + kx - 1; sx = (sx < 0) ? 1 : ((sx > 63) ? 62 : sx);
    float v = g[(((size_t)n * GC + c) << 12) + (sy << 6) + sx];
    __nv_bfloat16 h, l;
    split_bf16(v, h, l);
    d_imh[idx] = h; d_iml[idx] = l;
}

// ============================================================================
// mma.sync split-bf16 GEMM. 256 thr = 8 warps (2m x 4n), warp tile 64x32.
// Block 128x128, BK=32, 3-stage cp.async. SMEM tiles [128][40 halves] (80B).
// ============================================================================
__global__ __launch_bounds__(256, 1) void gemm_mma_kernel(
    const __nv_bfloat16* __restrict__ Ah, const __nv_bfloat16* __restrict__ Al,
    const __nv_bfloat16* __restrict__ Bh, const __nv_bfloat16* __restrict__ Bl,
    size_t a_rowb, size_t a_zb, size_t b_rowb, size_t b_zb,
    int nk, const float* __restrict__ bias,
    __nv_bfloat16* __restrict__ oh, __nv_bfloat16* __restrict__ ol,
    float* __restrict__ of)
{
    extern __shared__ char smraw[];
    const uint32_t smb = smem_u32(smraw);
    const int tid  = threadIdx.x;
    const int wid  = tid >> 5;
    const int lane = tid & 31;
    const int nn0  = blockIdx.x * 128;
    const int m0   = blockIdx.y * 128;
    const int nz   = blockIdx.z;

    // ---- cp.async slices: thread loads rows (tid>>2) and (tid>>2)+64 --------
    const int cr = tid >> 2;
    const int cc = (tid & 3) * 16;               // byte col within 64B row
    const char* pAh = (const char*)Ah;
    const char* pAl = (const char*)Al;
    const char* pBh = (const char*)Bh;
    const char* pBl = (const char*)Bl;
    const size_t aoff0 = (size_t)(m0 + cr)  * a_rowb + (size_t)nz * a_zb + cc;
    const size_t aoff1 = aoff0 + 64 * a_rowb;
    const size_t boff0 = (size_t)(nn0 + cr) * b_rowb + (size_t)nz * b_zb + cc;
    const size_t boff1 = boff0 + 64 * b_rowb;
    const uint32_t dd0 = (uint32_t)(cr * 80 + cc);
    const uint32_t dd1 = dd0 + 64 * 80;

#define ISSUE(t) do {                                                   \
        uint32_t sb_ = smb + ((t) % NSTG) * STGB;                        \
        size_t kb_ = (size_t)(t) * 64;                                   \
        CP16(sb_ + dd0,             pAh + aoff0 + kb_);                  \
        CP16(sb_ + dd1,             pAh + aoff1 + kb_);                  \
        CP16(sb_ + TILEB + dd0,     pAl + aoff0 + kb_);                  \
        CP16(sb_ + TILEB + dd1,     pAl + aoff1 + kb_);                  \
        CP16(sb_ + 2*TILEB + dd0,   pBh + boff0 + kb_);                  \
        CP16(sb_ + 2*TILEB + dd1,   pBh + boff1 + kb_);                  \
        CP16(sb_ + 3*TILEB + dd0,   pBl + boff0 + kb_);                  \
        CP16(sb_ + 3*TILEB + dd1,   pBl + boff1 + kb_);                  \
    } while (0)

    // ---- ldmatrix lane offsets ---------------------------------------------
    const int mbase = (wid >> 2) * 64;           // warp M origin
    const int nb    = (wid & 3) * 32;            // warp N origin
    const uint32_t aoffL = (uint32_t)((mbase + (lane & 15)) * 80 + (lane >> 4) * 16);
    const uint32_t boffL = (uint32_t)((nb + ((lane >> 4) * 8) + (lane & 7)) * 80
                                      + ((lane >> 3) & 1) * 16);

    float acc[4][4][4];
#pragma unroll
    for (int i = 0; i < 4; i++)
#pragma unroll
        for (int j = 0; j < 4; j++)
#pragma unroll
            for (int r = 0; r < 4; r++) acc[i][j][r] = 0.f;

    ISSUE(0); CP_COMMIT();
    ISSUE(1); CP_COMMIT();

    for (int t = 0; t < nk; t++) {
        if (t + 2 < nk) ISSUE(t + 2);
        CP_COMMIT();
        CP_WAIT2();
        __syncthreads();

        const uint32_t sb  = smb + (t % NSTG) * STGB;
        const uint32_t AhT = sb,             AlT = sb + TILEB;
        const uint32_t BhT = sb + 2 * TILEB, BlT = sb + 3 * TILEB;

#pragma unroll
        for (int ks = 0; ks < 2; ks++) {
            const uint32_t kb = ks * 32;
            uint32_t aH[16], aL[16], bH[8], bL[8];
#pragma unroll
            for (int i = 0; i < 4; i++) {
                LDSM4(aH + 4 * i, AhT + aoffL + i * 1280 + kb);
                LDSM4(aL + 4 * i, AlT + aoffL + i * 1280 + kb);
            }
#pragma unroll
            for (int jp = 0; jp < 2; jp++) {
                LDSM4(bH + 4 * jp, BhT + boffL + jp * 1280 + kb);
                LDSM4(bL + 4 * jp, BlT + boffL + jp * 1280 + kb);
            }
#pragma unroll
            for (int i = 0; i < 4; i++)
#pragma unroll
                for (int j = 0; j < 4; j++) {
                    MMA16816(acc[i][j], aH + 4 * i, bH[j * 2], bH[j * 2 + 1]);
                    MMA16816(acc[i][j], aH + 4 * i, bL[j * 2], bL[j * 2 + 1]);
                    MMA16816(acc[i][j], aL + 4 * i, bH[j * 2], bH[j * 2 + 1]);
                }
        }
        __syncthreads();
    }

    // ---- epilogue: transpose through SMEM, coalesced [g][p] stores ---------
    float* smf = (float*)smraw;                  // [128][129]
    const int g4 = lane >> 2, tq = lane & 3;
#pragma unroll
    for (int i = 0; i < 4; i++) {
        int m = mbase + i * 16 + g4;
#pragma unroll
        for (int j = 0; j < 4; j++) {
            int col = nb + j * 8 + tq * 2;
            smf[m * 129 + col]           = acc[i][j][0];
            smf[m * 129 + col + 1]       = acc[i][j][1];
            smf[(m + 8) * 129 + col]     = acc[i][j][2];
            smf[(m + 8) * 129 + col + 1] = acc[i][j][3];
        }
    }
    __syncthreads();

    const int g  = tid >> 1;                     // 0..127 output row (n dim)
    const int ph = (tid & 1) * 64;               // pixel half
    const float bv = bias ? bias[nn0 + g] : 0.f;
    const size_t orow = ((size_t)nz * GC + nn0 + g) * HW + m0 + ph;

    if (of) {
#pragma unroll 1
        for (int pc = 0; pc < 8; pc++) {
            float4 v0, v1;
            v0.x = smf[(ph + pc * 8 + 0) * 129 + g];
            v0.y = smf[(ph + pc * 8 + 1) * 129 + g];
            v0.z = smf[(ph + pc * 8 + 2) * 129 + g];
            v0.w = smf[(ph + pc * 8 + 3) * 129 + g];
            v1.x = smf[(ph + pc * 8 + 4) * 129 + g];
            v1.y = smf[(ph + pc * 8 + 5) * 129 + g];
            v1.z = smf[(ph + pc * 8 + 6) * 129 + g];
            v1.w = smf[(ph + pc * 8 + 7) * 129 + g];
            *(float4*)(of + orow + pc * 8)     = v0;
            *(float4*)(of + orow + pc * 8 + 4) = v1;
        }
    } else {
#pragma unroll 1
        for (int pc = 0; pc < 8; pc++) {
            uint32_t ph4[4], pl4[4];
#pragma unroll
            for (int q = 0; q < 4; q++) {
                float va = smf[(ph + pc * 8 + q * 2 + 0) * 129 + g] + bv;
                float vb = smf[(ph + pc * 8 + q * 2 + 1) * 129 + g] + bv;
                __nv_bfloat16 ha, la, hb, lb;
                split_bf16(va, ha, la);
                split_bf16(vb, hb, lb);
                ph4[q] = (uint32_t)__bfloat16_as_ushort(ha)
                       | ((uint32_t)__bfloat16_as_ushort(hb) << 16);
                pl4[q] = (uint32_t)__bfloat16_as_ushort(la)
                       | ((uint32_t)__bfloat16_as_ushort(lb) << 16);
            }
            *(uint4*)(oh + orow + pc * 8) = *(uint4*)ph4;
            *(uint4*)(ol + orow + pc * 8) = *(uint4*)pl4;
        }
    }
#undef ISSUE
}

// ============================================================================
// launch
// ============================================================================
extern "C" void kernel_launch(void* const* d_in, const int* in_sizes, int n_in,
                              void* d_out, int out_size)
{
    const float* c    = (const float*)d_in[0];
    const float* s    = (const float*)d_in[1];
    const float* grid = (const float*)d_in[2];
    const float* wc1  = (const float*)d_in[3];
    const float* bc1  = (const float*)d_in[4];
    const float* wc2  = (const float*)d_in[5];
    const float* bc2  = (const float*)d_in[6];
    const float* ws1  = (const float*)d_in[7];
    const float* bs1  = (const float*)d_in[8];
    const float* ws2  = (const float*)d_in[9];
    const float* bs2  = (const float*)d_in[10];
    const float* wsr  = (const float*)d_in[11];
    const float* bsr  = (const float*)d_in[12];
    float* out = (float*)d_out;

    float *h1, *c1, *s1, *A;
    __nv_bfloat16 *csh, *csl, *imh, *iml, *wh, *wl, *srh, *srl;
    cudaGetSymbolAddress((void**)&h1,  d_h1);
    cudaGetSymbolAddress((void**)&c1,  d_c1);
    cudaGetSymbolAddress((void**)&s1,  d_s1);
    cudaGetSymbolAddress((void**)&A,   d_A);
    cudaGetSymbolAddress((void**)&csh, d_csh);
    cudaGetSymbolAddress((void**)&csl, d_csl);
    cudaGetSymbolAddress((void**)&imh, d_imh);
    cudaGetSymbolAddress((void**)&iml, d_iml);
    cudaGetSymbolAddress((void**)&wh,  d_wh);
    cudaGetSymbolAddress((void**)&wl,  d_wl);
    cudaGetSymbolAddress((void**)&srh, d_srh);
    cudaGetSymbolAddress((void**)&srl, d_srl);

    cudaFuncSetAttribute(gemm_mma_kernel,
                         cudaFuncAttributeMaxDynamicSharedMemorySize, SMEM_DYN);

    // branches
    conv16_kernel<<<(2*16*128*128 + 255) / 256, 256>>>(c,  wc1, bc1, h1, 256, 128, 2, 1);
    conv16_kernel<<<(2*16*64*64   + 255) / 256, 256>>>(h1, wc2, bc2, c1, 128, 64,  2, 0);
    conv16_kernel<<<(2*16*128*128 + 255) / 256, 256>>>(s,  ws1, bs1, h1, 256, 128, 2, 1);
    conv16_kernel<<<(2*16*64*64   + 255) / 256, 256>>>(h1, ws2, bs2, s1, 128, 64,  2, 0);

    // affinity + softmax
    {
        dim3 b(32, 8), g(HW / 32, HW / 8, 2);
        affinity_kernel<<<g, b>>>(c1, s1, A);
    }
    softmax_kernel<<<2 * HW, 256>>>(A, csh, csl);

    // operand prep
    {
        long nw = (long)GC * KC1;
        split_kernel<<<(unsigned)((nw + 255) / 256), 256>>>(wsr, wh, wl, nw);
        long ni = (long)2 * HW * KC1;
        im2col_kernel<<<(unsigned)((ni + 255) / 256), 256>>>(grid);
    }

    // GEMM1: sr = im2col @ wsr^T + bsr -> bf16 hi/lo [g][p]
    {
        dim3 g(GC / 128, HW / 128, 2);
        gemm_mma_kernel<<<g, 256, SMEM_DYN>>>(
            imh, iml, wh, wl,
            (size_t)KC1 * 2, (size_t)HW * KC1 * 2,
            (size_t)KC1 * 2, (size_t)0,
            KC1 / 32, bsr, srh, srl, nullptr);
    }
    // GEMM2: out = cs @ sr^T -> fp32 [g][i]
    {
        dim3 g(GC / 128, HW / 128, 2);
        gemm_mma_kernel<<<g, 256, SMEM_DYN>>>(
            csh, csl, srh, srl,
            (size_t)HW * 2, (size_t)HW * HW * 2,
            (size_t)HW * 2, (size_t)GC * HW * 2,
            HW / 32, nullptr, nullptr, nullptr, out);
    }
}

// round 6
// speedup vs baseline: 3.3155x; 1.5359x over previous
#include <cuda_runtime.h>
#include <cuda_bf16.h>
#include <math.h>
#include <stdint.h>

// ============================================================================
// AttModule (sm_100-safe PTX, legacy tensor cores).
//   GEMM1 (conv-as-GEMM, K=19584): int8 two-word split, mma.m16n8k32.s8
//        D = sA*sB*(65536*acc_hh + 256*(acc_hl+acc_lh))   [3 IMMA per k32]
//   GEMM2 (K=4096): bf16 hi/lo split, mma.m16n8k16.bf16   [3 HMMA per k16]
// GEMM1 per-row scales: A rows (pixels) = 3x3-neighborhood channel max of
// grid; B rows (g) = weight row max.  q15 = 256*q_hi + q_lo.
// ============================================================================

#define HW    4096
#define GC    2176
#define KC1   19584          // 2176*9
#define QMAX  32512.0f       // 127*256

// bf16 GEMM2 smem geometry
#define TILEB 10240          // 128 rows * 80B (32 bf16 padded)
#define STGB  (4*TILEB)
#define NSTG  3
#define SMEM_DYN (NSTG*STGB) // 122880

// int8 GEMM1 smem geometry (same total)
#define TILE8 10240          // 128 rows * 80B (64 s8 padded)
#define STG8  (4*TILE8)

// ---------------- scratch ----------------------------------------------------
static __device__ float          d_h1[2*16*128*128];
static __device__ float          d_c1[2*16*HW];
static __device__ float          d_s1[2*16*HW];
static __device__ float          d_A  [(size_t)2*HW*HW];
static __device__ __nv_bfloat16  d_csh[(size_t)2*HW*HW];
static __device__ __nv_bfloat16  d_csl[(size_t)2*HW*HW];
static __device__ __nv_bfloat16  d_srh[(size_t)2*GC*HW];
static __device__ __nv_bfloat16  d_srl[(size_t)2*GC*HW];
// int8 GEMM1 operands
static __device__ int8_t         d_imqh[(size_t)2*HW*KC1];
static __device__ int8_t         d_imql[(size_t)2*HW*KC1];
static __device__ int8_t         d_wqh [(size_t)GC*KC1];
static __device__ int8_t         d_wql [(size_t)GC*KC1];
static __device__ float          d_cmax[2*HW];
static __device__ float          d_asc [2*HW];     // per (n,p) scale
static __device__ float          d_wsc [GC];       // per g scale

// ---------------- PTX helpers ------------------------------------------------
__device__ __forceinline__ uint32_t smem_u32(const void* p) {
    uint32_t a;
    asm("{ .reg .u64 t; cvta.to.shared.u64 t, %1; cvt.u32.u64 %0, t; }"
        : "=r"(a) : "l"(p));
    return a;
}

#define CP16(d, s) \
    asm volatile("cp.async.cg.shared.global [%0], [%1], 16;" :: "r"(d), "l"(s))
#define CP_COMMIT() asm volatile("cp.async.commit_group;" ::: "memory")
#define CP_WAIT2()  asm volatile("cp.async.wait_group 2;" ::: "memory")

#define LDSM4(r, addr) \
    asm volatile("ldmatrix.sync.aligned.m8n8.x4.shared.b16 {%0,%1,%2,%3}, [%4];" \
        : "=r"((r)[0]), "=r"((r)[1]), "=r"((r)[2]), "=r"((r)[3]) : "r"(addr))

#define MMA16816(d, a, b0, b1) \
    asm volatile("mma.sync.aligned.m16n8k16.row.col.f32.bf16.bf16.f32 " \
        "{%0,%1,%2,%3}, {%4,%5,%6,%7}, {%8,%9}, {%0,%1,%2,%3};" \
        : "+f"((d)[0]), "+f"((d)[1]), "+f"((d)[2]), "+f"((d)[3]) \
        : "r"((a)[0]), "r"((a)[1]), "r"((a)[2]), "r"((a)[3]), "r"(b0), "r"(b1))

#define MMAS8(d, a, b0, b1) \
    asm volatile("mma.sync.aligned.m16n8k32.row.col.s32.s8.s8.s32 " \
        "{%0,%1,%2,%3}, {%4,%5,%6,%7}, {%8,%9}, {%0,%1,%2,%3};" \
        : "+r"((d)[0]), "+r"((d)[1]), "+r"((d)[2]), "+r"((d)[3]) \
        : "r"((a)[0]), "r"((a)[1]), "r"((a)[2]), "r"((a)[3]), "r"(b0), "r"(b1))

__device__ __forceinline__ void split_bf16(float v, __nv_bfloat16& h, __nv_bfloat16& l) {
    h = __float2bfloat16(v);
    l = __float2bfloat16(v - __bfloat162float(h));
}

// ============================================================================
// prep kernels
// ============================================================================
__global__ void conv16_kernel(const float* __restrict__ in,
                              const float* __restrict__ w,
                              const float* __restrict__ b,
                              float* __restrict__ out,
                              int Hin, int Hout, int stride, int relu)
{
    int idx = blockIdx.x * blockDim.x + threadIdx.x;
    int total = 2 * 16 * Hout * Hout;
    if (idx >= total) return;
    int ox = idx % Hout;
    int oy = (idx / Hout) % Hout;
    int oc = (idx / (Hout * Hout)) % 16;
    int n  = idx / (Hout * Hout * 16);

    const float* wp = w + oc * 16 * 9;
    const float* ip = in + (size_t)n * 16 * Hin * Hin;

    int iy[3], ix[3];
#pragma unroll
    for (int k = 0; k < 3; k++) {
        int y = oy * stride - 1 + k;
        iy[k] = (y < 0) ? 1 : ((y >= Hin) ? Hin - 2 : y);
        int x = ox * stride - 1 + k;
        ix[k] = (x < 0) ? 1 : ((x >= Hin) ? Hin - 2 : x);
    }

    float acc = b[oc];
    for (int ic = 0; ic < 16; ic++) {
        const float* ipc = ip + (size_t)ic * Hin * Hin;
        const float* wpc = wp + ic * 9;
#pragma unroll
        for (int ky = 0; ky < 3; ky++) {
            const float* row = ipc + (size_t)iy[ky] * Hin;
#pragma unroll
            for (int kx = 0; kx < 3; kx++)
                acc += wpc[ky * 3 + kx] * __ldg(row + ix[kx]);
        }
    }
    out[idx] = relu ? fmaxf(acc, 0.f) : acc;
}

__global__ void affinity_kernel(const float* __restrict__ c1,
                                const float* __restrict__ s1,
                                float* __restrict__ A)
{
    int j = blockIdx.x * 32 + threadIdx.x;
    int i = blockIdx.y * 8  + threadIdx.y;
    int n = blockIdx.z;
    const float* cp = c1 + (size_t)n * 16 * HW + i;
    const float* sp = s1 + (size_t)n * 16 * HW + j;
    float acc = 0.f;
#pragma unroll
    for (int k = 0; k < 16; k++)
        acc += cp[(size_t)k * HW] * sp[(size_t)k * HW];
    A[((size_t)n * HW + i) * HW + j] = acc;
}

__global__ void softmax_kernel(float* __restrict__ A,
                               __nv_bfloat16* __restrict__ ch,
                               __nv_bfloat16* __restrict__ cl)
{
    float* p = A + (size_t)blockIdx.x * HW;
    __shared__ float red[256];
    int t = threadIdx.x;

    float m = -INFINITY;
    for (int j = t; j < HW; j += 256) m = fmaxf(m, p[j]);
    red[t] = m; __syncthreads();
    for (int s = 128; s > 0; s >>= 1) {
        if (t < s) red[t] = fmaxf(red[t], red[t + s]);
        __syncthreads();
    }
    m = red[0]; __syncthreads();

    float sum = 0.f;
    for (int j = t; j < HW; j += 256) {
        float e = __expf(p[j] - m);
        p[j] = e;
        sum += e;
    }
    red[t] = sum; __syncthreads();
    for (int s = 128; s > 0; s >>= 1) {
        if (t < s) red[t] += red[t + s];
        __syncthreads();
    }
    float inv = 1.f / red[0];
    size_t base = (size_t)blockIdx.x * HW;
    for (int j = t; j < HW; j += 256) {
        float v = p[j] * inv;
        __nv_bfloat16 h, l;
        split_bf16(v, h, l);
        ch[base + j] = h;
        cl[base + j] = l;
    }
}

// per-pixel channel max of |grid|
__global__ void chanmax_kernel(const float* __restrict__ g)
{
    int idx = blockIdx.x * blockDim.x + threadIdx.x;
    if (idx >= 2 * HW) return;
    int n = idx >> 12, p = idx & 4095;
    const float* base = g + (size_t)n * GC * HW + p;
    float m = 0.f;
    for (int c = 0; c < GC; c++) m = fmaxf(m, fabsf(base[(size_t)c * HW]));
    d_cmax[idx] = m;
}

// 3x3 reflect-neighborhood max -> per-row quant scale
__global__ void amax3_kernel()
{
    int idx = blockIdx.x * blockDim.x + threadIdx.x;
    if (idx >= 2 * HW) return;
    int n = idx >> 12, py = (idx >> 6) & 63, px = idx & 63;
    float m = 0.f;
#pragma unroll
    for (int dy = 0; dy < 3; dy++) {
        int y = py + dy - 1; y = (y < 0) ? 1 : ((y > 63) ? 62 : y);
#pragma unroll
        for (int dx = 0; dx < 3; dx++) {
            int x = px + dx - 1; x = (x < 0) ? 1 : ((x > 63) ? 62 : x);
            m = fmaxf(m, d_cmax[(n << 12) + (y << 6) + x]);
        }
    }
    d_asc[idx] = m / QMAX;
}

// weight row max + scale
__global__ void wmax_kernel(const float* __restrict__ w)
{
    int g = blockIdx.x;
    __shared__ float red[256];
    int t = threadIdx.x;
    const float* row = w + (size_t)g * KC1;
    float m = 0.f;
    for (int k = t; k < KC1; k += 256) m = fmaxf(m, fabsf(row[k]));
    red[t] = m; __syncthreads();
    for (int s = 128; s > 0; s >>= 1) {
        if (t < s) red[t] = fmaxf(red[t], red[t + s]);
        __syncthreads();
    }
    if (t == 0) d_wsc[g] = red[0] / QMAX;
}

__device__ __forceinline__ void q15(float v, float inv, int8_t& qh, int8_t& ql)
{
    int q = __float2int_rn(v * inv);
    q = max(-32512, min(32512, q));
    int ah = (q + 128) >> 8;
    qh = (int8_t)ah;
    ql = (int8_t)(q - (ah << 8));
}

__global__ void wquant_kernel(const float* __restrict__ w)
{
    int g = blockIdx.x;
    float s = d_wsc[g];
    float inv = (s > 0.f) ? 1.f / s : 0.f;
    const float* row = w + (size_t)g * KC1;
    for (int k = threadIdx.x; k < KC1; k += 256) {
        int8_t qh, ql;
        q15(row[k], inv, qh, ql);
        d_wqh[(size_t)g * KC1 + k] = qh;
        d_wql[(size_t)g * KC1 + k] = ql;
    }
}

// im2col with reflect pad, emitting int8 hi/lo: A[n][p][k=c*9+tap]
__global__ void im2col_q_kernel(const float* __restrict__ g)
{
    long idx = (long)blockIdx.x * blockDim.x + threadIdx.x;
    if (idx >= (long)2 * HW * KC1) return;
    int k = (int)(idx % KC1);
    long pn = idx / KC1;
    int p = (int)(pn & 4095);
    int n = (int)(pn >> 12);
    int c = k / 9;
    int tap = k - c * 9;
    int ky = tap / 3, kx = tap - ky * 3;
    int py = p >> 6, px = p & 63;
    int sy = py + ky - 1; sy = (sy < 0) ? 1 : ((sy > 63) ? 62 : sy);
    int sx = px + kx - 1; sx = (sx < 0) ? 1 : ((sx > 63) ? 62 : sx);
    float v = g[(((size_t)n * GC + c) << 12) + (sy << 6) + sx];
    float s = d_asc[(n << 12) + p];
    float inv = (s > 0.f) ? 1.f / s : 0.f;
    int8_t qh, ql;
    q15(v, inv, qh, ql);
    d_imqh[idx] = qh;
    d_imql[idx] = ql;
}

// ============================================================================
// GEMM1: int8 split. 512 thr = 16 warps (4m x 4n), warp tile 32x32, BK=64.
// ============================================================================
__global__ __launch_bounds__(512, 1) void gemm_s8_kernel(
    const float* __restrict__ bias,
    __nv_bfloat16* __restrict__ oh, __nv_bfloat16* __restrict__ ol)
{
    extern __shared__ char smraw[];
    const uint32_t smb = smem_u32(smraw);
    const int tid  = threadIdx.x;
    const int wid  = tid >> 5;
    const int lane = tid & 31;
    const int nn0  = blockIdx.x * 128;       // g tile
    const int m0   = blockIdx.y * 128;       // pixel tile
    const int nz   = blockIdx.z;
    const int nk   = KC1 / 64;               // 306

    // cp.async: thread -> row tid>>2, 16B chunk tid&3
    const int cr = tid >> 2;
    const int cc = (tid & 3) * 16;
    const char* pAh = (const char*)d_imqh;
    const char* pAl = (const char*)d_imql;
    const char* pBh = (const char*)d_wqh;
    const char* pBl = (const char*)d_wql;
    const size_t aoff = (size_t)(m0 + cr) * KC1 + (size_t)nz * HW * KC1 + cc;
    const size_t boff = (size_t)(nn0 + cr) * KC1 + cc;
    const uint32_t dd = (uint32_t)(cr * 80 + cc);

#define ISSUE8(t) do {                                               \
        uint32_t sb_ = smb + ((t) % NSTG) * STG8;                    \
        size_t kb_ = (size_t)(t) * 64;                               \
        CP16(sb_ + dd,             pAh + aoff + kb_);                \
        CP16(sb_ + TILE8 + dd,     pAl + aoff + kb_);                \
        CP16(sb_ + 2*TILE8 + dd,   pBh + boff + kb_);                \
        CP16(sb_ + 3*TILE8 + dd,   pBl + boff + kb_);                \
    } while (0)

    const int wm = wid >> 2;                 // 0..3
    const int wn = wid & 3;                  // 0..3
    const uint32_t aoffL = (uint32_t)((wm * 32 + (lane & 15)) * 80 + (lane >> 4) * 16);
    const uint32_t boffL = (uint32_t)((wn * 32 + ((lane >> 4) << 3) + (lane & 7)) * 80
                                      + ((lane >> 3) & 1) * 16);

    int acc1[2][4][4], acc2[2][4][4];
#pragma unroll
    for (int i = 0; i < 2; i++)
#pragma unroll
        for (int j = 0; j < 4; j++)
#pragma unroll
            for (int r = 0; r < 4; r++) { acc1[i][j][r] = 0; acc2[i][j][r] = 0; }

    ISSUE8(0); CP_COMMIT();
    ISSUE8(1); CP_COMMIT();

    for (int t = 0; t < nk; t++) {
        if (t + 2 < nk) ISSUE8(t + 2);
        CP_COMMIT();
        CP_WAIT2();
        __syncthreads();

        const uint32_t sb  = smb + (t % NSTG) * STG8;
        const uint32_t AhT = sb,             AlT = sb + TILE8;
        const uint32_t BhT = sb + 2 * TILE8, BlT = sb + 3 * TILE8;

#pragma unroll
        for (int ks = 0; ks < 2; ks++) {
            const uint32_t kb = ks * 32;
            uint32_t aH[8], aL[8], bH[8], bL[8];
            LDSM4(aH,     AhT + aoffL + kb);
            LDSM4(aH + 4, AhT + aoffL + 16 * 80 + kb);
            LDSM4(aL,     AlT + aoffL + kb);
            LDSM4(aL + 4, AlT + aoffL + 16 * 80 + kb);
            LDSM4(bH,     BhT + boffL + kb);
            LDSM4(bH + 4, BhT + boffL + 16 * 80 + kb);
            LDSM4(bL,     BlT + boffL + kb);
            LDSM4(bL + 4, BlT + boffL + 16 * 80 + kb);
#pragma unroll
            for (int i = 0; i < 2; i++)
#pragma unroll
                for (int j = 0; j < 4; j++) {
                    MMAS8(acc1[i][j], aH + 4 * i, bH[2 * j], bH[2 * j + 1]);
                    MMAS8(acc2[i][j], aH + 4 * i, bL[2 * j], bL[2 * j + 1]);
                    MMAS8(acc2[i][j], aL + 4 * i, bH[2 * j], bH[2 * j + 1]);
                }
        }
        __syncthreads();
    }

    // ---- epilogue: dequant, transpose through SMEM, coalesced [g][p] stores -
    float* smf = (float*)smraw;              // [128][129]
    const float* asb = d_asc + (nz << 12) + m0;
    const float* wsb = d_wsc + nn0;
#pragma unroll
    for (int i = 0; i < 2; i++) {
        int m = wm * 32 + i * 16 + (lane >> 2);
        float sa0 = asb[m], sa1 = asb[m + 8];
#pragma unroll
        for (int j = 0; j < 4; j++) {
            int col = wn * 32 + j * 8 + 2 * (lane & 3);
            float w0 = wsb[col], w1 = wsb[col + 1];
            float v0 = fmaf(65536.f, (float)acc1[i][j][0], 256.f * (float)acc2[i][j][0]);
            float v1 = fmaf(65536.f, (float)acc1[i][j][1], 256.f * (float)acc2[i][j][1]);
            float v2 = fmaf(65536.f, (float)acc1[i][j][2], 256.f * (float)acc2[i][j][2]);
            float v3 = fmaf(65536.f, (float)acc1[i][j][3], 256.f * (float)acc2[i][j][3]);
            smf[m * 129 + col]           = sa0 * w0 * v0;
            smf[m * 129 + col + 1]       = sa0 * w1 * v1;
            smf[(m + 8) * 129 + col]     = sa1 * w0 * v2;
            smf[(m + 8) * 129 + col + 1] = sa1 * w1 * v3;
        }
    }
    __syncthreads();

    const int g  = tid >> 2;                 // output row (g)
    const int q  = tid & 3;                  // pixel quarter (32 px)
    const float bv = bias[nn0 + g];
    const size_t orow = ((size_t)nz * GC + nn0 + g) * HW + m0 + q * 32;
#pragma unroll 1
    for (int pc = 0; pc < 4; pc++) {
        uint32_t ph4[4], pl4[4];
#pragma unroll
        for (int e = 0; e < 4; e++) {
            float va = smf[(q * 32 + pc * 8 + e * 2 + 0) * 129 + g] + bv;
            float vb = smf[(q * 32 + pc * 8 + e * 2 + 1) * 129 + g] + bv;
            __nv_bfloat16 ha, la, hb, lb;
            split_bf16(va, ha, la);
            split_bf16(vb, hb, lb);
            ph4[e] = (uint32_t)__bfloat16_as_ushort(ha)
                   | ((uint32_t)__bfloat16_as_ushort(hb) << 16);
            pl4[e] = (uint32_t)__bfloat16_as_ushort(la)
                   | ((uint32_t)__bfloat16_as_ushort(lb) << 16);
        }
        *(uint4*)(oh + orow + pc * 8) = *(uint4*)ph4;
        *(uint4*)(ol + orow + pc * 8) = *(uint4*)pl4;
    }
#undef ISSUE8
}

// ============================================================================
// GEMM2: bf16 split (proven R5 kernel). 256 thr = 8 warps (2m x 4n), BK=32.
// ============================================================================
__global__ __launch_bounds__(256, 1) void gemm_mma_kernel(
    const __nv_bfloat16* __restrict__ Ah, const __nv_bfloat16* __restrict__ Al,
    const __nv_bfloat16* __restrict__ Bh, const __nv_bfloat16* __restrict__ Bl,
    size_t a_rowb, size_t a_zb, size_t b_rowb, size_t b_zb,
    int nk, float* __restrict__ of)
{
    extern __shared__ char smraw[];
    const uint32_t smb = smem_u32(smraw);
    const int tid  = threadIdx.x;
    const int wid  = tid >> 5;
    const int lane = tid & 31;
    const int nn0  = blockIdx.x * 128;
    const int m0   = blockIdx.y * 128;
    const int nz   = blockIdx.z;

    const int cr = tid >> 2;
    const int cc = (tid & 3) * 16;
    const char* pAh = (const char*)Ah;
    const char* pAl = (const char*)Al;
    const char* pBh = (const char*)Bh;
    const char* pBl = (const char*)Bl;
    const size_t aoff0 = (size_t)(m0 + cr)  * a_rowb + (size_t)nz * a_zb + cc;
    const size_t aoff1 = aoff0 + 64 * a_rowb;
    const size_t boff0 = (size_t)(nn0 + cr) * b_rowb + (size_t)nz * b_zb + cc;
    const size_t boff1 = boff0 + 64 * b_rowb;
    const uint32_t dd0 = (uint32_t)(cr * 80 + cc);
    const uint32_t dd1 = dd0 + 64 * 80;

#define ISSUE(t) do {                                                   \
        uint32_t sb_ = smb + ((t) % NSTG) * STGB;                        \
        size_t kb_ = (size_t)(t) * 64;                                   \
        CP16(sb_ + dd0,             pAh + aoff0 + kb_);                  \
        CP16(sb_ + dd1,             pAh + aoff1 + kb_);                  \
        CP16(sb_ + TILEB + dd0,     pAl + aoff0 + kb_);                  \
        CP16(sb_ + TILEB + dd1,     pAl + aoff1 + kb_);                  \
        CP16(sb_ + 2*TILEB + dd0,   pBh + boff0 + kb_);                  \
        CP16(sb_ + 2*TILEB + dd1,   pBh + boff1 + kb_);                  \
        CP16(sb_ + 3*TILEB + dd0,   pBl + boff0 + kb_);                  \
        CP16(sb_ + 3*TILEB + dd1,   pBl + boff1 + kb_);                  \
    } while (0)

    const int mbase = (wid >> 2) * 64;
    const int nb    = (wid & 3) * 32;
    const uint32_t aoffL = (uint32_t)((mbase + (lane & 15)) * 80 + (lane >> 4) * 16);
    const uint32_t boffL = (uint32_t)((nb + ((lane >> 4) * 8) + (lane & 7)) * 80
                                      + ((lane >> 3) & 1) * 16);

    float acc[4][4][4];
#pragma unroll
    for (int i = 0; i < 4; i++)
#pragma unroll
        for (int j = 0; j < 4; j++)
#pragma unroll
            for (int r = 0; r < 4; r++) acc[i][j][r] = 0.f;

    ISSUE(0); CP_COMMIT();
    ISSUE(1); CP_COMMIT();

    for (int t = 0; t < nk; t++) {
        if (t + 2 < nk) ISSUE(t + 2);
        CP_COMMIT();
        CP_WAIT2();
        __syncthreads();

        const uint32_t sb  = smb + (t % NSTG) * STGB;
        const uint32_t AhT = sb,             AlT = sb + TILEB;
        const uint32_t BhT = sb + 2 * TILEB, BlT = sb + 3 * TILEB;

#pragma unroll
        for (int ks = 0; ks < 2; ks++) {
            const uint32_t kb = ks * 32;
            uint32_t aH[16], aL[16], bH[8], bL[8];
#pragma unroll
            for (int i = 0; i < 4; i++) {
                LDSM4(aH + 4 * i, AhT + aoffL + i * 1280 + kb);
                LDSM4(aL + 4 * i, AlT + aoffL + i * 1280 + kb);
            }
#pragma unroll
            for (int jp = 0; jp < 2; jp++) {
                LDSM4(bH + 4 * jp, BhT + boffL + jp * 1280 + kb);
                LDSM4(bL + 4 * jp, BlT + boffL + jp * 1280 + kb);
            }
#pragma unroll
            for (int i = 0; i < 4; i++)
#pragma unroll
                for (int j = 0; j < 4; j++) {
                    MMA16816(acc[i][j], aH + 4 * i, bH[j * 2], bH[j * 2 + 1]);
                    MMA16816(acc[i][j], aH + 4 * i, bL[j * 2], bL[j * 2 + 1]);
                    MMA16816(acc[i][j], aL + 4 * i, bH[j * 2], bH[j * 2 + 1]);
                }
        }
        __syncthreads();
    }

    float* smf = (float*)smraw;              // [128][129]
    const int g4 = lane >> 2, tq = lane & 3;
#pragma unroll
    for (int i = 0; i < 4; i++) {
        int m = mbase + i * 16 + g4;
#pragma unroll
        for (int j = 0; j < 4; j++) {
            int col = nb + j * 8 + tq * 2;
            smf[m * 129 + col]           = acc[i][j][0];
            smf[m * 129 + col + 1]       = acc[i][j][1];
            smf[(m + 8) * 129 + col]     = acc[i][j][2];
            smf[(m + 8) * 129 + col + 1] = acc[i][j][3];
        }
    }
    __syncthreads();

    const int g  = tid >> 1;
    const int ph = (tid & 1) * 64;
    const size_t orow = ((size_t)nz * GC + nn0 + g) * HW + m0 + ph;
#pragma unroll 1
    for (int pc = 0; pc < 8; pc++) {
        float4 v0, v1;
        v0.x = smf[(ph + pc * 8 + 0) * 129 + g];
        v0.y = smf[(ph + pc * 8 + 1) * 129 + g];
        v0.z = smf[(ph + pc * 8 + 2) * 129 + g];
        v0.w = smf[(ph + pc * 8 + 3) * 129 + g];
        v1.x = smf[(ph + pc * 8 + 4) * 129 + g];
        v1.y = smf[(ph + pc * 8 + 5) * 129 + g];
        v1.z = smf[(ph + pc * 8 + 6) * 129 + g];
        v1.w = smf[(ph + pc * 8 + 7) * 129 + g];
        *(float4*)(of + orow + pc * 8)     = v0;
        *(float4*)(of + orow + pc * 8 + 4) = v1;
    }
#undef ISSUE
}

// ============================================================================
// launch
// ============================================================================
extern "C" void kernel_launch(void* const* d_in, const int* in_sizes, int n_in,
                              void* d_out, int out_size)
{
    const float* c    = (const float*)d_in[0];
    const float* s    = (const float*)d_in[1];
    const float* grid = (const float*)d_in[2];
    const float* wc1  = (const float*)d_in[3];
    const float* bc1  = (const float*)d_in[4];
    const float* wc2  = (const float*)d_in[5];
    const float* bc2  = (const float*)d_in[6];
    const float* ws1  = (const float*)d_in[7];
    const float* bs1  = (const float*)d_in[8];
    const float* ws2  = (const float*)d_in[9];
    const float* bs2  = (const float*)d_in[10];
    const float* wsr  = (const float*)d_in[11];
    const float* bsr  = (const float*)d_in[12];
    float* out = (float*)d_out;

    float *h1, *c1, *s1, *A;
    __nv_bfloat16 *csh, *csl, *srh, *srl;
    cudaGetSymbolAddress((void**)&h1,  d_h1);
    cudaGetSymbolAddress((void**)&c1,  d_c1);
    cudaGetSymbolAddress((void**)&s1,  d_s1);
    cudaGetSymbolAddress((void**)&A,   d_A);
    cudaGetSymbolAddress((void**)&csh, d_csh);
    cudaGetSymbolAddress((void**)&csl, d_csl);
    cudaGetSymbolAddress((void**)&srh, d_srh);
    cudaGetSymbolAddress((void**)&srl, d_srl);

    cudaFuncSetAttribute(gemm_s8_kernel,
                         cudaFuncAttributeMaxDynamicSharedMemorySize, SMEM_DYN);
    cudaFuncSetAttribute(gemm_mma_kernel,
                         cudaFuncAttributeMaxDynamicSharedMemorySize, SMEM_DYN);

    // branches
    conv16_kernel<<<(2*16*128*128 + 255) / 256, 256>>>(c,  wc1, bc1, h1, 256, 128, 2, 1);
    conv16_kernel<<<(2*16*64*64   + 255) / 256, 256>>>(h1, wc2, bc2, c1, 128, 64,  2, 0);
    conv16_kernel<<<(2*16*128*128 + 255) / 256, 256>>>(s,  ws1, bs1, h1, 256, 128, 2, 1);
    conv16_kernel<<<(2*16*64*64   + 255) / 256, 256>>>(h1, ws2, bs2, s1, 128, 64,  2, 0);

    // affinity + softmax
    {
        dim3 b(32, 8), g(HW / 32, HW / 8, 2);
        affinity_kernel<<<g, b>>>(c1, s1, A);
    }
    softmax_kernel<<<2 * HW, 256>>>(A, csh, csl);

    // int8 operand prep for GEMM1
    chanmax_kernel<<<(2 * HW + 255) / 256, 256>>>(grid);
    amax3_kernel<<<(2 * HW + 255) / 256, 256>>>();
    wmax_kernel<<<GC, 256>>>(wsr);
    wquant_kernel<<<GC, 256>>>(wsr);
    {
        long ni = (long)2 * HW * KC1;
        im2col_q_kernel<<<(unsigned)((ni + 255) / 256), 256>>>(grid);
    }

    // GEMM1 (int8 split): sr = im2col @ wsr^T + bsr -> bf16 hi/lo [g][p]
    {
        dim3 g(GC / 128, HW / 128, 2);
        gemm_s8_kernel<<<g, 512, SMEM_DYN>>>(bsr, srh, srl);
    }
    // GEMM2 (bf16 split): out = cs @ sr^T -> fp32 [g][i]
    {
        dim3 g(GC / 128, HW / 128, 2);
        gemm_mma_kernel<<<g, 256, SMEM_DYN>>>(
            csh, csl, srh, srl,
            (size_t)HW * 2, (size_t)HW * HW * 2,
            (size_t)HW * 2, (size_t)GC * HW * 2,
            HW / 32, out);
    }
}

// round 8
// speedup vs baseline: 4.3681x; 1.3175x over previous
#include <cuda_runtime.h>
#include <cuda_bf16.h>
#include <math.h>
#include <stdint.h>

// ============================================================================
// AttModule (sm_100-safe PTX, legacy tensor cores).
//   GEMM1 via Winograd F(2x2,3x3): 16 pointwise GEMMs (uv), int8 two-word
//     split (mma.m16n8k32.s8, 3 IMMA per k32), exact per-row quant scales.
//   GEMM2 (K=4096): bf16 hi/lo split, mma.m16n8k16.bf16 (3 HMMA per k16).
// MMA budget: 113.7M IMMA + 107M HMMA at 37 inst/cyc chip-wide.
// ============================================================================

#define HW    4096
#define GC    2176
#define KC1   19584          // 2176*9
#define NT    1024           // 32x32 winograd tiles per image
#define QMAX  32512.0f       // 127*256

// bf16 GEMM2 smem geometry
#define TILEB 10240          // 128 rows * 80B
#define STGB  (4*TILEB)
#define NSTG  3
#define SMEM_DYN (NSTG*STGB) // 122880

// int8 wino GEMM smem geometry
#define TILE8 10240
#define STG8  (4*TILE8)

// ---------------- scratch ----------------------------------------------------
static __device__ float          d_h1[2*16*128*128];
static __device__ float          d_c1[2*16*HW];
static __device__ float          d_s1[2*16*HW];
static __device__ float          d_A  [(size_t)2*HW*HW];
static __device__ __nv_bfloat16  d_csh[(size_t)2*HW*HW];
static __device__ __nv_bfloat16  d_csl[(size_t)2*HW*HW];
static __device__ __nv_bfloat16  d_srh[(size_t)2*GC*HW];
static __device__ __nv_bfloat16  d_srl[(size_t)2*GC*HW];
// winograd weights: fp32 transformed, scales, quantized [g][uv][c]
static __device__ float          d_wtf[(size_t)GC*16*GC];
static __device__ float          d_wsc2[GC*16];
static __device__ int8_t         d_wqh[(size_t)GC*16*GC];
static __device__ int8_t         d_wql[(size_t)GC*16*GC];
// winograd inputs: fp32 transformed + quantized [uv*2+n][tile][c], scales
static __device__ float          d_xtf[(size_t)32*NT*GC];
static __device__ float          d_xsc[2*NT*16];
static __device__ int8_t         d_xqh[(size_t)32*NT*GC];
static __device__ int8_t         d_xql[(size_t)32*NT*GC];
// GEMM1 outputs in winograd domain: [n][g][uv][tile] fp32
static __device__ float          d_mt[(size_t)2*GC*16*NT];

// ---------------- PTX helpers ------------------------------------------------
__device__ __forceinline__ uint32_t smem_u32(const void* p) {
    uint32_t a;
    asm("{ .reg .u64 t; cvta.to.shared.u64 t, %1; cvt.u32.u64 %0, t; }"
        : "=r"(a) : "l"(p));
    return a;
}

#define CP16(d, s) \
    asm volatile("cp.async.cg.shared.global [%0], [%1], 16;" :: "r"(d), "l"(s))
#define CP_COMMIT() asm volatile("cp.async.commit_group;" ::: "memory")
#define CP_WAIT2()  asm volatile("cp.async.wait_group 2;" ::: "memory")

#define LDSM4(r, addr) \
    asm volatile("ldmatrix.sync.aligned.m8n8.x4.shared.b16 {%0,%1,%2,%3}, [%4];" \
        : "=r"((r)[0]), "=r"((r)[1]), "=r"((r)[2]), "=r"((r)[3]) : "r"(addr))

#define MMA16816(d, a, b0, b1) \
    asm volatile("mma.sync.aligned.m16n8k16.row.col.f32.bf16.bf16.f32 " \
        "{%0,%1,%2,%3}, {%4,%5,%6,%7}, {%8,%9}, {%0,%1,%2,%3};" \
        : "+f"((d)[0]), "+f"((d)[1]), "+f"((d)[2]), "+f"((d)[3]) \
        : "r"((a)[0]), "r"((a)[1]), "r"((a)[2]), "r"((a)[3]), "r"(b0), "r"(b1))

#define MMAS8(d, a, b0, b1) \
    asm volatile("mma.sync.aligned.m16n8k32.row.col.s32.s8.s8.s32 " \
        "{%0,%1,%2,%3}, {%4,%5,%6,%7}, {%8,%9}, {%0,%1,%2,%3};" \
        : "+r"((d)[0]), "+r"((d)[1]), "+r"((d)[2]), "+r"((d)[3]) \
        : "r"((a)[0]), "r"((a)[1]), "r"((a)[2]), "r"((a)[3]), "r"(b0), "r"(b1))

__device__ __forceinline__ void split_bf16(float v, __nv_bfloat16& h, __nv_bfloat16& l) {
    h = __float2bfloat16(v);
    l = __float2bfloat16(v - __bfloat162float(h));
}

__device__ __forceinline__ void q15(float v, float inv, int8_t& qh, int8_t& ql)
{
    int q = __float2int_rn(v * inv);
    q = max(-32512, min(32512, q));
    int ah = (q + 128) >> 8;
    qh = (int8_t)ah;
    ql = (int8_t)(q - (ah << 8));
}

__device__ __forceinline__ int refl(int y) { return y < 0 ? 1 : (y > 63 ? 62 : y); }

// ============================================================================
// branch / attention prep kernels
// ============================================================================
__global__ void conv16_kernel(const float* __restrict__ in,
                              const float* __restrict__ w,
                              const float* __restrict__ b,
                              float* __restrict__ out,
                              int Hin, int Hout, int stride, int relu)
{
    int idx = blockIdx.x * blockDim.x + threadIdx.x;
    int total = 2 * 16 * Hout * Hout;
    if (idx >= total) return;
    int ox = idx % Hout;
    int oy = (idx / Hout) % Hout;
    int oc = (idx / (Hout * Hout)) % 16;
    int n  = idx / (Hout * Hout * 16);

    const float* wp = w + oc * 16 * 9;
    const float* ip = in + (size_t)n * 16 * Hin * Hin;

    int iy[3], ix[3];
#pragma unroll
    for (int k = 0; k < 3; k++) {
        int y = oy * stride - 1 + k;
        iy[k] = (y < 0) ? 1 : ((y >= Hin) ? Hin - 2 : y);
        int x = ox * stride - 1 + k;
        ix[k] = (x < 0) ? 1 : ((x >= Hin) ? Hin - 2 : x);
    }

    float acc = b[oc];
    for (int ic = 0; ic < 16; ic++) {
        const float* ipc = ip + (size_t)ic * Hin * Hin;
        const float* wpc = wp + ic * 9;
#pragma unroll
        for (int ky = 0; ky < 3; ky++) {
            const float* row = ipc + (size_t)iy[ky] * Hin;
#pragma unroll
            for (int kx = 0; kx < 3; kx++)
                acc += wpc[ky * 3 + kx] * __ldg(row + ix[kx]);
        }
    }
    out[idx] = relu ? fmaxf(acc, 0.f) : acc;
}

__global__ void affinity_kernel(const float* __restrict__ c1,
                                const float* __restrict__ s1,
                                float* __restrict__ A)
{
    int j = blockIdx.x * 32 + threadIdx.x;
    int i = blockIdx.y * 8  + threadIdx.y;
    int n = blockIdx.z;
    const float* cp = c1 + (size_t)n * 16 * HW + i;
    const float* sp = s1 + (size_t)n * 16 * HW + j;
    float acc = 0.f;
#pragma unroll
    for (int k = 0; k < 16; k++)
        acc += cp[(size_t)k * HW] * sp[(size_t)k * HW];
    A[((size_t)n * HW + i) * HW + j] = acc;
}

__global__ void softmax_kernel(float* __restrict__ A,
                               __nv_bfloat16* __restrict__ ch,
                               __nv_bfloat16* __restrict__ cl)
{
    float* p = A + (size_t)blockIdx.x * HW;
    __shared__ float red[256];
    int t = threadIdx.x;

    float m = -INFINITY;
    for (int j = t; j < HW; j += 256) m = fmaxf(m, p[j]);
    red[t] = m; __syncthreads();
    for (int s = 128; s > 0; s >>= 1) {
        if (t < s) red[t] = fmaxf(red[t], red[t + s]);
        __syncthreads();
    }
    m = red[0]; __syncthreads();

    float sum = 0.f;
    for (int j = t; j < HW; j += 256) {
        float e = __expf(p[j] - m);
        p[j] = e;
        sum += e;
    }
    red[t] = sum; __syncthreads();
    for (int s = 128; s > 0; s >>= 1) {
        if (t < s) red[t] += red[t + s];
        __syncthreads();
    }
    float inv = 1.f / red[0];
    size_t base = (size_t)blockIdx.x * HW;
    for (int j = t; j < HW; j += 256) {
        float v = p[j] * inv;
        __nv_bfloat16 h, l;
        split_bf16(v, h, l);
        ch[base + j] = h;
        cl[base + j] = l;
    }
}

// ============================================================================
// winograd weight path:  W_t = G g G^T  -> per-(g,uv) max -> quantize
// ============================================================================
__global__ void wtrans_kernel(const float* __restrict__ wsr)
{
    long idx = (long)blockIdx.x * blockDim.x + threadIdx.x;
    if (idx >= (long)GC * GC) return;
    int c = (int)(idx % GC);
    int g = (int)(idx / GC);
    const float* w9 = wsr + (size_t)g * KC1 + c * 9;

    float V[4][3];
#pragma unroll
    for (int j = 0; j < 3; j++) {
        float g0 = w9[0 * 3 + j], g1 = w9[1 * 3 + j], g2 = w9[2 * 3 + j];
        V[0][j] = g0;
        V[1][j] = 0.5f * (g0 + g1 + g2);
        V[2][j] = 0.5f * (g0 - g1 + g2);
        V[3][j] = g2;
    }
#pragma unroll
    for (int i = 0; i < 4; i++) {
        float v0 = V[i][0], v1 = V[i][1], v2 = V[i][2];
        float W0 = v0;
        float W1 = 0.5f * (v0 + v1 + v2);
        float W2 = 0.5f * (v0 - v1 + v2);
        float W3 = v2;
        size_t b = ((size_t)g * 16 + i * 4) * GC + c;
        d_wtf[b]          = W0;
        d_wtf[b + GC]     = W1;
        d_wtf[b + 2 * GC] = W2;
        d_wtf[b + 3 * GC] = W3;
    }
}

__global__ void wmax_kernel()
{
    int g = blockIdx.x;
    int t = threadIdx.x;
    __shared__ float red[256];
    for (int uv = 0; uv < 16; uv++) {
        const float* row = d_wtf + ((size_t)g * 16 + uv) * GC;
        float m = 0.f;
        for (int c = t; c < GC; c += 256) m = fmaxf(m, fabsf(row[c]));
        red[t] = m; __syncthreads();
        for (int s = 128; s > 0; s >>= 1) {
            if (t < s) red[t] = fmaxf(red[t], red[t + s]);
            __syncthreads();
        }
        if (t == 0) d_wsc2[g * 16 + uv] = red[0] / QMAX;
        __syncthreads();
    }
}

__global__ void wquant_kernel()
{
    long idx = (long)blockIdx.x * blockDim.x + threadIdx.x;
    if (idx >= (long)GC * 16 * GC) return;
    int row = (int)(idx / GC);             // g*16+uv
    float s = d_wsc2[row];
    float inv = (s > 0.f) ? 1.f / s : 0.f;
    int8_t qh, ql;
    q15(d_wtf[idx], inv, qh, ql);
    d_wqh[idx] = qh;
    d_wql[idx] = ql;
}

// ============================================================================
// winograd input path:  X_t = B^T d B  -> per-(n,tile,uv) max -> quantize
// layout: d_xtf[(uv*2+n)*NT + tile][c]
// ============================================================================
__global__ void xtrans_kernel(const float* __restrict__ grid)
{
    long idx = (long)blockIdx.x * blockDim.x + threadIdx.x;
    if (idx >= (long)2 * NT * GC) return;
    int c    = (int)(idx % GC);
    int tile = (int)((idx / GC) % NT);
    int n    = (int)(idx / ((long)GC * NT));
    int ty = tile >> 5, tx = tile & 31;

    const float* gp = grid + (((size_t)n * GC + c) << 12);
    float d[4][4];
#pragma unroll
    for (int iy = 0; iy < 4; iy++) {
        int ry = refl(2 * ty - 1 + iy);
#pragma unroll
        for (int ix = 0; ix < 4; ix++) {
            int rx = refl(2 * tx - 1 + ix);
            d[iy][ix] = __ldg(gp + (ry << 6) + rx);
        }
    }
    float U[4][4];
#pragma unroll
    for (int j = 0; j < 4; j++) {
        U[0][j] = d[0][j] - d[2][j];
        U[1][j] = d[1][j] + d[2][j];
        U[2][j] = d[2][j] - d[1][j];
        U[3][j] = d[1][j] - d[3][j];
    }
#pragma unroll
    for (int i = 0; i < 4; i++) {
        float X0 = U[i][0] - U[i][2];
        float X1 = U[i][1] + U[i][2];
        float X2 = U[i][2] - U[i][1];
        float X3 = U[i][1] - U[i][3];
        size_t b = ((size_t)((i * 4) * 2 + n) * NT + tile) * GC + c;
        size_t step = (size_t)2 * NT * GC;
        d_xtf[b]            = X0;
        d_xtf[b + step]     = X1;
        d_xtf[b + 2 * step] = X2;
        d_xtf[b + 3 * step] = X3;
    }
}

__global__ void xmax_kernel()
{
    int tile = blockIdx.x & (NT - 1);
    int n    = blockIdx.x >> 10;
    int t = threadIdx.x;
    __shared__ float red[256];
    for (int uv = 0; uv < 16; uv++) {
        const float* row = d_xtf + ((size_t)(uv * 2 + n) * NT + tile) * GC;
        float m = 0.f;
        for (int c = t; c < GC; c += 256) m = fmaxf(m, fabsf(row[c]));
        red[t] = m; __syncthreads();
        for (int s = 128; s > 0; s >>= 1) {
            if (t < s) red[t] = fmaxf(red[t], red[t + s]);
            __syncthreads();
        }
        if (t == 0) d_xsc[(n * NT + tile) * 16 + uv] = red[0] / QMAX;
        __syncthreads();
    }
}

__global__ void xquant_kernel()
{
    long idx = (long)blockIdx.x * blockDim.x + threadIdx.x;
    if (idx >= (long)32 * NT * GC) return;
    long row = idx / GC;                    // (uv*2+n)*NT + tile
    int tile = (int)(row & (NT - 1));
    int pl   = (int)(row >> 10);            // uv*2+n
    int n = pl & 1, uv = pl >> 1;
    float s = d_xsc[(n * NT + tile) * 16 + uv];
    float inv = (s > 0.f) ? 1.f / s : 0.f;
    int8_t qh, ql;
    q15(d_xtf[idx], inv, qh, ql);
    d_xqh[idx] = qh;
    d_xql[idx] = ql;
}

// ============================================================================
// winograd GEMM: per (uv,n): M[tile][g] = sum_c X_t[tile,c] * W_t[g,c]
// int8 two-word split, 512 thr = 16 warps (4m x 4n), BK=64, K=2176 (34 iters)
// grid = (17 g-tiles, 8 tile-tiles, 32 z=uv*2+n). out: d_mt[n][g][uv][tile]
// ============================================================================
__global__ __launch_bounds__(512, 1) void gemm_wino_kernel()
{
    extern __shared__ char smraw[];
    const uint32_t smb = smem_u32(smraw);
    const int tid  = threadIdx.x;
    const int wid  = tid >> 5;
    const int lane = tid & 31;
    const int nn0  = blockIdx.x * 128;       // g tile
    const int m0   = blockIdx.y * 128;       // wino-tile tile
    const int z    = blockIdx.z;             // uv*2+n
    const int n    = z & 1, uv = z >> 1;
    const int nk   = GC / 64;                // 34

    const int cr = tid >> 2;
    const int cc = (tid & 3) * 16;
    const char* pAh = (const char*)d_xqh;
    const char* pAl = (const char*)d_xql;
    const char* pBh = (const char*)d_wqh;
    const char* pBl = (const char*)d_wql;
    const size_t aoff = ((size_t)z * NT + m0 + cr) * GC + cc;
    const size_t boff = ((size_t)(nn0 + cr) * 16 + uv) * GC + cc;
    const uint32_t dd = (uint32_t)(cr * 80 + cc);

#define ISSUE8(t) do {                                               \
        uint32_t sb_ = smb + ((t) % NSTG) * STG8;                    \
        size_t kb_ = (size_t)(t) * 64;                               \
        CP16(sb_ + dd,             pAh + aoff + kb_);                \
        CP16(sb_ + TILE8 + dd,     pAl + aoff + kb_);                \
        CP16(sb_ + 2*TILE8 + dd,   pBh + boff + kb_);                \
        CP16(sb_ + 3*TILE8 + dd,   pBl + boff + kb_);                \
    } while (0)

    const int wm = wid >> 2;
    const int wn = wid & 3;
    const uint32_t aoffL = (uint32_t)((wm * 32 + (lane & 15)) * 80 + (lane >> 4) * 16);
    const uint32_t boffL = (uint32_t)((wn * 32 + ((lane >> 4) << 3) + (lane & 7)) * 80
                                      + ((lane >> 3) & 1) * 16);

    int acc1[2][4][4], acc2[2][4][4];
#pragma unroll
    for (int i = 0; i < 2; i++)
#pragma unroll
        for (int j = 0; j < 4; j++)
#pragma unroll
            for (int r = 0; r < 4; r++) { acc1[i][j][r] = 0; acc2[i][j][r] = 0; }

    ISSUE8(0); CP_COMMIT();
    ISSUE8(1); CP_COMMIT();

    for (int t = 0; t < nk; t++) {
        if (t + 2 < nk) ISSUE8(t + 2);
        CP_COMMIT();
        CP_WAIT2();
        __syncthreads();

        const uint32_t sb  = smb + (t % NSTG) * STG8;
        const uint32_t AhT = sb,             AlT = sb + TILE8;
        const uint32_t BhT = sb + 2 * TILE8, BlT = sb + 3 * TILE8;

#pragma unroll
        for (int ks = 0; ks < 2; ks++) {
            const uint32_t kb = ks * 32;
            uint32_t aH[8], aL[8], bH[8], bL[8];
            LDSM4(aH,     AhT + aoffL + kb);
            LDSM4(aH + 4, AhT + aoffL + 16 * 80 + kb);
            LDSM4(aL,     AlT + aoffL + kb);
            LDSM4(aL + 4, AlT + aoffL + 16 * 80 + kb);
            LDSM4(bH,     BhT + boffL + kb);
            LDSM4(bH + 4, BhT + boffL + 16 * 80 + kb);
            LDSM4(bL,     BlT + boffL + kb);
            LDSM4(bL + 4, BlT + boffL + 16 * 80 + kb);
#pragma unroll
            for (int i = 0; i < 2; i++)
#pragma unroll
                for (int j = 0; j < 4; j++) {
                    MMAS8(acc1[i][j], aH + 4 * i, bH[2 * j], bH[2 * j + 1]);
                    MMAS8(acc2[i][j], aH + 4 * i, bL[2 * j], bL[2 * j + 1]);
                    MMAS8(acc2[i][j], aL + 4 * i, bH[2 * j], bH[2 * j + 1]);
                }
        }
        __syncthreads();
    }

    // dequant + transpose -> [g][tile] fp32
    float* smf = (float*)smraw;              // [128][129]
    const float* asb = d_xsc + ((size_t)(n * NT + m0)) * 16 + uv;   // stride 16
    const float* wsb = d_wsc2 + (size_t)nn0 * 16 + uv;              // stride 16
#pragma unroll
    for (int i = 0; i < 2; i++) {
        int m = wm * 32 + i * 16 + (lane >> 2);
        float sa0 = asb[m * 16], sa1 = asb[(m + 8) * 16];
#pragma unroll
        for (int j = 0; j < 4; j++) {
            int col = wn * 32 + j * 8 + 2 * (lane & 3);
            float w0 = wsb[col * 16], w1 = wsb[(col + 1) * 16];
            float v0 = fmaf(65536.f, (float)acc1[i][j][0], 256.f * (float)acc2[i][j][0]);
            float v1 = fmaf(65536.f, (float)acc1[i][j][1], 256.f * (float)acc2[i][j][1]);
            float v2 = fmaf(65536.f, (float)acc1[i][j][2], 256.f * (float)acc2[i][j][2]);
            float v3 = fmaf(65536.f, (float)acc1[i][j][3], 256.f * (float)acc2[i][j][3]);
            smf[m * 129 + col]           = sa0 * w0 * v0;
            smf[m * 129 + col + 1]       = sa0 * w1 * v1;
            smf[(m + 8) * 129 + col]     = sa1 * w0 * v2;
            smf[(m + 8) * 129 + col + 1] = sa1 * w1 * v3;
        }
    }
    __syncthreads();

    const int g = tid >> 2;                  // g-local
    const int q = tid & 3;                   // tile quarter
    const size_t ob = (((size_t)n * GC + nn0 + g) * 16 + uv) * NT + m0 + q * 32;
#pragma unroll 1
    for (int pc = 0; pc < 8; pc++) {
        float4 v;
        v.x = smf[(q * 32 + pc * 4 + 0) * 129 + g];
        v.y = smf[(q * 32 + pc * 4 + 1) * 129 + g];
        v.z = smf[(q * 32 + pc * 4 + 2) * 129 + g];
        v.w = smf[(q * 32 + pc * 4 + 3) * 129 + g];
        *(float4*)(d_mt + ob + pc * 4) = v;
    }
#undef ISSUE8
}

// ============================================================================
// output transform: Y = A^T M A + bias -> sr bf16 hi/lo [n*GC+g][64*64]
// ============================================================================
__global__ void outtrans_kernel(const float* __restrict__ bias,
                                __nv_bfloat16* __restrict__ oh,
                                __nv_bfloat16* __restrict__ ol)
{
    long idx = (long)blockIdx.x * blockDim.x + threadIdx.x;
    if (idx >= (long)2 * GC * NT) return;
    int tile = (int)(idx & (NT - 1));
    int g    = (int)((idx >> 10) % GC);
    int n    = (int)(idx / ((long)GC * NT));
    int ty = tile >> 5, tx = tile & 31;

    const float* mb = d_mt + (((size_t)n * GC + g) * 16) * NT + tile;
    float M[16];
#pragma unroll
    for (int uv = 0; uv < 16; uv++) M[uv] = mb[(size_t)uv * NT];

    float T0[4], T1[4];
#pragma unroll
    for (int j = 0; j < 4; j++) {
        T0[j] = M[j] + M[4 + j] + M[8 + j];
        T1[j] = M[4 + j] - M[8 + j] - M[12 + j];
    }
    float bv = bias[g];
    float y00 = T0[0] + T0[1] + T0[2] + bv;
    float y01 = T0[1] - T0[2] - T0[3] + bv;
    float y10 = T1[0] + T1[1] + T1[2] + bv;
    float y11 = T1[1] - T1[2] - T1[3] + bv;

    size_t row = ((size_t)n * GC + g) * HW + (ty << 7) + (tx << 1);  // (2ty)*64+2tx
    __nv_bfloat16 h0, l0, h1, l1;
    split_bf16(y00, h0, l0); split_bf16(y01, h1, l1);
    *(uint32_t*)(oh + row) = (uint32_t)__bfloat16_as_ushort(h0)
                           | ((uint32_t)__bfloat16_as_ushort(h1) << 16);
    *(uint32_t*)(ol + row) = (uint32_t)__bfloat16_as_ushort(l0)
                           | ((uint32_t)__bfloat16_as_ushort(l1) << 16);
    split_bf16(y10, h0, l0); split_bf16(y11, h1, l1);
    *(uint32_t*)(oh + row + 64) = (uint32_t)__bfloat16_as_ushort(h0)
                                | ((uint32_t)__bfloat16_as_ushort(h1) << 16);
    *(uint32_t*)(ol + row + 64) = (uint32_t)__bfloat16_as_ushort(l0)
                                | ((uint32_t)__bfloat16_as_ushort(l1) << 16);
}

// ============================================================================
// GEMM2: bf16 split (proven). 256 thr = 8 warps (2m x 4n), BK=32.
// ============================================================================
__global__ __launch_bounds__(256, 1) void gemm_mma_kernel(
    const __nv_bfloat16* __restrict__ Ah, const __nv_bfloat16* __restrict__ Al,
    const __nv_bfloat16* __restrict__ Bh, const __nv_bfloat16* __restrict__ Bl,
    size_t a_rowb, size_t a_zb, size_t b_rowb, size_t b_zb,
    int nk, float* __restrict__ of)
{
    extern __shared__ char smraw[];
    const uint32_t smb = smem_u32(smraw);
    const int tid  = threadIdx.x;
    const int wid  = tid >> 5;
    const int lane = tid & 31;
    const int nn0  = blockIdx.x * 128;
    const int m0   = blockIdx.y * 128;
    const int nz   = blockIdx.z;

    const int cr = tid >> 2;
    const int cc = (tid & 3) * 16;
    const char* pAh = (const char*)Ah;
    const char* pAl = (const char*)Al;
    const char* pBh = (const char*)Bh;
    const char* pBl = (const char*)Bl;
    const size_t aoff0 = (size_t)(m0 + cr)  * a_rowb + (size_t)nz * a_zb + cc;
    const size_t aoff1 = aoff0 + 64 * a_rowb;
    const size_t boff0 = (size_t)(nn0 + cr) * b_rowb + (size_t)nz * b_zb + cc;
    const size_t boff1 = boff0 + 64 * b_rowb;
    const uint32_t dd0 = (uint32_t)(cr * 80 + cc);
    const uint32_t dd1 = dd0 + 64 * 80;

#define ISSUE(t) do {                                                   \
        uint32_t sb_ = smb + ((t) % NSTG) * STGB;                        \
        size_t kb_ = (size_t)(t) * 64;                                   \
        CP16(sb_ + dd0,             pAh + aoff0 + kb_);                  \
        CP16(sb_ + dd1,             pAh + aoff1 + kb_);                  \
        CP16(sb_ + TILEB + dd0,     pAl + aoff0 + kb_);                  \
        CP16(sb_ + TILEB + dd1,     pAl + aoff1 + kb_);                  \
        CP16(sb_ + 2*TILEB + dd0,   pBh + boff0 + kb_);                  \
        CP16(sb_ + 2*TILEB + dd1,   pBh + boff1 + kb_);                  \
        CP16(sb_ + 3*TILEB + dd0,   pBl + boff0 + kb_);                  \
        CP16(sb_ + 3*TILEB + dd1,   pBl + boff1 + kb_);                  \
    } while (0)

    const int mbase = (wid >> 2) * 64;
    const int nb    = (wid & 3) * 32;
    const uint32_t aoffL = (uint32_t)((mbase + (lane & 15)) * 80 + (lane >> 4) * 16);
    const uint32_t boffL = (uint32_t)((nb + ((lane >> 4) * 8) + (lane & 7)) * 80
                                      + ((lane >> 3) & 1) * 16);

    float acc[4][4][4];
#pragma unroll
    for (int i = 0; i < 4; i++)
#pragma unroll
        for (int j = 0; j < 4; j++)
#pragma unroll
            for (int r = 0; r < 4; r++) acc[i][j][r] = 0.f;

    ISSUE(0); CP_COMMIT();
    ISSUE(1); CP_COMMIT();

    for (int t = 0; t < nk; t++) {
        if (t + 2 < nk) ISSUE(t + 2);
        CP_COMMIT();
        CP_WAIT2();
        __syncthreads();

        const uint32_t sb  = smb + (t % NSTG) * STGB;
        const uint32_t AhT = sb,             AlT = sb + TILEB;
        const uint32_t BhT = sb + 2 * TILEB, BlT = sb + 3 * TILEB;

#pragma unroll
        for (int ks = 0; ks < 2; ks++) {
            const uint32_t kb = ks * 32;
            uint32_t aH[16], aL[16], bH[8], bL[8];
#pragma unroll
            for (int i = 0; i < 4; i++) {
                LDSM4(aH + 4 * i, AhT + aoffL + i * 1280 + kb);
                LDSM4(aL + 4 * i, AlT + aoffL + i * 1280 + kb);
            }
#pragma unroll
            for (int jp = 0; jp < 2; jp++) {
                LDSM4(bH + 4 * jp, BhT + boffL + jp * 1280 + kb);
                LDSM4(bL + 4 * jp, BlT + boffL + jp * 1280 + kb);
            }
#pragma unroll
            for (int i = 0; i < 4; i++)
#pragma unroll
                for (int j = 0; j < 4; j++) {
                    MMA16816(acc[i][j], aH + 4 * i, bH[j * 2], bH[j * 2 + 1]);
                    MMA16816(acc[i][j], aH + 4 * i, bL[j * 2], bL[j * 2 + 1]);
                    MMA16816(acc[i][j], aL + 4 * i, bH[j * 2], bH[j * 2 + 1]);
                }
        }
        __syncthreads();
    }

    float* smf = (float*)smraw;              // [128][129]
    const int g4 = lane >> 2, tq = lane & 3;
#pragma unroll
    for (int i = 0; i < 4; i++) {
        int m = mbase + i * 16 + g4;
#pragma unroll
        for (int j = 0; j < 4; j++) {
            int col = nb + j * 8 + tq * 2;
            smf[m * 129 + col]           = acc[i][j][0];
            smf[m * 129 + col + 1]       = acc[i][j][1];
            smf[(m + 8) * 129 + col]     = acc[i][j][2];
            smf[(m + 8) * 129 + col + 1] = acc[i][j][3];
        }
    }
    __syncthreads();

    const int g  = tid >> 1;
    const int ph = (tid & 1) * 64;
    const size_t orow = ((size_t)nz * GC + nn0 + g) * HW + m0 + ph;
#pragma unroll 1
    for (int pc = 0; pc < 8; pc++) {
        float4 v0, v1;
        v0.x = smf[(ph + pc * 8 + 0) * 129 + g];
        v0.y = smf[(ph + pc * 8 + 1) * 129 + g];
        v0.z = smf[(ph + pc * 8 + 2) * 129 + g];
        v0.w = smf[(ph + pc * 8 + 3) * 129 + g];
        v1.x = smf[(ph + pc * 8 + 4) * 129 + g];
        v1.y = smf[(ph + pc * 8 + 5) * 129 + g];
        v1.z = smf[(ph + pc * 8 + 6) * 129 + g];
        v1.w = smf[(ph + pc * 8 + 7) * 129 + g];
        *(float4*)(of + orow + pc * 8)     = v0;
        *(float4*)(of + orow + pc * 8 + 4) = v1;
    }
#undef ISSUE
}

// ============================================================================
// launch
// ============================================================================
extern "C" void kernel_launch(void* const* d_in, const int* in_sizes, int n_in,
                              void* d_out, int out_size)
{
    const float* c    = (const float*)d_in[0];
    const float* s    = (const float*)d_in[1];
    const float* grid = (const float*)d_in[2];
    const float* wc1  = (const float*)d_in[3];
    const float* bc1  = (const float*)d_in[4];
    const float* wc2  = (const float*)d_in[5];
    const float* bc2  = (const float*)d_in[6];
    const float* ws1  = (const float*)d_in[7];
    const float* bs1  = (const float*)d_in[8];
    const float* ws2  = (const float*)d_in[9];
    const float* bs2  = (const float*)d_in[10];
    const float* wsr  = (const float*)d_in[11];
    const float* bsr  = (const float*)d_in[12];
    float* out = (float*)d_out;

    float *h1, *c1, *s1, *A;
    __nv_bfloat16 *csh, *csl, *srh, *srl;
    cudaGetSymbolAddress((void**)&h1,  d_h1);
    cudaGetSymbolAddress((void**)&c1,  d_c1);
    cudaGetSymbolAddress((void**)&s1,  d_s1);
    cudaGetSymbolAddress((void**)&A,   d_A);
    cudaGetSymbolAddress((void**)&csh, d_csh);
    cudaGetSymbolAddress((void**)&csl, d_csl);
    cudaGetSymbolAddress((void**)&srh, d_srh);
    cudaGetSymbolAddress((void**)&srl, d_srl);

    cudaFuncSetAttribute(gemm_wino_kernel,
                         cudaFuncAttributeMaxDynamicSharedMemorySize, SMEM_DYN);
    cudaFuncSetAttribute(gemm_mma_kernel,
                         cudaFuncAttributeMaxDynamicSharedMemorySize, SMEM_DYN);

    // branches
    conv16_kernel<<<(2*16*128*128 + 255) / 256, 256>>>(c,  wc1, bc1, h1, 256, 128, 2, 1);
    conv16_kernel<<<(2*16*64*64   + 255) / 256, 256>>>(h1, wc2, bc2, c1, 128, 64,  2, 0);
    conv16_kernel<<<(2*16*128*128 + 255) / 256, 256>>>(s,  ws1, bs1, h1, 256, 128, 2, 1);
    conv16_kernel<<<(2*16*64*64   + 255) / 256, 256>>>(h1, ws2, bs2, s1, 128, 64,  2, 0);

    // affinity + softmax
    {
        dim3 b(32, 8), g(HW / 32, HW / 8, 2);
        affinity_kernel<<<g, b>>>(c1, s1, A);
    }
    softmax_kernel<<<2 * HW, 256>>>(A, csh, csl);

    // winograd weight prep
    {
        long nw = (long)GC * GC;
        wtrans_kernel<<<(unsigned)((nw + 255) / 256), 256>>>(wsr);
        wmax_kernel<<<GC, 256>>>();
        long nq = (long)GC * 16 * GC;
        wquant_kernel<<<(unsigned)((nq + 255) / 256), 256>>>();
    }
    // winograd input prep
    {
        long nx = (long)2 * NT * GC;
        xtrans_kernel<<<(unsigned)((nx + 255) / 256), 256>>>(grid);
        xmax_kernel<<<2 * NT, 256>>>();
        long nq = (long)32 * NT * GC;
        xquant_kernel<<<(unsigned)((nq + 255) / 256), 256>>>();
    }

    // GEMM1 in winograd domain + inverse transform
    {
        dim3 g(GC / 128, NT / 128, 32);
        gemm_wino_kernel<<<g, 512, SMEM_DYN>>>();
        long no = (long)2 * GC * NT;
        outtrans_kernel<<<(unsigned)((no + 255) / 256), 256>>>(bsr, srh, srl);
    }

    // GEMM2 (bf16 split): out = cs @ sr^T -> fp32 [g][i]
    {
        dim3 g(GC / 128, HW / 128, 2);
        gemm_mma_kernel<<<g, 256, SMEM_DYN>>>(
            csh, csl, srh, srl,
            (size_t)HW * 2, (size_t)HW * HW * 2,
            (size_t)HW * 2, (size_t)GC * HW * 2,
            HW / 32, out);
    }
}

// round 9
// speedup vs baseline: 5.6982x; 1.3045x over previous
#include <cuda_runtime.h>
#include <math.h>
#include <stdint.h>

// ============================================================================
// AttModule (sm_100-safe PTX, legacy tensor cores) — all-int8 tensor path.
//   GEMM1 via Winograd F(2x2,3x3): 16 pointwise GEMMs, int8 two-word split
//     (3x mma.m16n8k32.s8 per k32), exact per-row quant scales.
//   GEMM2 (K=4096): int8 two-word split as well; cs scale = softmax inv (free),
//     sr scale from fused output-transform rowmax.
// MMA budget: 113.7M + 53.5M IMMA at ~37 inst/cyc chip-wide.
// ============================================================================

#define HW    4096
#define GC    2176
#define KC1   19584          // 2176*9
#define NT    1024           // 32x32 winograd tiles per image
#define QMAX  32512.0f       // 127*256

#define TILE8 10240          // 128 rows * 80B
#define STG8  (4*TILE8)
#define NSTG  3
#define SMEM_DYN (NSTG*STG8) // 122880; epilogue reuses as float[128][129]

// ---------------- scratch ----------------------------------------------------
static __device__ float   d_h1[2*16*128*128];
static __device__ float   d_c1[2*16*HW];
static __device__ float   d_s1[2*16*HW];
static __device__ float   d_A  [(size_t)2*HW*HW];      // logits -> exp
// GEMM2 operands (int8 split)
static __device__ int8_t  d_csqh[(size_t)2*HW*HW];
static __device__ int8_t  d_csql[(size_t)2*HW*HW];
static __device__ float   d_cssc[2*HW];
static __device__ int8_t  d_srqh[(size_t)2*GC*HW];
static __device__ int8_t  d_srql[(size_t)2*GC*HW];
static __device__ float   d_srsc[2*GC];
// winograd weights (quantized) + scales
static __device__ int8_t  d_wqh[(size_t)GC*16*GC];
static __device__ int8_t  d_wql[(size_t)GC*16*GC];
static __device__ float   d_wsc2[GC*16];
// winograd inputs (quantized) + scales
static __device__ int8_t  d_xqh[(size_t)32*NT*GC];
static __device__ int8_t  d_xql[(size_t)32*NT*GC];
static __device__ float   d_xsc[2*NT*16];
// GEMM1 outputs in winograd domain: [n][g][uv][tile] fp32
static __device__ float   d_mt[(size_t)2*GC*16*NT];

// ---------------- PTX helpers ------------------------------------------------
__device__ __forceinline__ uint32_t smem_u32(const void* p) {
    uint32_t a;
    asm("{ .reg .u64 t; cvta.to.shared.u64 t, %1; cvt.u32.u64 %0, t; }"
        : "=r"(a) : "l"(p));
    return a;
}

#define CP16(d, s) \
    asm volatile("cp.async.cg.shared.global [%0], [%1], 16;" :: "r"(d), "l"(s))
#define CP_COMMIT() asm volatile("cp.async.commit_group;" ::: "memory")
#define CP_WAIT2()  asm volatile("cp.async.wait_group 2;" ::: "memory")

#define LDSM4(r, addr) \
    asm volatile("ldmatrix.sync.aligned.m8n8.x4.shared.b16 {%0,%1,%2,%3}, [%4];" \
        : "=r"((r)[0]), "=r"((r)[1]), "=r"((r)[2]), "=r"((r)[3]) : "r"(addr))

#define MMAS8(d, a, b0, b1) \
    asm volatile("mma.sync.aligned.m16n8k32.row.col.s32.s8.s8.s32 " \
        "{%0,%1,%2,%3}, {%4,%5,%6,%7}, {%8,%9}, {%0,%1,%2,%3};" \
        : "+r"((d)[0]), "+r"((d)[1]), "+r"((d)[2]), "+r"((d)[3]) \
        : "r"((a)[0]), "r"((a)[1]), "r"((a)[2]), "r"((a)[3]), "r"(b0), "r"(b1))

__device__ __forceinline__ void q15(float v, float inv, int8_t& qh, int8_t& ql)
{
    int q = __float2int_rn(v * inv);
    q = max(-32512, min(32512, q));
    int ah = (q + 128) >> 8;
    qh = (int8_t)ah;
    ql = (int8_t)(q - (ah << 8));
}

__device__ __forceinline__ int refl(int y) { return y < 0 ? 1 : (y > 63 ? 62 : y); }

// winograd transforms (identical math to R8)
__device__ __forceinline__ void wino_w(const float* w9, float W[16])
{
    float V[4][3];
#pragma unroll
    for (int j = 0; j < 3; j++) {
        float g0 = w9[j], g1 = w9[3 + j], g2 = w9[6 + j];
        V[0][j] = g0;
        V[1][j] = 0.5f * (g0 + g1 + g2);
        V[2][j] = 0.5f * (g0 - g1 + g2);
        V[3][j] = g2;
    }
#pragma unroll
    for (int i = 0; i < 4; i++) {
        float v0 = V[i][0], v1 = V[i][1], v2 = V[i][2];
        W[i * 4 + 0] = v0;
        W[i * 4 + 1] = 0.5f * (v0 + v1 + v2);
        W[i * 4 + 2] = 0.5f * (v0 - v1 + v2);
        W[i * 4 + 3] = v2;
    }
}

__device__ __forceinline__ void wino_x(const float d[4][4], float X[16])
{
    float U[4][4];
#pragma unroll
    for (int j = 0; j < 4; j++) {
        U[0][j] = d[0][j] - d[2][j];
        U[1][j] = d[1][j] + d[2][j];
        U[2][j] = d[2][j] - d[1][j];
        U[3][j] = d[1][j] - d[3][j];
    }
#pragma unroll
    for (int i = 0; i < 4; i++) {
        X[i * 4 + 0] = U[i][0] - U[i][2];
        X[i * 4 + 1] = U[i][1] + U[i][2];
        X[i * 4 + 2] = U[i][2] - U[i][1];
        X[i * 4 + 3] = U[i][1] - U[i][3];
    }
}

// ============================================================================
// branch / attention prep
// ============================================================================
__global__ void conv16_kernel(const float* __restrict__ in,
                              const float* __restrict__ w,
                              const float* __restrict__ b,
                              float* __restrict__ out,
                              int Hin, int Hout, int stride, int relu)
{
    int idx = blockIdx.x * blockDim.x + threadIdx.x;
    int total = 2 * 16 * Hout * Hout;
    if (idx >= total) return;
    int ox = idx % Hout;
    int oy = (idx / Hout) % Hout;
    int oc = (idx / (Hout * Hout)) % 16;
    int n  = idx / (Hout * Hout * 16);

    const float* wp = w + oc * 16 * 9;
    const float* ip = in + (size_t)n * 16 * Hin * Hin;

    int iy[3], ix[3];
#pragma unroll
    for (int k = 0; k < 3; k++) {
        int y = oy * stride - 1 + k;
        iy[k] = (y < 0) ? 1 : ((y >= Hin) ? Hin - 2 : y);
        int x = ox * stride - 1 + k;
        ix[k] = (x < 0) ? 1 : ((x >= Hin) ? Hin - 2 : x);
    }

    float acc = b[oc];
    for (int ic = 0; ic < 16; ic++) {
        const float* ipc = ip + (size_t)ic * Hin * Hin;
        const float* wpc = wp + ic * 9;
#pragma unroll
        for (int ky = 0; ky < 3; ky++) {
            const float* row = ipc + (size_t)iy[ky] * Hin;
#pragma unroll
            for (int kx = 0; kx < 3; kx++)
                acc += wpc[ky * 3 + kx] * __ldg(row + ix[kx]);
        }
    }
    out[idx] = relu ? fmaxf(acc, 0.f) : acc;
}

__global__ void affinity_kernel(const float* __restrict__ c1,
                                const float* __restrict__ s1,
                                float* __restrict__ A)
{
    int j = blockIdx.x * 32 + threadIdx.x;
    int i = blockIdx.y * 8  + threadIdx.y;
    int n = blockIdx.z;
    const float* cp = c1 + (size_t)n * 16 * HW + i;
    const float* sp = s1 + (size_t)n * 16 * HW + j;
    float acc = 0.f;
#pragma unroll
    for (int k = 0; k < 16; k++)
        acc += cp[(size_t)k * HW] * sp[(size_t)k * HW];
    A[((size_t)n * HW + i) * HW + j] = acc;
}

// softmax emitting q15 int8 directly; row scale = inv/QMAX (max cs = inv).
__global__ void softmax_q_kernel(float* __restrict__ A)
{
    float* p = A + (size_t)blockIdx.x * HW;
    __shared__ float red[256];
    int t = threadIdx.x;

    float m = -INFINITY;
    for (int j = t; j < HW; j += 256) m = fmaxf(m, p[j]);
    red[t] = m; __syncthreads();
    for (int s = 128; s > 0; s >>= 1) {
        if (t < s) red[t] = fmaxf(red[t], red[t + s]);
        __syncthreads();
    }
    m = red[0]; __syncthreads();

    float sum = 0.f;
    for (int j = t; j < HW; j += 256) {
        float e = __expf(p[j] - m);
        p[j] = e;
        sum += e;
    }
    red[t] = sum; __syncthreads();
    for (int s = 128; s > 0; s >>= 1) {
        if (t < s) red[t] += red[t + s];
        __syncthreads();
    }
    float inv = 1.f / red[0];
    if (t == 0) d_cssc[blockIdx.x] = inv / QMAX;

    size_t base = (size_t)blockIdx.x * HW;
    for (int j = t * 4; j < HW; j += 1024) {
        char4 h4, l4;
        int8_t qh, ql;
        q15(p[j + 0], QMAX, qh, ql); h4.x = qh; l4.x = ql;
        q15(p[j + 1], QMAX, qh, ql); h4.y = qh; l4.y = ql;
        q15(p[j + 2], QMAX, qh, ql); h4.z = qh; l4.z = ql;
        q15(p[j + 3], QMAX, qh, ql); h4.w = qh; l4.w = ql;
        *(char4*)(d_csqh + base + j) = h4;
        *(char4*)(d_csql + base + j) = l4;
    }
}

// ============================================================================
// fused winograd weight prep: transform + per-(g,uv) max + quantize (2-pass)
// ============================================================================
__global__ void wprep_kernel(const float* __restrict__ wsr)
{
    int g = blockIdx.x;
    int t = threadIdx.x;
    __shared__ float redm[16 * 256];
    __shared__ float scinv[16];

    float mx[16];
#pragma unroll
    for (int uv = 0; uv < 16; uv++) mx[uv] = 0.f;

    for (int c = t; c < GC; c += 256) {
        float w9[9], W[16];
        const float* wp = wsr + (size_t)g * KC1 + c * 9;
#pragma unroll
        for (int k = 0; k < 9; k++) w9[k] = wp[k];
        wino_w(w9, W);
#pragma unroll
        for (int uv = 0; uv < 16; uv++) mx[uv] = fmaxf(mx[uv], fabsf(W[uv]));
    }
#pragma unroll
    for (int uv = 0; uv < 16; uv++) redm[uv * 256 + t] = mx[uv];
    __syncthreads();
    for (int s = 128; s > 0; s >>= 1) {
        if (t < s)
#pragma unroll
            for (int uv = 0; uv < 16; uv++)
                redm[uv * 256 + t] = fmaxf(redm[uv * 256 + t], redm[uv * 256 + t + s]);
        __syncthreads();
    }
    if (t < 16) {
        float sc = redm[t * 256] / QMAX;
        d_wsc2[g * 16 + t] = sc;
        scinv[t] = (sc > 0.f) ? 1.f / sc : 0.f;
    }
    __syncthreads();

    for (int c = t; c < GC; c += 256) {
        float w9[9], W[16];
        const float* wp = wsr + (size_t)g * KC1 + c * 9;
#pragma unroll
        for (int k = 0; k < 9; k++) w9[k] = wp[k];
        wino_w(w9, W);
#pragma unroll
        for (int uv = 0; uv < 16; uv++) {
            int8_t qh, ql;
            q15(W[uv], scinv[uv], qh, ql);
            size_t o = ((size_t)g * 16 + uv) * GC + c;
            d_wqh[o] = qh;
            d_wql[o] = ql;
        }
    }
}

// ============================================================================
// fused winograd input prep: transform + per-(n,tile,uv) max + quantize
// ============================================================================
__global__ void xprep_kernel(const float* __restrict__ grid)
{
    int tile = blockIdx.x & (NT - 1);
    int n    = blockIdx.x >> 10;
    int t = threadIdx.x;
    int ty = tile >> 5, tx = tile & 31;
    __shared__ float redm[16 * 256];
    __shared__ float scinv[16];

    int ry[4], rx[4];
#pragma unroll
    for (int k = 0; k < 4; k++) {
        ry[k] = refl(2 * ty - 1 + k);
        rx[k] = refl(2 * tx - 1 + k);
    }

    float mx[16];
#pragma unroll
    for (int uv = 0; uv < 16; uv++) mx[uv] = 0.f;

    for (int c = t; c < GC; c += 256) {
        const float* gp = grid + (((size_t)n * GC + c) << 12);
        float d[4][4], X[16];
#pragma unroll
        for (int iy = 0; iy < 4; iy++)
#pragma unroll
            for (int ix = 0; ix < 4; ix++)
                d[iy][ix] = __ldg(gp + (ry[iy] << 6) + rx[ix]);
        wino_x(d, X);
#pragma unroll
        for (int uv = 0; uv < 16; uv++) mx[uv] = fmaxf(mx[uv], fabsf(X[uv]));
    }
#pragma unroll
    for (int uv = 0; uv < 16; uv++) redm[uv * 256 + t] = mx[uv];
    __syncthreads();
    for (int s = 128; s > 0; s >>= 1) {
        if (t < s)
#pragma unroll
            for (int uv = 0; uv < 16; uv++)
                redm[uv * 256 + t] = fmaxf(redm[uv * 256 + t], redm[uv * 256 + t + s]);
        __syncthreads();
    }
    if (t < 16) {
        float sc = redm[t * 256] / QMAX;
        d_xsc[(n * NT + tile) * 16 + t] = sc;
        scinv[t] = (sc > 0.f) ? 1.f / sc : 0.f;
    }
    __syncthreads();

    for (int c = t; c < GC; c += 256) {
        const float* gp = grid + (((size_t)n * GC + c) << 12);
        float d[4][4], X[16];
#pragma unroll
        for (int iy = 0; iy < 4; iy++)
#pragma unroll
            for (int ix = 0; ix < 4; ix++)
                d[iy][ix] = __ldg(gp + (ry[iy] << 6) + rx[ix]);
        wino_x(d, X);
#pragma unroll
        for (int uv = 0; uv < 16; uv++) {
            int8_t qh, ql;
            q15(X[uv], scinv[uv], qh, ql);
            size_t o = ((size_t)(uv * 2 + n) * NT + tile) * GC + c;
            d_xqh[o] = qh;
            d_xql[o] = ql;
        }
    }
}

// ============================================================================
// winograd GEMM (unchanged from R8): per (uv,n): M[tile][g] = X_t . W_t
// ============================================================================
__global__ __launch_bounds__(512, 1) void gemm_wino_kernel()
{
    extern __shared__ char smraw[];
    const uint32_t smb = smem_u32(smraw);
    const int tid  = threadIdx.x;
    const int wid  = tid >> 5;
    const int lane = tid & 31;
    const int nn0  = blockIdx.x * 128;
    const int m0   = blockIdx.y * 128;
    const int z    = blockIdx.z;             // uv*2+n
    const int n    = z & 1, uv = z >> 1;
    const int nk   = GC / 64;                // 34

    const int cr = tid >> 2;
    const int cc = (tid & 3) * 16;
    const char* pAh = (const char*)d_xqh;
    const char* pAl = (const char*)d_xql;
    const char* pBh = (const char*)d_wqh;
    const char* pBl = (const char*)d_wql;
    const size_t aoff = ((size_t)z * NT + m0 + cr) * GC + cc;
    const size_t boff = ((size_t)(nn0 + cr) * 16 + uv) * GC + cc;
    const uint32_t dd = (uint32_t)(cr * 80 + cc);

#define ISSUE8(t) do {                                               \
        uint32_t sb_ = smb + ((t) % NSTG) * STG8;                    \
        size_t kb_ = (size_t)(t) * 64;                               \
        CP16(sb_ + dd,             pAh + aoff + kb_);                \
        CP16(sb_ + TILE8 + dd,     pAl + aoff + kb_);                \
        CP16(sb_ + 2*TILE8 + dd,   pBh + boff + kb_);                \
        CP16(sb_ + 3*TILE8 + dd,   pBl + boff + kb_);                \
    } while (0)

    const int wm = wid >> 2;
    const int wn = wid & 3;
    const uint32_t aoffL = (uint32_t)((wm * 32 + (lane & 15)) * 80 + (lane >> 4) * 16);
    const uint32_t boffL = (uint32_t)((wn * 32 + ((lane >> 4) << 3) + (lane & 7)) * 80
                                      + ((lane >> 3) & 1) * 16);

    int acc1[2][4][4], acc2[2][4][4];
#pragma unroll
    for (int i = 0; i < 2; i++)
#pragma unroll
        for (int j = 0; j < 4; j++)
#pragma unroll
            for (int r = 0; r < 4; r++) { acc1[i][j][r] = 0; acc2[i][j][r] = 0; }

    ISSUE8(0); CP_COMMIT();
    ISSUE8(1); CP_COMMIT();

    for (int t = 0; t < nk; t++) {
        if (t + 2 < nk) ISSUE8(t + 2);
        CP_COMMIT();
        CP_WAIT2();
        __syncthreads();

        const uint32_t sb  = smb + (t % NSTG) * STG8;
        const uint32_t AhT = sb,             AlT = sb + TILE8;
        const uint32_t BhT = sb + 2 * TILE8, BlT = sb + 3 * TILE8;

#pragma unroll
        for (int ks = 0; ks < 2; ks++) {
            const uint32_t kb = ks * 32;
            uint32_t aH[8], aL[8], bH[8], bL[8];
            LDSM4(aH,     AhT + aoffL + kb);
            LDSM4(aH + 4, AhT + aoffL + 16 * 80 + kb);
            LDSM4(aL,     AlT + aoffL + kb);
            LDSM4(aL + 4, AlT + aoffL + 16 * 80 + kb);
            LDSM4(bH,     BhT + boffL + kb);
            LDSM4(bH + 4, BhT + boffL + 16 * 80 + kb);
            LDSM4(bL,     BlT + boffL + kb);
            LDSM4(bL + 4, BlT + boffL + 16 * 80 + kb);
#pragma unroll
            for (int i = 0; i < 2; i++)
#pragma unroll
                for (int j = 0; j < 4; j++) {
                    MMAS8(acc1[i][j], aH + 4 * i, bH[2 * j], bH[2 * j + 1]);
                    MMAS8(acc2[i][j], aH + 4 * i, bL[2 * j], bL[2 * j + 1]);
                    MMAS8(acc2[i][j], aL + 4 * i, bH[2 * j], bH[2 * j + 1]);
                }
        }
        __syncthreads();
    }

    // dequant + transpose -> [g][tile] fp32
    float* smf = (float*)smraw;              // [128][129]
    const float* asb = d_xsc + ((size_t)(n * NT + m0)) * 16 + uv;   // stride 16
    const float* wsb = d_wsc2 + (size_t)nn0 * 16 + uv;              // stride 16
#pragma unroll
    for (int i = 0; i < 2; i++) {
        int m = wm * 32 + i * 16 + (lane >> 2);
        float sa0 = asb[m * 16], sa1 = asb[(m + 8) * 16];
#pragma unroll
        for (int j = 0; j < 4; j++) {
            int col = wn * 32 + j * 8 + 2 * (lane & 3);
            float w0 = wsb[col * 16], w1 = wsb[(col + 1) * 16];
            float v0 = fmaf(65536.f, (float)acc1[i][j][0], 256.f * (float)acc2[i][j][0]);
            float v1 = fmaf(65536.f, (float)acc1[i][j][1], 256.f * (float)acc2[i][j][1]);
            float v2 = fmaf(65536.f, (float)acc1[i][j][2], 256.f * (float)acc2[i][j][2]);
            float v3 = fmaf(65536.f, (float)acc1[i][j][3], 256.f * (float)acc2[i][j][3]);
            smf[m * 129 + col]           = sa0 * w0 * v0;
            smf[m * 129 + col + 1]       = sa0 * w1 * v1;
            smf[(m + 8) * 129 + col]     = sa1 * w0 * v2;
            smf[(m + 8) * 129 + col + 1] = sa1 * w1 * v3;
        }
    }
    __syncthreads();

    const int g = tid >> 2;
    const int q = tid & 3;
    const size_t ob = (((size_t)n * GC + nn0 + g) * 16 + uv) * NT + m0 + q * 32;
#pragma unroll 1
    for (int pc = 0; pc < 8; pc++) {
        float4 v;
        v.x = smf[(q * 32 + pc * 4 + 0) * 129 + g];
        v.y = smf[(q * 32 + pc * 4 + 1) * 129 + g];
        v.z = smf[(q * 32 + pc * 4 + 2) * 129 + g];
        v.w = smf[(q * 32 + pc * 4 + 3) * 129 + g];
        *(float4*)(d_mt + ob + pc * 4) = v;
    }
#undef ISSUE8
}

// ============================================================================
// fused output transform + bias + rowmax + q15 quantize: one block per (n,g)
// ============================================================================
__global__ void outtrans_q_kernel(const float* __restrict__ bias)
{
    int g = blockIdx.x % GC;
    int n = blockIdx.x / GC;
    int t = threadIdx.x;
    __shared__ float y[4096];
    __shared__ float red[256];

    const float* mb = d_mt + (((size_t)n * GC + g) * 16) * NT;
    float bv = bias[g];
    float mx = 0.f;

#pragma unroll 1
    for (int it = 0; it < 4; it++) {
        int tile = t + it * 256;
        float M[16];
#pragma unroll
        for (int uv = 0; uv < 16; uv++) M[uv] = mb[(size_t)uv * NT + tile];

        float T0[4], T1[4];
#pragma unroll
        for (int j = 0; j < 4; j++) {
            T0[j] = M[j] + M[4 + j] + M[8 + j];
            T1[j] = M[4 + j] - M[8 + j] - M[12 + j];
        }
        float y00 = T0[0] + T0[1] + T0[2] + bv;
        float y01 = T0[1] - T0[2] - T0[3] + bv;
        float y10 = T1[0] + T1[1] + T1[2] + bv;
        float y11 = T1[1] - T1[2] - T1[3] + bv;

        int ty = tile >> 5, tx = tile & 31;
        int p0 = (ty << 7) + (tx << 1);
        y[p0]      = y00;
        y[p0 + 1]  = y01;
        y[p0 + 64] = y10;
        y[p0 + 65] = y11;
        mx = fmaxf(mx, fmaxf(fmaxf(fabsf(y00), fabsf(y01)),
                             fmaxf(fabsf(y10), fabsf(y11))));
    }
    red[t] = mx; __syncthreads();
    for (int s = 128; s > 0; s >>= 1) {
        if (t < s) red[t] = fmaxf(red[t], red[t + s]);
        __syncthreads();
    }
    float sc = red[0] / QMAX;
    if (t == 0) d_srsc[n * GC + g] = sc;
    float inv = (sc > 0.f) ? 1.f / sc : 0.f;

    size_t base = ((size_t)n * GC + g) * HW;
#pragma unroll 1
    for (int i = t * 4; i < 4096; i += 1024) {
        char4 h4, l4;
        int8_t qh, ql;
        q15(y[i + 0], inv, qh, ql); h4.x = qh; l4.x = ql;
        q15(y[i + 1], inv, qh, ql); h4.y = qh; l4.y = ql;
        q15(y[i + 2], inv, qh, ql); h4.z = qh; l4.z = ql;
        q15(y[i + 3], inv, qh, ql); h4.w = qh; l4.w = ql;
        *(char4*)(d_srqh + base + i) = h4;
        *(char4*)(d_srql + base + i) = l4;
    }
}

// ============================================================================
// GEMM2 int8 split: out[n,g,i] = sum_j cs[n,i,j]*sr[n,g,j], fp32 out.
// 512 thr = 16 warps (4m x 4n), warp tile 32x32, BK=64, nk=64.
// ============================================================================
__global__ __launch_bounds__(512, 1) void gemm2_s8_kernel(float* __restrict__ of)
{
    extern __shared__ char smraw[];
    const uint32_t smb = smem_u32(smraw);
    const int tid  = threadIdx.x;
    const int wid  = tid >> 5;
    const int lane = tid & 31;
    const int nn0  = blockIdx.x * 128;       // g tile
    const int m0   = blockIdx.y * 128;       // pixel tile (i)
    const int nz   = blockIdx.z;
    const int nk   = HW / 64;                // 64

    const int cr = tid >> 2;
    const int cc = (tid & 3) * 16;
    const char* pAh = (const char*)d_csqh;
    const char* pAl = (const char*)d_csql;
    const char* pBh = (const char*)d_srqh;
    const char* pBl = (const char*)d_srql;
    const size_t aoff = (size_t)(m0 + cr) * HW + (size_t)nz * HW * HW + cc;
    const size_t boff = (size_t)(nn0 + cr) * HW + (size_t)nz * GC * HW + cc;
    const uint32_t dd = (uint32_t)(cr * 80 + cc);

#define ISSUE2(t) do {                                               \
        uint32_t sb_ = smb + ((t) % NSTG) * STG8;                    \
        size_t kb_ = (size_t)(t) * 64;                               \
        CP16(sb_ + dd,             pAh + aoff + kb_);                \
        CP16(sb_ + TILE8 + dd,     pAl + aoff + kb_);                \
        CP16(sb_ + 2*TILE8 + dd,   pBh + boff + kb_);                \
        CP16(sb_ + 3*TILE8 + dd,   pBl + boff + kb_);                \
    } while (0)

    const int wm = wid >> 2;
    const int wn = wid & 3;
    const uint32_t aoffL = (uint32_t)((wm * 32 + (lane & 15)) * 80 + (lane >> 4) * 16);
    const uint32_t boffL = (uint32_t)((wn * 32 + ((lane >> 4) << 3) + (lane & 7)) * 80
                                      + ((lane >> 3) & 1) * 16);

    int acc1[2][4][4], acc2[2][4][4];
#pragma unroll
    for (int i = 0; i < 2; i++)
#pragma unroll
        for (int j = 0; j < 4; j++)
#pragma unroll
            for (int r = 0; r < 4; r++) { acc1[i][j][r] = 0; acc2[i][j][r] = 0; }

    ISSUE2(0); CP_COMMIT();
    ISSUE2(1); CP_COMMIT();

    for (int t = 0; t < nk; t++) {
        if (t + 2 < nk) ISSUE2(t + 2);
        CP_COMMIT();
        CP_WAIT2();
        __syncthreads();

        const uint32_t sb  = smb + (t % NSTG) * STG8;
        const uint32_t AhT = sb,             AlT = sb + TILE8;
        const uint32_t BhT = sb + 2 * TILE8, BlT = sb + 3 * TILE8;

#pragma unroll
        for (int ks = 0; ks < 2; ks++) {
            const uint32_t kb = ks * 32;
            uint32_t aH[8], aL[8], bH[8], bL[8];
            LDSM4(aH,     AhT + aoffL + kb);
            LDSM4(aH + 4, AhT + aoffL + 16 * 80 + kb);
            LDSM4(aL,     AlT + aoffL + kb);
            LDSM4(aL + 4, AlT + aoffL + 16 * 80 + kb);
            LDSM4(bH,     BhT + boffL + kb);
            LDSM4(bH + 4, BhT + boffL + 16 * 80 + kb);
            LDSM4(bL,     BlT + boffL + kb);
            LDSM4(bL + 4, BlT + boffL + 16 * 80 + kb);
#pragma unroll
            for (int i = 0; i < 2; i++)
#pragma unroll
                for (int j = 0; j < 4; j++) {
                    MMAS8(acc1[i][j], aH + 4 * i, bH[2 * j], bH[2 * j + 1]);
                    MMAS8(acc2[i][j], aH + 4 * i, bL[2 * j], bL[2 * j + 1]);
                    MMAS8(acc2[i][j], aL + 4 * i, bH[2 * j], bH[2 * j + 1]);
                }
        }
        __syncthreads();
    }

    // dequant + transpose -> [g][i] fp32
    float* smf = (float*)smraw;              // [128][129]
    const float* asb = d_cssc + (size_t)nz * HW + m0;
    const float* wsb = d_srsc + (size_t)nz * GC + nn0;
#pragma unroll
    for (int i = 0; i < 2; i++) {
        int m = wm * 32 + i * 16 + (lane >> 2);
        float sa0 = asb[m], sa1 = asb[m + 8];
#pragma unroll
        for (int j = 0; j < 4; j++) {
            int col = wn * 32 + j * 8 + 2 * (lane & 3);
            float w0 = wsb[col], w1 = wsb[col + 1];
            float v0 = fmaf(65536.f, (float)acc1[i][j][0], 256.f * (float)acc2[i][j][0]);
            float v1 = fmaf(65536.f, (float)acc1[i][j][1], 256.f * (float)acc2[i][j][1]);
            float v2 = fmaf(65536.f, (float)acc1[i][j][2], 256.f * (float)acc2[i][j][2]);
            float v3 = fmaf(65536.f, (float)acc1[i][j][3], 256.f * (float)acc2[i][j][3]);
            smf[m * 129 + col]           = sa0 * w0 * v0;
            smf[m * 129 + col + 1]       = sa0 * w1 * v1;
            smf[(m + 8) * 129 + col]     = sa1 * w0 * v2;
            smf[(m + 8) * 129 + col + 1] = sa1 * w1 * v3;
        }
    }
    __syncthreads();

    const int g = tid >> 2;                  // g-local row
    const int q = tid & 3;                   // pixel quarter
    const size_t orow = ((size_t)nz * GC + nn0 + g) * HW + m0 + q * 32;
#pragma unroll 1
    for (int pc = 0; pc < 8; pc++) {
        float4 v;
        v.x = smf[(q * 32 + pc * 4 + 0) * 129 + g];
        v.y = smf[(q * 32 + pc * 4 + 1) * 129 + g];
        v.z = smf[(q * 32 + pc * 4 + 2) * 129 + g];
        v.w = smf[(q * 32 + pc * 4 + 3) * 129 + g];
        *(float4*)(of + orow + pc * 4) = v;
    }
#undef ISSUE2
}

// ============================================================================
// launch
// ============================================================================
extern "C" void kernel_launch(void* const* d_in, const int* in_sizes, int n_in,
                              void* d_out, int out_size)
{
    const float* c    = (const float*)d_in[0];
    const float* s    = (const float*)d_in[1];
    const float* grid = (const float*)d_in[2];
    const float* wc1  = (const float*)d_in[3];
    const float* bc1  = (const float*)d_in[4];
    const float* wc2  = (const float*)d_in[5];
    const float* bc2  = (const float*)d_in[6];
    const float* ws1  = (const float*)d_in[7];
    const float* bs1  = (const float*)d_in[8];
    const float* ws2  = (const float*)d_in[9];
    const float* bs2  = (const float*)d_in[10];
    const float* wsr  = (const float*)d_in[11];
    const float* bsr  = (const float*)d_in[12];
    float* out = (float*)d_out;

    float *h1, *c1, *s1, *A;
    cudaGetSymbolAddress((void**)&h1, d_h1);
    cudaGetSymbolAddress((void**)&c1, d_c1);
    cudaGetSymbolAddress((void**)&s1, d_s1);
    cudaGetSymbolAddress((void**)&A,  d_A);

    cudaFuncSetAttribute(gemm_wino_kernel,
                         cudaFuncAttributeMaxDynamicSharedMemorySize, SMEM_DYN);
    cudaFuncSetAttribute(gemm2_s8_kernel,
                         cudaFuncAttributeMaxDynamicSharedMemorySize, SMEM_DYN);

    // branches
    conv16_kernel<<<(2*16*128*128 + 255) / 256, 256>>>(c,  wc1, bc1, h1, 256, 128, 2, 1);
    conv16_kernel<<<(2*16*64*64   + 255) / 256, 256>>>(h1, wc2, bc2, c1, 128, 64,  2, 0);
    conv16_kernel<<<(2*16*128*128 + 255) / 256, 256>>>(s,  ws1, bs1, h1, 256, 128, 2, 1);
    conv16_kernel<<<(2*16*64*64   + 255) / 256, 256>>>(h1, ws2, bs2, s1, 128, 64,  2, 0);

    // affinity + softmax (emits int8 q15 cs + row scales)
    {
        dim3 b(32, 8), g(HW / 32, HW / 8, 2);
        affinity_kernel<<<g, b>>>(c1, s1, A);
    }
    softmax_q_kernel<<<2 * HW, 256>>>(A);

    // fused winograd operand prep
    wprep_kernel<<<GC, 256>>>(wsr);
    xprep_kernel<<<2 * NT, 256>>>(grid);

    // GEMM1 in winograd domain + fused inverse transform / quantize
    {
        dim3 g(GC / 128, NT / 128, 32);
        gemm_wino_kernel<<<g, 512, SMEM_DYN>>>();
    }
    outtrans_q_kernel<<<2 * GC, 256>>>(bsr);

    // GEMM2 int8 split -> fp32 out
    {
        dim3 g(GC / 128, HW / 128, 2);
        gemm2_s8_kernel<<<g, 512, SMEM_DYN>>>(out);
    }
}

// round 11
// speedup vs baseline: 6.1195x; 1.0739x over previous
#include <cuda_runtime.h>
#include <math.h>
#include <stdint.h>

// ============================================================================
// AttModule (sm_100-safe PTX, legacy tensor cores) — all-int8 tensor path.
//   GEMM1 via Winograd F(2x2,3x3): int8 two-word split (3 IMMA per k32).
//   GEMM2: cs as UNSIGNED 16-bit two-word (u8.s8 MMA), sr as signed q15.
//   Coalesced winograd input prep (smem strip + atomicMax scales).
//   Fused affinity+softmax+quantize (no logits roundtrip).
// ============================================================================

#define HW    4096
#define GC    2176
#define KC1   19584
#define NT    1024
#define QMAX  32512.0f      // 127*256 (signed q15)

#define TILE8 10240         // 128 rows * 80B
#define STG8  (4*TILE8)
#define NSTG  3
#define SMEM_DYN (NSTG*STG8)     // 122880
#define SMEM_XM  (64*257*4)      // 65792 strip
#define SMEM_XQ  (64*257*4 + 512*4)

// ---------------- scratch ----------------------------------------------------
static __device__ float   d_h1[2*16*128*128];
static __device__ float   d_c1[2*16*HW];
static __device__ float   d_s1[2*16*HW];
// GEMM2 operands
static __device__ int8_t  d_csqh[(size_t)2*HW*HW];   // u8 bits
static __device__ int8_t  d_csql[(size_t)2*HW*HW];   // u8 bits
static __device__ float   d_cssc[2*HW];
static __device__ int8_t  d_srqh[(size_t)2*GC*HW];
static __device__ int8_t  d_srql[(size_t)2*GC*HW];
static __device__ float   d_srsc[2*GC];
// winograd weights
static __device__ int8_t  d_wqh[(size_t)GC*16*GC];
static __device__ int8_t  d_wql[(size_t)GC*16*GC];
static __device__ float   d_wsc2[GC*16];
// winograd inputs
static __device__ int8_t  d_xqh[(size_t)32*NT*GC];
static __device__ int8_t  d_xql[(size_t)32*NT*GC];
static __device__ float   d_xsc[2*NT*16];
static __device__ int     d_xsci[2*NT*16];
// GEMM1 wino-domain outputs [n][g][uv][tile]
static __device__ float   d_mt[(size_t)2*GC*16*NT];

// ---------------- PTX helpers ------------------------------------------------
__device__ __forceinline__ uint32_t smem_u32(const void* p) {
    uint32_t a;
    asm("{ .reg .u64 t; cvta.to.shared.u64 t, %1; cvt.u32.u64 %0, t; }"
        : "=r"(a) : "l"(p));
    return a;
}

#define CP16(d, s) \
    asm volatile("cp.async.cg.shared.global [%0], [%1], 16;" :: "r"(d), "l"(s))
#define CP_COMMIT() asm volatile("cp.async.commit_group;" ::: "memory")
#define CP_WAIT2()  asm volatile("cp.async.wait_group 2;" ::: "memory")

#define LDSM4(r, addr) \
    asm volatile("ldmatrix.sync.aligned.m8n8.x4.shared.b16 {%0,%1,%2,%3}, [%4];" \
        : "=r"((r)[0]), "=r"((r)[1]), "=r"((r)[2]), "=r"((r)[3]) : "r"(addr))

#define MMAS8(d, a, b0, b1) \
    asm volatile("mma.sync.aligned.m16n8k32.row.col.s32.s8.s8.s32 " \
        "{%0,%1,%2,%3}, {%4,%5,%6,%7}, {%8,%9}, {%0,%1,%2,%3};" \
        : "+r"((d)[0]), "+r"((d)[1]), "+r"((d)[2]), "+r"((d)[3]) \
        : "r"((a)[0]), "r"((a)[1]), "r"((a)[2]), "r"((a)[3]), "r"(b0), "r"(b1))

#define MMAU8(d, a, b0, b1) \
    asm volatile("mma.sync.aligned.m16n8k32.row.col.s32.u8.s8.s32 " \
        "{%0,%1,%2,%3}, {%4,%5,%6,%7}, {%8,%9}, {%0,%1,%2,%3};" \
        : "+r"((d)[0]), "+r"((d)[1]), "+r"((d)[2]), "+r"((d)[3]) \
        : "r"((a)[0]), "r"((a)[1]), "r"((a)[2]), "r"((a)[3]), "r"(b0), "r"(b1))

__device__ __forceinline__ void q15(float v, float inv, int8_t& qh, int8_t& ql)
{
    int q = __float2int_rn(v * inv);
    q = max(-32512, min(32512, q));
    int ah = (q + 128) >> 8;
    qh = (int8_t)ah;
    ql = (int8_t)(q - (ah << 8));
}

__device__ __forceinline__ int refl(int y) { return y < 0 ? 1 : (y > 63 ? 62 : y); }

__device__ __forceinline__ void wino_w(const float* w9, float W[16])
{
    float V[4][3];
#pragma unroll
    for (int j = 0; j < 3; j++) {
        float g0 = w9[j], g1 = w9[3 + j], g2 = w9[6 + j];
        V[0][j] = g0;
        V[1][j] = 0.5f * (g0 + g1 + g2);
        V[2][j] = 0.5f * (g0 - g1 + g2);
        V[3][j] = g2;
    }
#pragma unroll
    for (int i = 0; i < 4; i++) {
        float v0 = V[i][0], v1 = V[i][1], v2 = V[i][2];
        W[i * 4 + 0] = v0;
        W[i * 4 + 1] = 0.5f * (v0 + v1 + v2);
        W[i * 4 + 2] = 0.5f * (v0 - v1 + v2);
        W[i * 4 + 3] = v2;
    }
}

__device__ __forceinline__ void wino_x(const float d[4][4], float X[16])
{
    float U[4][4];
#pragma unroll
    for (int j = 0; j < 4; j++) {
        U[0][j] = d[0][j] - d[2][j];
        U[1][j] = d[1][j] + d[2][j];
        U[2][j] = d[2][j] - d[1][j];
        U[3][j] = d[1][j] - d[3][j];
    }
#pragma unroll
    for (int i = 0; i < 4; i++) {
        X[i * 4 + 0] = U[i][0] - U[i][2];
        X[i * 4 + 1] = U[i][1] + U[i][2];
        X[i * 4 + 2] = U[i][2] - U[i][1];
        X[i * 4 + 3] = U[i][1] - U[i][3];
    }
}

// ============================================================================
// branch convs
// ============================================================================
__global__ void conv16_kernel(const float* __restrict__ in,
                              const float* __restrict__ w,
                              const float* __restrict__ b,
                              float* __restrict__ out,
                              int Hin, int Hout, int stride, int relu)
{
    int idx = blockIdx.x * blockDim.x + threadIdx.x;
    int total = 2 * 16 * Hout * Hout;
    if (idx >= total) return;
    int ox = idx % Hout;
    int oy = (idx / Hout) % Hout;
    int oc = (idx / (Hout * Hout)) % 16;
    int n  = idx / (Hout * Hout * 16);

    const float* wp = w + oc * 16 * 9;
    const float* ip = in + (size_t)n * 16 * Hin * Hin;

    int iy[3], ix[3];
#pragma unroll
    for (int k = 0; k < 3; k++) {
        int y = oy * stride - 1 + k;
        iy[k] = (y < 0) ? 1 : ((y >= Hin) ? Hin - 2 : y);
        int x = ox * stride - 1 + k;
        ix[k] = (x < 0) ? 1 : ((x >= Hin) ? Hin - 2 : x);
    }

    float acc = b[oc];
    for (int ic = 0; ic < 16; ic++) {
        const float* ipc = ip + (size_t)ic * Hin * Hin;
        const float* wpc = wp + ic * 9;
#pragma unroll
        for (int ky = 0; ky < 3; ky++) {
            const float* row = ipc + (size_t)iy[ky] * Hin;
#pragma unroll
            for (int kx = 0; kx < 3; kx++)
                acc += wpc[ky * 3 + kx] * __ldg(row + ix[kx]);
        }
    }
    out[idx] = relu ? fmaxf(acc, 0.f) : acc;
}

// ============================================================================
// fused affinity + softmax + u16 quantize. Block = (8 rows, n). 256 thr.
// pass1: logits + rowmax (no exp). pass2: logits + exp + quantize + sum.
// ============================================================================
__global__ __launch_bounds__(256) void affsoft_kernel(const float* __restrict__ c1,
                                                      const float* __restrict__ s1)
{
    const int n  = blockIdx.y;
    const int r0 = blockIdx.x * 8;
    const int t  = threadIdx.x;
    __shared__ float c1s[16][8];
    __shared__ float red[256];
    __shared__ float mrow[8];

    if (t < 128) {
        int c = t >> 3, r = t & 7;
        c1s[c][r] = c1[((size_t)n * 16 + c) * HW + r0 + r];
    }
    __syncthreads();
    const float* s1n = s1 + (size_t)n * 16 * HW;

    float m8[8];
#pragma unroll
    for (int r = 0; r < 8; r++) m8[r] = -INFINITY;

    for (int j = t; j < HW; j += 256) {
        float sv[16];
#pragma unroll
        for (int c = 0; c < 16; c++) sv[c] = s1n[(size_t)c * HW + j];
#pragma unroll
        for (int r = 0; r < 8; r++) {
            float l = 0.f;
#pragma unroll
            for (int c = 0; c < 16; c++) l += c1s[c][r] * sv[c];
            m8[r] = fmaxf(m8[r], l);
        }
    }
#pragma unroll 1
    for (int r = 0; r < 8; r++) {
        red[t] = m8[r]; __syncthreads();
        for (int s = 128; s > 0; s >>= 1) {
            if (t < s) red[t] = fmaxf(red[t], red[t + s]);
            __syncthreads();
        }
        if (t == 0) mrow[r] = red[0];
        __syncthreads();
    }

    float s8v[8];
#pragma unroll
    for (int r = 0; r < 8; r++) s8v[r] = 0.f;

    for (int j = t; j < HW; j += 256) {
        float sv[16];
#pragma unroll
        for (int c = 0; c < 16; c++) sv[c] = s1n[(size_t)c * HW + j];
#pragma unroll
        for (int r = 0; r < 8; r++) {
            float l = 0.f;
#pragma unroll
            for (int c = 0; c < 16; c++) l += c1s[c][r] * sv[c];
            float e = __expf(l - mrow[r]);
            s8v[r] += e;
            int q = __float2int_rn(e * 65535.f);
            q = max(0, min(65535, q));
            size_t o = ((size_t)n * HW + r0 + r) * HW + j;
            d_csqh[o] = (int8_t)(uint8_t)(q >> 8);
            d_csql[o] = (int8_t)(uint8_t)(q & 255);
        }
    }
#pragma unroll 1
    for (int r = 0; r < 8; r++) {
        red[t] = s8v[r]; __syncthreads();
        for (int s = 128; s > 0; s >>= 1) {
            if (t < s) red[t] += red[t + s];
            __syncthreads();
        }
        if (t == 0) d_cssc[n * HW + r0 + r] = 1.f / (65535.f * red[0]);
        __syncthreads();
    }
}

// ============================================================================
// winograd weight prep (2-pass recompute, per-g block)
// ============================================================================
__global__ void wprep_kernel(const float* __restrict__ wsr)
{
    int g = blockIdx.x;
    int t = threadIdx.x;
    __shared__ float redm[16 * 256];
    __shared__ float scinv[16];

    float mx[16];
#pragma unroll
    for (int uv = 0; uv < 16; uv++) mx[uv] = 0.f;

    for (int c = t; c < GC; c += 256) {
        float w9[9], W[16];
        const float* wp = wsr + (size_t)g * KC1 + c * 9;
#pragma unroll
        for (int k = 0; k < 9; k++) w9[k] = wp[k];
        wino_w(w9, W);
#pragma unroll
        for (int uv = 0; uv < 16; uv++) mx[uv] = fmaxf(mx[uv], fabsf(W[uv]));
    }
#pragma unroll
    for (int uv = 0; uv < 16; uv++) redm[uv * 256 + t] = mx[uv];
    __syncthreads();
    for (int s = 128; s > 0; s >>= 1) {
        if (t < s)
#pragma unroll
            for (int uv = 0; uv < 16; uv++)
                redm[uv * 256 + t] = fmaxf(redm[uv * 256 + t], redm[uv * 256 + t + s]);
        __syncthreads();
    }
    if (t < 16) {
        float sc = redm[t * 256] / QMAX;
        d_wsc2[g * 16 + t] = sc;
        scinv[t] = (sc > 0.f) ? 1.f / sc : 0.f;
    }
    __syncthreads();

    for (int c = t; c < GC; c += 256) {
        float w9[9], W[16];
        const float* wp = wsr + (size_t)g * KC1 + c * 9;
#pragma unroll
        for (int k = 0; k < 9; k++) w9[k] = wp[k];
        wino_w(w9, W);
#pragma unroll
        for (int uv = 0; uv < 16; uv++) {
            int8_t qh, ql;
            q15(W[uv], scinv[uv], qh, ql);
            size_t o = ((size_t)g * 16 + uv) * GC + c;
            d_wqh[o] = qh;
            d_wql[o] = ql;
        }
    }
}

// ============================================================================
// winograd input prep, coalesced: strip = 4 source rows x 64 px x 64 ch in smem
// block = (cgroup 0..33, ty 0..31, n 0..1)
// ============================================================================
__global__ void zeroxsc_kernel()
{
    int i = blockIdx.x * blockDim.x + threadIdx.x;
    if (i < 2 * NT * 16) d_xsci[i] = 0;
}

__global__ __launch_bounds__(256) void xmax2_kernel(const float* __restrict__ grid)
{
    extern __shared__ float strip[];          // [64][257]
    int bid = blockIdx.x;
    int cg = bid % 34;
    int ty = (bid / 34) % 32;
    int n  = bid / (34 * 32);
    int c0 = cg * 64;
    int t  = threadIdx.x;

    int ry[4];
#pragma unroll
    for (int k = 0; k < 4; k++) ry[k] = refl(2 * ty - 1 + k);

    for (int idx = t; idx < 64 * 256; idx += 256) {
        int ch = idx >> 8;
        int rpx = idx & 255;
        int r = rpx >> 6, px = rpx & 63;
        strip[ch * 257 + rpx] =
            grid[(((size_t)n * GC + c0 + ch) << 12) + (ry[r] << 6) + px];
    }
    __syncthreads();

    const int tx = t & 31;
    const int w  = t >> 5;                    // 0..7, channels w*8..w*8+7
    int rx[4];
#pragma unroll
    for (int k = 0; k < 4; k++) rx[k] = refl(2 * tx - 1 + k);

    float mx[16];
#pragma unroll
    for (int uv = 0; uv < 16; uv++) mx[uv] = 0.f;

#pragma unroll 1
    for (int cc = 0; cc < 8; cc++) {
        int ch = w * 8 + cc;
        float d[4][4], X[16];
#pragma unroll
        for (int r = 0; r < 4; r++)
#pragma unroll
            for (int k = 0; k < 4; k++)
                d[r][k] = strip[ch * 257 + r * 64 + rx[k]];
        wino_x(d, X);
#pragma unroll
        for (int uv = 0; uv < 16; uv++) mx[uv] = fmaxf(mx[uv], fabsf(X[uv]));
    }
    __syncthreads();
    // reduce 8 threads per tx via smem (reuse strip)
#pragma unroll
    for (int uv = 0; uv < 16; uv++) strip[(tx * 8 + w) * 16 + uv] = mx[uv];
    __syncthreads();
    if (t < 32) {
#pragma unroll
        for (int uv = 0; uv < 16; uv++) {
            float m = 0.f;
#pragma unroll
            for (int ww = 0; ww < 8; ww++)
                m = fmaxf(m, strip[(t * 8 + ww) * 16 + uv]);
            atomicMax(&d_xsci[(n * NT + ty * 32 + t) * 16 + uv], __float_as_int(m));
        }
    }
}

__global__ void xscconv_kernel()
{
    int i = blockIdx.x * blockDim.x + threadIdx.x;
    if (i < 2 * NT * 16) d_xsc[i] = __int_as_float(d_xsci[i]) / QMAX;
}

__global__ __launch_bounds__(256) void xq2_kernel(const float* __restrict__ grid)
{
    extern __shared__ float smdyn[];
    float* strip = smdyn;                     // [64][257]
    float* sci   = smdyn + 64 * 257;          // [32][16]
    int bid = blockIdx.x;
    int cg = bid % 34;
    int ty = (bid / 34) % 32;
    int n  = bid / (34 * 32);
    int c0 = cg * 64;
    int t  = threadIdx.x;

    int ry[4];
#pragma unroll
    for (int k = 0; k < 4; k++) ry[k] = refl(2 * ty - 1 + k);

    for (int idx = t; idx < 64 * 256; idx += 256) {
        int ch = idx >> 8;
        int rpx = idx & 255;
        int r = rpx >> 6, px = rpx & 63;
        strip[ch * 257 + rpx] =
            grid[(((size_t)n * GC + c0 + ch) << 12) + (ry[r] << 6) + px];
    }
    for (int i = t; i < 512; i += 256) {
        int tx = i >> 4, uv = i & 15;
        float mxv = __int_as_float(d_xsci[(n * NT + ty * 32 + tx) * 16 + uv]);
        sci[i] = (mxv > 0.f) ? QMAX / mxv : 0.f;
    }
    __syncthreads();

    const int w    = t >> 5;                  // warp -> tx group of 4
    const int lane = t & 31;
#pragma unroll 1
    for (int q = 0; q < 4; q++) {
        int tx = w * 4 + q;
        int rx[4];
#pragma unroll
        for (int k = 0; k < 4; k++) rx[k] = refl(2 * tx - 1 + k);
#pragma unroll 1
        for (int h = 0; h < 2; h++) {
            int ch = lane + 32 * h;
            float d[4][4], X[16];
#pragma unroll
            for (int r = 0; r < 4; r++)
#pragma unroll
                for (int k = 0; k < 4; k++)
                    d[r][k] = strip[ch * 257 + r * 64 + rx[k]];
            wino_x(d, X);
#pragma unroll
            for (int uv = 0; uv < 16; uv++) {
                int8_t qh, ql;
                q15(X[uv], sci[tx * 16 + uv], qh, ql);
                size_t o = ((size_t)(uv * 2 + n) * NT + ty * 32 + tx) * GC + c0 + ch;
                d_xqh[o] = qh;
                d_xql[o] = ql;
            }
        }
    }
}

// ============================================================================
// winograd GEMM (unchanged): per (uv,n): M[tile][g] = X_t . W_t
// ============================================================================
__global__ __launch_bounds__(512, 1) void gemm_wino_kernel()
{
    extern __shared__ char smraw[];
    const uint32_t smb = smem_u32(smraw);
    const int tid  = threadIdx.x;
    const int wid  = tid >> 5;
    const int lane = tid & 31;
    const int nn0  = blockIdx.x * 128;
    const int m0   = blockIdx.y * 128;
    const int z    = blockIdx.z;
    const int n    = z & 1, uv = z >> 1;
    const int nk   = GC / 64;

    const int cr = tid >> 2;
    const int cc = (tid & 3) * 16;
    const char* pAh = (const char*)d_xqh;
    const char* pAl = (const char*)d_xql;
    const char* pBh = (const char*)d_wqh;
    const char* pBl = (const char*)d_wql;
    const size_t aoff = ((size_t)z * NT + m0 + cr) * GC + cc;
    const size_t boff = ((size_t)(nn0 + cr) * 16 + uv) * GC + cc;
    const uint32_t dd = (uint32_t)(cr * 80 + cc);

#define ISSUE8(t) do {                                               \
        uint32_t sb_ = smb + ((t) % NSTG) * STG8;                    \
        size_t kb_ = (size_t)(t) * 64;                               \
        CP16(sb_ + dd,             pAh + aoff + kb_);                \
        CP16(sb_ + TILE8 + dd,     pAl + aoff + kb_);                \
        CP16(sb_ + 2*TILE8 + dd,   pBh + boff + kb_);                \
        CP16(sb_ + 3*TILE8 + dd,   pBl + boff + kb_);                \
    } while (0)

    const int wm = wid >> 2;
    const int wn = wid & 3;
    const uint32_t aoffL = (uint32_t)((wm * 32 + (lane & 15)) * 80 + (lane >> 4) * 16);
    const uint32_t boffL = (uint32_t)((wn * 32 + ((lane >> 4) << 3) + (lane & 7)) * 80
                                      + ((lane >> 3) & 1) * 16);

    int acc1[2][4][4], acc2[2][4][4];
#pragma unroll
    for (int i = 0; i < 2; i++)
#pragma unroll
        for (int j = 0; j < 4; j++)
#pragma unroll
            for (int r = 0; r < 4; r++) { acc1[i][j][r] = 0; acc2[i][j][r] = 0; }

    ISSUE8(0); CP_COMMIT();
    ISSUE8(1); CP_COMMIT();

    for (int t = 0; t < nk; t++) {
        if (t + 2 < nk) ISSUE8(t + 2);
        CP_COMMIT();
        CP_WAIT2();
        __syncthreads();

        const uint32_t sb  = smb + (t % NSTG) * STG8;
        const uint32_t AhT = sb,             AlT = sb + TILE8;
        const uint32_t BhT = sb + 2 * TILE8, BlT = sb + 3 * TILE8;

#pragma unroll
        for (int ks = 0; ks < 2; ks++) {
            const uint32_t kb = ks * 32;
            uint32_t aH[8], aL[8], bH[8], bL[8];
            LDSM4(aH,     AhT + aoffL + kb);
            LDSM4(aH + 4, AhT + aoffL + 16 * 80 + kb);
            LDSM4(aL,     AlT + aoffL + kb);
            LDSM4(aL + 4, AlT + aoffL + 16 * 80 + kb);
            LDSM4(bH,     BhT + boffL + kb);
            LDSM4(bH + 4, BhT + boffL + 16 * 80 + kb);
            LDSM4(bL,     BlT + boffL + kb);
            LDSM4(bL + 4, BlT + boffL + 16 * 80 + kb);
#pragma unroll
            for (int i = 0; i < 2; i++)
#pragma unroll
                for (int j = 0; j < 4; j++) {
                    MMAS8(acc1[i][j], aH + 4 * i, bH[2 * j], bH[2 * j + 1]);
                    MMAS8(acc2[i][j], aH + 4 * i, bL[2 * j], bL[2 * j + 1]);
                    MMAS8(acc2[i][j], aL + 4 * i, bH[2 * j], bH[2 * j + 1]);
                }
        }
        __syncthreads();
    }

    float* smf = (float*)smraw;              // [128][129]
    const float* asb = d_xsc + ((size_t)(n * NT + m0)) * 16 + uv;
    const float* wsb = d_wsc2 + (size_t)nn0 * 16 + uv;
#pragma unroll
    for (int i = 0; i < 2; i++) {
        int m = wm * 32 + i * 16 + (lane >> 2);
        float sa0 = asb[m * 16], sa1 = asb[(m + 8) * 16];
#pragma unroll
        for (int j = 0; j < 4; j++) {
            int col = wn * 32 + j * 8 + 2 * (lane & 3);
            float w0 = wsb[col * 16], w1 = wsb[(col + 1) * 16];
            float v0 = fmaf(65536.f, (float)acc1[i][j][0], 256.f * (float)acc2[i][j][0]);
            float v1 = fmaf(65536.f, (float)acc1[i][j][1], 256.f * (float)acc2[i][j][1]);
            float v2 = fmaf(65536.f, (float)acc1[i][j][2], 256.f * (float)acc2[i][j][2]);
            float v3 = fmaf(65536.f, (float)acc1[i][j][3], 256.f * (float)acc2[i][j][3]);
            smf[m * 129 + col]           = sa0 * w0 * v0;
            smf[m * 129 + col + 1]       = sa0 * w1 * v1;
            smf[(m + 8) * 129 + col]     = sa1 * w0 * v2;
            smf[(m + 8) * 129 + col + 1] = sa1 * w1 * v3;
        }
    }
    __syncthreads();

    const int g = tid >> 2;
    const int q = tid & 3;
    const size_t ob = (((size_t)n * GC + nn0 + g) * 16 + uv) * NT + m0 + q * 32;
#pragma unroll 1
    for (int pc = 0; pc < 8; pc++) {
        float4 v;
        v.x = smf[(q * 32 + pc * 4 + 0) * 129 + g];
        v.y = smf[(q * 32 + pc * 4 + 1) * 129 + g];
        v.z = smf[(q * 32 + pc * 4 + 2) * 129 + g];
        v.w = smf[(q * 32 + pc * 4 + 3) * 129 + g];
        *(float4*)(d_mt + ob + pc * 4) = v;
    }
#undef ISSUE8
}

// ============================================================================
// output transform + bias + rowmax + q15 quantize (unchanged)
// ============================================================================
__global__ void outtrans_q_kernel(const float* __restrict__ bias)
{
    int g = blockIdx.x % GC;
    int n = blockIdx.x / GC;
    int t = threadIdx.x;
    __shared__ float y[4096];
    __shared__ float red[256];

    const float* mb = d_mt + (((size_t)n * GC + g) * 16) * NT;
    float bv = bias[g];
    float mx = 0.f;

#pragma unroll 1
    for (int it = 0; it < 4; it++) {
        int tile = t + it * 256;
        float M[16];
#pragma unroll
        for (int uv = 0; uv < 16; uv++) M[uv] = mb[(size_t)uv * NT + tile];

        float T0[4], T1[4];
#pragma unroll
        for (int j = 0; j < 4; j++) {
            T0[j] = M[j] + M[4 + j] + M[8 + j];
            T1[j] = M[4 + j] - M[8 + j] - M[12 + j];
        }
        float y00 = T0[0] + T0[1] + T0[2] + bv;
        float y01 = T0[1] - T0[2] - T0[3] + bv;
        float y10 = T1[0] + T1[1] + T1[2] + bv;
        float y11 = T1[1] - T1[2] - T1[3] + bv;

        int ty = tile >> 5, tx = tile & 31;
        int p0 = (ty << 7) + (tx << 1);
        y[p0]      = y00;
        y[p0 + 1]  = y01;
        y[p0 + 64] = y10;
        y[p0 + 65] = y11;
        mx = fmaxf(mx, fmaxf(fmaxf(fabsf(y00), fabsf(y01)),
                             fmaxf(fabsf(y10), fabsf(y11))));
    }
    red[t] = mx; __syncthreads();
    for (int s = 128; s > 0; s >>= 1) {
        if (t < s) red[t] = fmaxf(red[t], red[t + s]);
        __syncthreads();
    }
    float sc = red[0] / QMAX;
    if (t == 0) d_srsc[n * GC + g] = sc;
    float inv = (sc > 0.f) ? 1.f / sc : 0.f;

    size_t base = ((size_t)n * GC + g) * HW;
#pragma unroll 1
    for (int i = t * 4; i < 4096; i += 1024) {
        char4 h4, l4;
        int8_t qh, ql;
        q15(y[i + 0], inv, qh, ql); h4.x = qh; l4.x = ql;
        q15(y[i + 1], inv, qh, ql); h4.y = qh; l4.y = ql;
        q15(y[i + 2], inv, qh, ql); h4.z = qh; l4.z = ql;
        q15(y[i + 3], inv, qh, ql); h4.w = qh; l4.w = ql;
        *(char4*)(d_srqh + base + i) = h4;
        *(char4*)(d_srql + base + i) = l4;
    }
}

// ============================================================================
// GEMM2: cs (u8 16-bit) x sr (s8 q15), u8.s8 MMAs.
// ============================================================================
__global__ __launch_bounds__(512, 1) void gemm2_s8_kernel(float* __restrict__ of)
{
    extern __shared__ char smraw[];
    const uint32_t smb = smem_u32(smraw);
    const int tid  = threadIdx.x;
    const int wid  = tid >> 5;
    const int lane = tid & 31;
    const int nn0  = blockIdx.x * 128;
    const int m0   = blockIdx.y * 128;
    const int nz   = blockIdx.z;
    const int nk   = HW / 64;

    const int cr = tid >> 2;
    const int cc = (tid & 3) * 16;
    const char* pAh = (const char*)d_csqh;
    const char* pAl = (const char*)d_csql;
    const char* pBh = (const char*)d_srqh;
    const char* pBl = (const char*)d_srql;
    const size_t aoff = (size_t)(m0 + cr) * HW + (size_t)nz * HW * HW + cc;
    const size_t boff = (size_t)(nn0 + cr) * HW + (size_t)nz * GC * HW + cc;
    const uint32_t dd = (uint32_t)(cr * 80 + cc);

#define ISSUE2(t) do {                                               \
        uint32_t sb_ = smb + ((t) % NSTG) * STG8;                    \
        size_t kb_ = (size_t)(t) * 64;                               \
        CP16(sb_ + dd,             pAh + aoff + kb_);                \
        CP16(sb_ + TILE8 + dd,     pAl + aoff + kb_);                \
        CP16(sb_ + 2*TILE8 + dd,   pBh + boff + kb_);                \
        CP16(sb_ + 3*TILE8 + dd,   pBl + boff + kb_);                \
    } while (0)

    const int wm = wid >> 2;
    const int wn = wid & 3;
    const uint32_t aoffL = (uint32_t)((wm * 32 + (lane & 15)) * 80 + (lane >> 4) * 16);
    const uint32_t boffL = (uint32_t)((wn * 32 + ((lane >> 4) << 3) + (lane & 7)) * 80
                                      + ((lane >> 3) & 1) * 16);

    int acc1[2][4][4], acc2[2][4][4];
#pragma unroll
    for (int i = 0; i < 2; i++)
#pragma unroll
        for (int j = 0; j < 4; j++)
#pragma unroll
            for (int r = 0; r < 4; r++) { acc1[i][j][r] = 0; acc2[i][j][r] = 0; }

    ISSUE2(0); CP_COMMIT();
    ISSUE2(1); CP_COMMIT();

    for (int t = 0; t < nk; t++) {
        if (t + 2 < nk) ISSUE2(t + 2);
        CP_COMMIT();
        CP_WAIT2();
        __syncthreads();

        const uint32_t sb  = smb + (t % NSTG) * STG8;
        const uint32_t AhT = sb,             AlT = sb + TILE8;
        const uint32_t BhT = sb + 2 * TILE8, BlT = sb + 3 * TILE8;

#pragma unroll
        for (int ks = 0; ks < 2; ks++) {
            const uint32_t kb = ks * 32;
            uint32_t aH[8], aL[8], bH[8], bL[8];
            LDSM4(aH,     AhT + aoffL + kb);
            LDSM4(aH + 4, AhT + aoffL + 16 * 80 + kb);
            LDSM4(aL,     AlT + aoffL + kb);
            LDSM4(aL + 4, AlT + aoffL + 16 * 80 + kb);
            LDSM4(bH,     BhT + boffL + kb);
            LDSM4(bH + 4, BhT + boffL + 16 * 80 + kb);
            LDSM4(bL,     BlT + boffL + kb);
            LDSM4(bL + 4, BlT + boffL + 16 * 80 + kb);
#pragma unroll
            for (int i = 0; i < 2; i++)
#pragma unroll
                for (int j = 0; j < 4; j++) {
                    MMAU8(acc1[i][j], aH + 4 * i, bH[2 * j], bH[2 * j + 1]);
                    MMAU8(acc2[i][j], aH + 4 * i, bL[2 * j], bL[2 * j + 1]);
                    MMAU8(acc2[i][j], aL + 4 * i, bH[2 * j], bH[2 * j + 1]);
                }
        }
        __syncthreads();
    }

    float* smf = (float*)smraw;              // [128][129]
    const float* asb = d_cssc + (size_t)nz * HW + m0;
    const float* wsb = d_srsc + (size_t)nz * GC + nn0;
#pragma unroll
    for (int i = 0; i < 2; i++) {
        int m = wm * 32 + i * 16 + (lane >> 2);
        float sa0 = asb[m], sa1 = asb[m + 8];
#pragma unroll
        for (int j = 0; j < 4; j++) {
            int col = wn * 32 + j * 8 + 2 * (lane & 3);
            float w0 = wsb[col], w1 = wsb[col + 1];
            float v0 = fmaf(65536.f, (float)acc1[i][j][0], 256.f * (float)acc2[i][j][0]);
            float v1 = fmaf(65536.f, (float)acc1[i][j][1], 256.f * (float)acc2[i][j][1]);
            float v2 = fmaf(65536.f, (float)acc1[i][j][2], 256.f * (float)acc2[i][j][2]);
            float v3 = fmaf(65536.f, (float)acc1[i][j][3], 256.f * (float)acc2[i][j][3]);
            smf[m * 129 + col]           = sa0 * w0 * v0;
            smf[m * 129 + col + 1]       = sa0 * w1 * v1;
            smf[(m + 8) * 129 + col]     = sa1 * w0 * v2;
            smf[(m + 8) * 129 + col + 1] = sa1 * w1 * v3;
        }
    }
    __syncthreads();

    const int g = tid >> 2;
    const int q = tid & 3;
    const size_t orow = ((size_t)nz * GC + nn0 + g) * HW + m0 + q * 32;
#pragma unroll 1
    for (int pc = 0; pc < 8; pc++) {
        float4 v;
        v.x = smf[(q * 32 + pc * 4 + 0) * 129 + g];
        v.y = smf[(q * 32 + pc * 4 + 1) * 129 + g];
        v.z = smf[(q * 32 + pc * 4 + 2) * 129 + g];
        v.w = smf[(q * 32 + pc * 4 + 3) * 129 + g];
        *(float4*)(of + orow + pc * 4) = v;
    }
#undef ISSUE2
}

// ============================================================================
// launch
// ============================================================================
extern "C" void kernel_launch(void* const* d_in, const int* in_sizes, int n_in,
                              void* d_out, int out_size)
{
    const float* c    = (const float*)d_in[0];
    const float* s    = (const float*)d_in[1];
    const float* grid = (const float*)d_in[2];
    const float* wc1  = (const float*)d_in[3];
    const float* bc1  = (const float*)d_in[4];
    const float* wc2  = (const float*)d_in[5];
    const float* bc2  = (const float*)d_in[6];
    const float* ws1  = (const float*)d_in[7];
    const float* bs1  = (const float*)d_in[8];
    const float* ws2  = (const float*)d_in[9];
    const float* bs2  = (const float*)d_in[10];
    const float* wsr  = (const float*)d_in[11];
    const float* bsr  = (const float*)d_in[12];
    float* out = (float*)d_out;

    float *h1, *c1, *s1;
    cudaGetSymbolAddress((void**)&h1, d_h1);
    cudaGetSymbolAddress((void**)&c1, d_c1);
    cudaGetSymbolAddress((void**)&s1, d_s1);

    cudaFuncSetAttribute(gemm_wino_kernel,
                         cudaFuncAttributeMaxDynamicSharedMemorySize, SMEM_DYN);
    cudaFuncSetAttribute(gemm2_s8_kernel,
                         cudaFuncAttributeMaxDynamicSharedMemorySize, SMEM_DYN);
    cudaFuncSetAttribute(xmax2_kernel,
                         cudaFuncAttributeMaxDynamicSharedMemorySize, SMEM_XM);
    cudaFuncSetAttribute(xq2_kernel,
                         cudaFuncAttributeMaxDynamicSharedMemorySize, SMEM_XQ);

    // branches
    conv16_kernel<<<(2*16*128*128 + 255) / 256, 256>>>(c,  wc1, bc1, h1, 256, 128, 2, 1);
    conv16_kernel<<<(2*16*64*64   + 255) / 256, 256>>>(h1, wc2, bc2, c1, 128, 64,  2, 0);
    conv16_kernel<<<(2*16*128*128 + 255) / 256, 256>>>(s,  ws1, bs1, h1, 256, 128, 2, 1);
    conv16_kernel<<<(2*16*64*64   + 255) / 256, 256>>>(h1, ws2, bs2, s1, 128, 64,  2, 0);

    // fused affinity + softmax + u16 quantize
    {
        dim3 g(HW / 8, 2);
        affsoft_kernel<<<g, 256>>>(c1, s1);
    }

    // winograd operand prep
    wprep_kernel<<<GC, 256>>>(wsr);
    zeroxsc_kernel<<<(2 * NT * 16 + 255) / 256, 256>>>();
    xmax2_kernel<<<2 * 32 * 34, 256, SMEM_XM>>>(grid);
    xscconv_kernel<<<(2 * NT * 16 + 255) / 256, 256>>>();
    xq2_kernel<<<2 * 32 * 34, 256, SMEM_XQ>>>(grid);

    // GEMM1 + inverse transform / quantize
    {
        dim3 g(GC / 128, NT / 128, 32);
        gemm_wino_kernel<<<g, 512, SMEM_DYN>>>();
    }
    outtrans_q_kernel<<<2 * GC, 256>>>(bsr);

    // GEMM2 -> fp32 out
    {
        dim3 g(GC / 128, HW / 128, 2);
        gemm2_s8_kernel<<<g, 512, SMEM_DYN>>>(out);
    }
}

// round 13
// speedup vs baseline: 6.4400x; 1.0524x over previous
#include <cuda_runtime.h>
#include <math.h>
#include <stdint.h>

// ============================================================================
// AttModule (sm_100-safe PTX, legacy tensor cores) — all-int8 tensor path.
//   GEMM1 via Winograd F(2x2,3x3): int8 two-word split (3 IMMA per k32).
//   GEMM2: cs as u16 BALANCED split (Ah u8, Al s8), sr signed q15; the
//     dropped ll term's rms is halved vs unsigned lo-byte.
//   affsoft pass2 skips MUFU for logits < max-20 (q rounds to 0 anyway).
// ============================================================================

#define HW    4096
#define GC    2176
#define KC1   19584
#define NT    1024
#define QMAX  32512.0f      // 127*256 (signed q15)
#define CSQ   65280.0f      // 255*256 (balanced u16)

#define TILE8 10240         // 128 rows * 80B
#define STG8  (4*TILE8)
#define NSTG  3
#define SMEM_DYN (NSTG*STG8)     // 122880
#define SMEM_XM  (64*257*4)      // 65792 strip
#define SMEM_XQ  (64*257*4 + 512*4)

// ---------------- scratch ----------------------------------------------------
static __device__ float   d_h1[2*16*128*128];
static __device__ float   d_c1[2*16*HW];
static __device__ float   d_s1[2*16*HW];
// GEMM2 operands
static __device__ int8_t  d_csqh[(size_t)2*HW*HW];   // u8 bits
static __device__ int8_t  d_csql[(size_t)2*HW*HW];   // s8 balanced
static __device__ float   d_cssc[2*HW];
static __device__ int8_t  d_srqh[(size_t)2*GC*HW];
static __device__ int8_t  d_srql[(size_t)2*GC*HW];
static __device__ float   d_srsc[2*GC];
// winograd weights
static __device__ int8_t  d_wqh[(size_t)GC*16*GC];
static __device__ int8_t  d_wql[(size_t)GC*16*GC];
static __device__ float   d_wsc2[GC*16];
// winograd inputs
static __device__ int8_t  d_xqh[(size_t)32*NT*GC];
static __device__ int8_t  d_xql[(size_t)32*NT*GC];
static __device__ float   d_xsc[2*NT*16];
static __device__ int     d_xsci[2*NT*16];
// GEMM1 wino-domain outputs [n][g][uv][tile]
static __device__ float   d_mt[(size_t)2*GC*16*NT];

// ---------------- PTX helpers ------------------------------------------------
__device__ __forceinline__ uint32_t smem_u32(const void* p) {
    uint32_t a;
    asm("{ .reg .u64 t; cvta.to.shared.u64 t, %1; cvt.u32.u64 %0, t; }"
        : "=r"(a) : "l"(p));
    return a;
}

#define CP16(d, s) \
    asm volatile("cp.async.cg.shared.global [%0], [%1], 16;" :: "r"(d), "l"(s))
#define CP_COMMIT() asm volatile("cp.async.commit_group;" ::: "memory")
#define CP_WAIT2()  asm volatile("cp.async.wait_group 2;" ::: "memory")

#define LDSM4(r, addr) \
    asm volatile("ldmatrix.sync.aligned.m8n8.x4.shared.b16 {%0,%1,%2,%3}, [%4];" \
        : "=r"((r)[0]), "=r"((r)[1]), "=r"((r)[2]), "=r"((r)[3]) : "r"(addr))

#define MMAS8(d, a, b0, b1) \
    asm volatile("mma.sync.aligned.m16n8k32.row.col.s32.s8.s8.s32 " \
        "{%0,%1,%2,%3}, {%4,%5,%6,%7}, {%8,%9}, {%0,%1,%2,%3};" \
        : "+r"((d)[0]), "+r"((d)[1]), "+r"((d)[2]), "+r"((d)[3]) \
        : "r"((a)[0]), "r"((a)[1]), "r"((a)[2]), "r"((a)[3]), "r"(b0), "r"(b1))

#define MMAU8(d, a, b0, b1) \
    asm volatile("mma.sync.aligned.m16n8k32.row.col.s32.u8.s8.s32 " \
        "{%0,%1,%2,%3}, {%4,%5,%6,%7}, {%8,%9}, {%0,%1,%2,%3};" \
        : "+r"((d)[0]), "+r"((d)[1]), "+r"((d)[2]), "+r"((d)[3]) \
        : "r"((a)[0]), "r"((a)[1]), "r"((a)[2]), "r"((a)[3]), "r"(b0), "r"(b1))

__device__ __forceinline__ void q15(float v, float inv, int8_t& qh, int8_t& ql)
{
    int q = __float2int_rn(v * inv);
    q = max(-32512, min(32512, q));
    int ah = (q + 128) >> 8;
    qh = (int8_t)ah;
    ql = (int8_t)(q - (ah << 8));
}

__device__ __forceinline__ int refl(int y) { return y < 0 ? 1 : (y > 63 ? 62 : y); }

__device__ __forceinline__ void wino_w(const float* w9, float W[16])
{
    float V[4][3];
#pragma unroll
    for (int j = 0; j < 3; j++) {
        float g0 = w9[j], g1 = w9[3 + j], g2 = w9[6 + j];
        V[0][j] = g0;
        V[1][j] = 0.5f * (g0 + g1 + g2);
        V[2][j] = 0.5f * (g0 - g1 + g2);
        V[3][j] = g2;
    }
#pragma unroll
    for (int i = 0; i < 4; i++) {
        float v0 = V[i][0], v1 = V[i][1], v2 = V[i][2];
        W[i * 4 + 0] = v0;
        W[i * 4 + 1] = 0.5f * (v0 + v1 + v2);
        W[i * 4 + 2] = 0.5f * (v0 - v1 + v2);
        W[i * 4 + 3] = v2;
    }
}

__device__ __forceinline__ void wino_x(const float d[4][4], float X[16])
{
    float U[4][4];
#pragma unroll
    for (int j = 0; j < 4; j++) {
        U[0][j] = d[0][j] - d[2][j];
        U[1][j] = d[1][j] + d[2][j];
        U[2][j] = d[2][j] - d[1][j];
        U[3][j] = d[1][j] - d[3][j];
    }
#pragma unroll
    for (int i = 0; i < 4; i++) {
        X[i * 4 + 0] = U[i][0] - U[i][2];
        X[i * 4 + 1] = U[i][1] + U[i][2];
        X[i * 4 + 2] = U[i][2] - U[i][1];
        X[i * 4 + 3] = U[i][1] - U[i][3];
    }
}

// ============================================================================
// branch convs
// ============================================================================
__global__ void conv16_kernel(const float* __restrict__ in,
                              const float* __restrict__ w,
                              const float* __restrict__ b,
                              float* __restrict__ out,
                              int Hin, int Hout, int stride, int relu)
{
    int idx = blockIdx.x * blockDim.x + threadIdx.x;
    int total = 2 * 16 * Hout * Hout;
    if (idx >= total) return;
    int ox = idx % Hout;
    int oy = (idx / Hout) % Hout;
    int oc = (idx / (Hout * Hout)) % 16;
    int n  = idx / (Hout * Hout * 16);

    const float* wp = w + oc * 16 * 9;
    const float* ip = in + (size_t)n * 16 * Hin * Hin;

    int iy[3], ix[3];
#pragma unroll
    for (int k = 0; k < 3; k++) {
        int y = oy * stride - 1 + k;
        iy[k] = (y < 0) ? 1 : ((y >= Hin) ? Hin - 2 : y);
        int x = ox * stride - 1 + k;
        ix[k] = (x < 0) ? 1 : ((x >= Hin) ? Hin - 2 : x);
    }

    float acc = b[oc];
    for (int ic = 0; ic < 16; ic++) {
        const float* ipc = ip + (size_t)ic * Hin * Hin;
        const float* wpc = wp + ic * 9;
#pragma unroll
        for (int ky = 0; ky < 3; ky++) {
            const float* row = ipc + (size_t)iy[ky] * Hin;
#pragma unroll
            for (int kx = 0; kx < 3; kx++)
                acc += wpc[ky * 3 + kx] * __ldg(row + ix[kx]);
        }
    }
    out[idx] = relu ? fmaxf(acc, 0.f) : acc;
}

// ============================================================================
// fused affinity + softmax + balanced-u16 quantize. Block = (8 rows, n).
// pass1: logits + rowmax. pass2: logits + exp (skipped when < max-20) + quant.
// ============================================================================
__global__ __launch_bounds__(256) void affsoft_kernel(const float* __restrict__ c1,
                                                      const float* __restrict__ s1)
{
    const int n  = blockIdx.y;
    const int r0 = blockIdx.x * 8;
    const int t  = threadIdx.x;
    __shared__ float c1s[16][8];
    __shared__ float red[256];
    __shared__ float mrow[8];

    if (t < 128) {
        int c = t >> 3, r = t & 7;
        c1s[c][r] = c1[((size_t)n * 16 + c) * HW + r0 + r];
    }
    __syncthreads();
    const float* s1n = s1 + (size_t)n * 16 * HW;

    float m8[8];
#pragma unroll
    for (int r = 0; r < 8; r++) m8[r] = -INFINITY;

    for (int j = t; j < HW; j += 256) {
        float sv[16];
#pragma unroll
        for (int c = 0; c < 16; c++) sv[c] = s1n[(size_t)c * HW + j];
#pragma unroll
        for (int r = 0; r < 8; r++) {
            float l = 0.f;
#pragma unroll
            for (int c = 0; c < 16; c++) l += c1s[c][r] * sv[c];
            m8[r] = fmaxf(m8[r], l);
        }
    }
#pragma unroll 1
    for (int r = 0; r < 8; r++) {
        red[t] = m8[r]; __syncthreads();
        for (int s = 128; s > 0; s >>= 1) {
            if (t < s) red[t] = fmaxf(red[t], red[t + s]);
            __syncthreads();
        }
        if (t == 0) mrow[r] = red[0];
        __syncthreads();
    }

    float s8v[8];
#pragma unroll
    for (int r = 0; r < 8; r++) s8v[r] = 0.f;

    for (int j = t; j < HW; j += 256) {
        float sv[16];
#pragma unroll
        for (int c = 0; c < 16; c++) sv[c] = s1n[(size_t)c * HW + j];
#pragma unroll
        for (int r = 0; r < 8; r++) {
            float l = 0.f;
#pragma unroll
            for (int c = 0; c < 16; c++) l += c1s[c][r] * sv[c];
            float d = l - mrow[r];
            int8_t qh = 0, ql = 0;
            if (d >= -20.f) {                 // e*CSQ rounds to >= 1 only here;
                float e = __expf(d);          // skipped e < 2.1e-9 (sum err <1e-5)
                s8v[r] += e;
                int q = __float2int_rn(e * CSQ);
                q = max(0, min(65280, q));
                int ah = (q + 128) >> 8;      // 0..255
                qh = (int8_t)(uint8_t)ah;
                ql = (int8_t)(q - (ah << 8)); // -128..127
            }
            size_t o = ((size_t)n * HW + r0 + r) * HW + j;
            d_csqh[o] = qh;
            d_csql[o] = ql;
        }
    }
#pragma unroll 1
    for (int r = 0; r < 8; r++) {
        red[t] = s8v[r]; __syncthreads();
        for (int s = 128; s > 0; s >>= 1) {
            if (t < s) red[t] += red[t + s];
            __syncthreads();
        }
        if (t == 0) d_cssc[n * HW + r0 + r] = 1.f / (CSQ * red[0]);
        __syncthreads();
    }
}

// ============================================================================
// winograd weight prep (2-pass recompute, per-g block)
// ============================================================================
__global__ void wprep_kernel(const float* __restrict__ wsr)
{
    int g = blockIdx.x;
    int t = threadIdx.x;
    __shared__ float redm[16 * 256];
    __shared__ float scinv[16];

    float mx[16];
#pragma unroll
    for (int uv = 0; uv < 16; uv++) mx[uv] = 0.f;

    for (int c = t; c < GC; c += 256) {
        float w9[9], W[16];
        const float* wp = wsr + (size_t)g * KC1 + c * 9;
#pragma unroll
        for (int k = 0; k < 9; k++) w9[k] = wp[k];
        wino_w(w9, W);
#pragma unroll
        for (int uv = 0; uv < 16; uv++) mx[uv] = fmaxf(mx[uv], fabsf(W[uv]));
    }
#pragma unroll
    for (int uv = 0; uv < 16; uv++) redm[uv * 256 + t] = mx[uv];
    __syncthreads();
    for (int s = 128; s > 0; s >>= 1) {
        if (t < s)
#pragma unroll
            for (int uv = 0; uv < 16; uv++)
                redm[uv * 256 + t] = fmaxf(redm[uv * 256 + t], redm[uv * 256 + t + s]);
        __syncthreads();
    }
    if (t < 16) {
        float sc = redm[t * 256] / QMAX;
        d_wsc2[g * 16 + t] = sc;
        scinv[t] = (sc > 0.f) ? 1.f / sc : 0.f;
    }
    __syncthreads();

    for (int c = t; c < GC; c += 256) {
        float w9[9], W[16];
        const float* wp = wsr + (size_t)g * KC1 + c * 9;
#pragma unroll
        for (int k = 0; k < 9; k++) w9[k] = wp[k];
        wino_w(w9, W);
#pragma unroll
        for (int uv = 0; uv < 16; uv++) {
            int8_t qh, ql;
            q15(W[uv], scinv[uv], qh, ql);
            size_t o = ((size_t)g * 16 + uv) * GC + c;
            d_wqh[o] = qh;
            d_wql[o] = ql;
        }
    }
}

// ============================================================================
// winograd input prep, coalesced strip kernels
// ============================================================================
__global__ void zeroxsc_kernel()
{
    int i = blockIdx.x * blockDim.x + threadIdx.x;
    if (i < 2 * NT * 16) d_xsci[i] = 0;
}

__global__ __launch_bounds__(256) void xmax2_kernel(const float* __restrict__ grid)
{
    extern __shared__ float strip[];          // [64][257]
    int bid = blockIdx.x;
    int cg = bid % 34;
    int ty = (bid / 34) % 32;
    int n  = bid / (34 * 32);
    int c0 = cg * 64;
    int t  = threadIdx.x;

    int ry[4];
#pragma unroll
    for (int k = 0; k < 4; k++) ry[k] = refl(2 * ty - 1 + k);

    for (int idx = t; idx < 64 * 256; idx += 256) {
        int ch = idx >> 8;
        int rpx = idx & 255;
        int r = rpx >> 6, px = rpx & 63;
        strip[ch * 257 + rpx] =
            grid[(((size_t)n * GC + c0 + ch) << 12) + (ry[r] << 6) + px];
    }
    __syncthreads();

    const int tx = t & 31;
    const int w  = t >> 5;
    int rx[4];
#pragma unroll
    for (int k = 0; k < 4; k++) rx[k] = refl(2 * tx - 1 + k);

    float mx[16];
#pragma unroll
    for (int uv = 0; uv < 16; uv++) mx[uv] = 0.f;

#pragma unroll 1
    for (int cc = 0; cc < 8; cc++) {
        int ch = w * 8 + cc;
        float d[4][4], X[16];
#pragma unroll
        for (int r = 0; r < 4; r++)
#pragma unroll
            for (int k = 0; k < 4; k++)
                d[r][k] = strip[ch * 257 + r * 64 + rx[k]];
        wino_x(d, X);
#pragma unroll
        for (int uv = 0; uv < 16; uv++) mx[uv] = fmaxf(mx[uv], fabsf(X[uv]));
    }
    __syncthreads();
#pragma unroll
    for (int uv = 0; uv < 16; uv++) strip[(tx * 8 + w) * 16 + uv] = mx[uv];
    __syncthreads();
    if (t < 32) {
#pragma unroll
        for (int uv = 0; uv < 16; uv++) {
            float m = 0.f;
#pragma unroll
            for (int ww = 0; ww < 8; ww++)
                m = fmaxf(m, strip[(t * 8 + ww) * 16 + uv]);
            atomicMax(&d_xsci[(n * NT + ty * 32 + t) * 16 + uv], __float_as_int(m));
        }
    }
}

__global__ void xscconv_kernel()
{
    int i = blockIdx.x * blockDim.x + threadIdx.x;
    if (i < 2 * NT * 16) d_xsc[i] = __int_as_float(d_xsci[i]) / QMAX;
}

__global__ __launch_bounds__(256) void xq2_kernel(const float* __restrict__ grid)
{
    extern __shared__ float smdyn[];
    float* strip = smdyn;                     // [64][257]
    float* sci   = smdyn + 64 * 257;          // [32][16]
    int bid = blockIdx.x;
    int cg = bid % 34;
    int ty = (bid / 34) % 32;
    int n  = bid / (34 * 32);
    int c0 = cg * 64;
    int t  = threadIdx.x;

    int ry[4];
#pragma unroll
    for (int k = 0; k < 4; k++) ry[k] = refl(2 * ty - 1 + k);

    for (int idx = t; idx < 64 * 256; idx += 256) {
        int ch = idx >> 8;
        int rpx = idx & 255;
        int r = rpx >> 6, px = rpx & 63;
        strip[ch * 257 + rpx] =
            grid[(((size_t)n * GC + c0 + ch) << 12) + (ry[r] << 6) + px];
    }
    for (int i = t; i < 512; i += 256) {
        int tx = i >> 4, uv = i & 15;
        float mxv = __int_as_float(d_xsci[(n * NT + ty * 32 + tx) * 16 + uv]);
        sci[i] = (mxv > 0.f) ? QMAX / mxv : 0.f;
    }
    __syncthreads();

    const int w    = t >> 5;
    const int lane = t & 31;
#pragma unroll 1
    for (int q = 0; q < 4; q++) {
        int tx = w * 4 + q;
        int rx[4];
#pragma unroll
        for (int k = 0; k < 4; k++) rx[k] = refl(2 * tx - 1 + k);
#pragma unroll 1
        for (int h = 0; h < 2; h++) {
            int ch = lane + 32 * h;
            float d[4][4], X[16];
#pragma unroll
            for (int r = 0; r < 4; r++)
#pragma unroll
                for (int k = 0; k < 4; k++)
                    d[r][k] = strip[ch * 257 + r * 64 + rx[k]];
            wino_x(d, X);
#pragma unroll
            for (int uv = 0; uv < 16; uv++) {
                int8_t qh, ql;
                q15(X[uv], sci[tx * 16 + uv], qh, ql);
                size_t o = ((size_t)(uv * 2 + n) * NT + ty * 32 + tx) * GC + c0 + ch;
                d_xqh[o] = qh;
                d_xql[o] = ql;
            }
        }
    }
}

// ============================================================================
// winograd GEMM: per (uv,n): M[tile][g] = X_t . W_t
// ============================================================================
__global__ __launch_bounds__(512, 1) void gemm_wino_kernel()
{
    extern __shared__ char smraw[];
    const uint32_t smb = smem_u32(smraw);
    const int tid  = threadIdx.x;
    const int wid  = tid >> 5;
    const int lane = tid & 31;
    const int nn0  = blockIdx.x * 128;
    const int m0   = blockIdx.y * 128;
    const int z    = blockIdx.z;
    const int n    = z & 1, uv = z >> 1;
    const int nk   = GC / 64;

    const int cr = tid >> 2;
    const int cc = (tid & 3) * 16;
    const char* pAh = (const char*)d_xqh;
    const char* pAl = (const char*)d_xql;
    const char* pBh = (const char*)d_wqh;
    const char* pBl = (const char*)d_wql;
    const size_t aoff = ((size_t)z * NT + m0 + cr) * GC + cc;
    const size_t boff = ((size_t)(nn0 + cr) * 16 + uv) * GC + cc;
    const uint32_t dd = (uint32_t)(cr * 80 + cc);

#define ISSUE8(t) do {                                               \
        uint32_t sb_ = smb + ((t) % NSTG) * STG8;                    \
        size_t kb_ = (size_t)(t) * 64;                               \
        CP16(sb_ + dd,             pAh + aoff + kb_);                \
        CP16(sb_ + TILE8 + dd,     pAl + aoff + kb_);                \
        CP16(sb_ + 2*TILE8 + dd,   pBh + boff + kb_);                \
        CP16(sb_ + 3*TILE8 + dd,   pBl + boff + kb_);                \
    } while (0)

    const int wm = wid >> 2;
    const int wn = wid & 3;
    const uint32_t aoffL = (uint32_t)((wm * 32 + (lane & 15)) * 80 + (lane >> 4) * 16);
    const uint32_t boffL = (uint32_t)((wn * 32 + ((lane >> 4) << 3) + (lane & 7)) * 80
                                      + ((lane >> 3) & 1) * 16);

    int acc1[2][4][4], acc2[2][4][4];
#pragma unroll
    for (int i = 0; i < 2; i++)
#pragma unroll
        for (int j = 0; j < 4; j++)
#pragma unroll
            for (int r = 0; r < 4; r++) { acc1[i][j][r] = 0; acc2[i][j][r] = 0; }

    ISSUE8(0); CP_COMMIT();
    ISSUE8(1); CP_COMMIT();

    for (int t = 0; t < nk; t++) {
        if (t + 2 < nk) ISSUE8(t + 2);
        CP_COMMIT();
        CP_WAIT2();
        __syncthreads();

        const uint32_t sb  = smb + (t % NSTG) * STG8;
        const uint32_t AhT = sb,             AlT = sb + TILE8;
        const uint32_t BhT = sb + 2 * TILE8, BlT = sb + 3 * TILE8;

#pragma unroll
        for (int ks = 0; ks < 2; ks++) {
            const uint32_t kb = ks * 32;
            uint32_t aH[8], aL[8], bH[8], bL[8];
            LDSM4(aH,     AhT + aoffL + kb);
            LDSM4(aH + 4, AhT + aoffL + 16 * 80 + kb);
            LDSM4(aL,     AlT + aoffL + kb);
            LDSM4(aL + 4, AlT + aoffL + 16 * 80 + kb);
            LDSM4(bH,     BhT + boffL + kb);
            LDSM4(bH + 4, BhT + boffL + 16 * 80 + kb);
            LDSM4(bL,     BlT + boffL + kb);
            LDSM4(bL + 4, BlT + boffL + 16 * 80 + kb);
#pragma unroll
            for (int i = 0; i < 2; i++)
#pragma unroll
                for (int j = 0; j < 4; j++) {
                    MMAS8(acc1[i][j], aH + 4 * i, bH[2 * j], bH[2 * j + 1]);
                    MMAS8(acc2[i][j], aH + 4 * i, bL[2 * j], bL[2 * j + 1]);
                    MMAS8(acc2[i][j], aL + 4 * i, bH[2 * j], bH[2 * j + 1]);
                }
        }
        __syncthreads();
    }

    float* smf = (float*)smraw;              // [128][129]
    const float* asb = d_xsc + ((size_t)(n * NT + m0)) * 16 + uv;
    const float* wsb = d_wsc2 + (size_t)nn0 * 16 + uv;
#pragma unroll
    for (int i = 0; i < 2; i++) {
        int m = wm * 32 + i * 16 + (lane >> 2);
        float sa0 = asb[m * 16], sa1 = asb[(m + 8) * 16];
#pragma unroll
        for (int j = 0; j < 4; j++) {
            int col = wn * 32 + j * 8 + 2 * (lane & 3);
            float w0 = wsb[col * 16], w1 = wsb[(col + 1) * 16];
            float v0 = fmaf(65536.f, (float)acc1[i][j][0], 256.f * (float)acc2[i][j][0]);
            float v1 = fmaf(65536.f, (float)acc1[i][j][1], 256.f * (float)acc2[i][j][1]);
            float v2 = fmaf(65536.f, (float)acc1[i][j][2], 256.f * (float)acc2[i][j][2]);
            float v3 = fmaf(65536.f, (float)acc1[i][j][3], 256.f * (float)acc2[i][j][3]);
            smf[m * 129 + col]           = sa0 * w0 * v0;
            smf[m * 129 + col + 1]       = sa0 * w1 * v1;
            smf[(m + 8) * 129 + col]     = sa1 * w0 * v2;
            smf[(m + 8) * 129 + col + 1] = sa1 * w1 * v3;
        }
    }
    __syncthreads();

    const int g = tid >> 2;
    const int q = tid & 3;
    const size_t ob = (((size_t)n * GC + nn0 + g) * 16 + uv) * NT + m0 + q * 32;
#pragma unroll 1
    for (int pc = 0; pc < 8; pc++) {
        float4 v;
        v.x = smf[(q * 32 + pc * 4 + 0) * 129 + g];
        v.y = smf[(q * 32 + pc * 4 + 1) * 129 + g];
        v.z = smf[(q * 32 + pc * 4 + 2) * 129 + g];
        v.w = smf[(q * 32 + pc * 4 + 3) * 129 + g];
        *(float4*)(d_mt + ob + pc * 4) = v;
    }
#undef ISSUE8
}

// ============================================================================
// output transform + bias + rowmax + q15 quantize
// ============================================================================
__global__ void outtrans_q_kernel(const float* __restrict__ bias)
{
    int g = blockIdx.x % GC;
    int n = blockIdx.x / GC;
    int t = threadIdx.x;
    __shared__ float y[4096];
    __shared__ float red[256];

    const float* mb = d_mt + (((size_t)n * GC + g) * 16) * NT;
    float bv = bias[g];
    float mx = 0.f;

#pragma unroll 1
    for (int it = 0; it < 4; it++) {
        int tile = t + it * 256;
        float M[16];
#pragma unroll
        for (int uv = 0; uv < 16; uv++) M[uv] = mb[(size_t)uv * NT + tile];

        float T0[4], T1[4];
#pragma unroll
        for (int j = 0; j < 4; j++) {
            T0[j] = M[j] + M[4 + j] + M[8 + j];
            T1[j] = M[4 + j] - M[8 + j] - M[12 + j];
        }
        float y00 = T0[0] + T0[1] + T0[2] + bv;
        float y01 = T0[1] - T0[2] - T0[3] + bv;
        float y10 = T1[0] + T1[1] + T1[2] + bv;
        float y11 = T1[1] - T1[2] - T1[3] + bv;

        int ty = tile >> 5, tx = tile & 31;
        int p0 = (ty << 7) + (tx << 1);
        y[p0]      = y00;
        y[p0 + 1]  = y01;
        y[p0 + 64] = y10;
        y[p0 + 65] = y11;
        mx = fmaxf(mx, fmaxf(fmaxf(fabsf(y00), fabsf(y01)),
                             fmaxf(fabsf(y10), fabsf(y11))));
    }
    red[t] = mx; __syncthreads();
    for (int s = 128; s > 0; s >>= 1) {
        if (t < s) red[t] = fmaxf(red[t], red[t + s]);
        __syncthreads();
    }
    float sc = red[0] / QMAX;
    if (t == 0) d_srsc[n * GC + g] = sc;
    float inv = (sc > 0.f) ? 1.f / sc : 0.f;

    size_t base = ((size_t)n * GC + g) * HW;
#pragma unroll 1
    for (int i = t * 4; i < 4096; i += 1024) {
        char4 h4, l4;
        int8_t qh, ql;
        q15(y[i + 0], inv, qh, ql); h4.x = qh; l4.x = ql;
        q15(y[i + 1], inv, qh, ql); h4.y = qh; l4.y = ql;
        q15(y[i + 2], inv, qh, ql); h4.z = qh; l4.z = ql;
        q15(y[i + 3], inv, qh, ql); h4.w = qh; l4.w = ql;
        *(char4*)(d_srqh + base + i) = h4;
        *(char4*)(d_srql + base + i) = l4;
    }
}

// ============================================================================
// GEMM2: cs (balanced u16: Ah u8 / Al s8) x sr (s8 q15).
// ============================================================================
__global__ __launch_bounds__(512, 1) void gemm2_s8_kernel(float* __restrict__ of)
{
    extern __shared__ char smraw[];
    const uint32_t smb = smem_u32(smraw);
    const int tid  = threadIdx.x;
    const int wid  = tid >> 5;
    const int lane = tid & 31;
    const int nn0  = blockIdx.x * 128;
    const int m0   = blockIdx.y * 128;
    const int nz   = blockIdx.z;
    const int nk   = HW / 64;

    const int cr = tid >> 2;
    const int cc = (tid & 3) * 16;
    const char* pAh = (const char*)d_csqh;
    const char* pAl = (const char*)d_csql;
    const char* pBh = (const char*)d_srqh;
    const char* pBl = (const char*)d_srql;
    const size_t aoff = (size_t)(m0 + cr) * HW + (size_t)nz * HW * HW + cc;
    const size_t boff = (size_t)(nn0 + cr) * HW + (size_t)nz * GC * HW + cc;
    const uint32_t dd = (uint32_t)(cr * 80 + cc);

#define ISSUE2(t) do {                                               \
        uint32_t sb_ = smb + ((t) % NSTG) * STG8;                    \
        size_t kb_ = (size_t)(t) * 64;                               \
        CP16(sb_ + dd,             pAh + aoff + kb_);                \
        CP16(sb_ + TILE8 + dd,     pAl + aoff + kb_);                \
        CP16(sb_ + 2*TILE8 + dd,   pBh + boff + kb_);                \
        CP16(sb_ + 3*TILE8 + dd,   pBl + boff + kb_);                \
    } while (0)

    const int wm = wid >> 2;
    const int wn = wid & 3;
    const uint32_t aoffL = (uint32_t)((wm * 32 + (lane & 15)) * 80 + (lane >> 4) * 16);
    const uint32_t boffL = (uint32_t)((wn * 32 + ((lane >> 4) << 3) + (lane & 7)) * 80
                                      + ((lane >> 3) & 1) * 16);

    int acc1[2][4][4], acc2[2][4][4];
#pragma unroll
    for (int i = 0; i < 2; i++)
#pragma unroll
        for (int j = 0; j < 4; j++)
#pragma unroll
            for (int r = 0; r < 4; r++) { acc1[i][j][r] = 0; acc2[i][j][r] = 0; }

    ISSUE2(0); CP_COMMIT();
    ISSUE2(1); CP_COMMIT();

    for (int t = 0; t < nk; t++) {
        if (t + 2 < nk) ISSUE2(t + 2);
        CP_COMMIT();
        CP_WAIT2();
        __syncthreads();

        const uint32_t sb  = smb + (t % NSTG) * STG8;
        const uint32_t AhT = sb,             AlT = sb + TILE8;
        const uint32_t BhT = sb + 2 * TILE8, BlT = sb + 3 * TILE8;

#pragma unroll
        for (int ks = 0; ks < 2; ks++) {
            const uint32_t kb = ks * 32;
            uint32_t aH[8], aL[8], bH[8], bL[8];
            LDSM4(aH,     AhT + aoffL + kb);
            LDSM4(aH + 4, AhT + aoffL + 16 * 80 + kb);
            LDSM4(aL,     AlT + aoffL + kb);
            LDSM4(aL + 4, AlT + aoffL + 16 * 80 + kb);
            LDSM4(bH,     BhT + boffL + kb);
            LDSM4(bH + 4, BhT + boffL + 16 * 80 + kb);
            LDSM4(bL,     BlT + boffL + kb);
            LDSM4(bL + 4, BlT + boffL + 16 * 80 + kb);
#pragma unroll
            for (int i = 0; i < 2; i++)
#pragma unroll
                for (int j = 0; j < 4; j++) {
                    MMAU8(acc1[i][j], aH + 4 * i, bH[2 * j], bH[2 * j + 1]);
                    MMAU8(acc2[i][j], aH + 4 * i, bL[2 * j], bL[2 * j + 1]);
                    MMAS8(acc2[i][j], aL + 4 * i, bH[2 * j], bH[2 * j + 1]);
                }
        }
        __syncthreads();
    }

    float* smf = (float*)smraw;              // [128][129]
    const float* asb = d_cssc + (size_t)nz * HW + m0;
    const float* wsb = d_srsc + (size_t)nz * GC + nn0;
#pragma unroll
    for (int i = 0; i < 2; i++) {
        int m = wm * 32 + i * 16 + (lane >> 2);
        float sa0 = asb[m], sa1 = asb[m + 8];
#pragma unroll
        for (int j = 0; j < 4; j++) {
            int col = wn * 32 + j * 8 + 2 * (lane & 3);
            float w0 = wsb[col], w1 = wsb[col + 1];
            float v0 = fmaf(65536.f, (float)acc1[i][j][0], 256.f * (float)acc2[i][j][0]);
            float v1 = fmaf(65536.f, (float)acc1[i][j][1], 256.f * (float)acc2[i][j][1]);
            float v2 = fmaf(65536.f, (float)acc1[i][j][2], 256.f * (float)acc2[i][j][2]);
            float v3 = fmaf(65536.f, (float)acc1[i][j][3], 256.f * (float)acc2[i][j][3]);
            smf[m * 129 + col]           = sa0 * w0 * v0;
            smf[m * 129 + col + 1]       = sa0 * w1 * v1;
            smf[(m + 8) * 129 + col]     = sa1 * w0 * v2;
            smf[(m + 8) * 129 + col + 1] = sa1 * w1 * v3;
        }
    }
    __syncthreads();

    const int g = tid >> 2;
    const int q = tid & 3;
    const size_t orow = ((size_t)nz * GC + nn0 + g) * HW + m0 + q * 32;
#pragma unroll 1
    for (int pc = 0; pc < 8; pc++) {
        float4 v;
        v.x = smf[(q * 32 + pc * 4 + 0) * 129 + g];
        v.y = smf[(q * 32 + pc * 4 + 1) * 129 + g];
        v.z = smf[(q * 32 + pc * 4 + 2) * 129 + g];
        v.w = smf[(q * 32 + pc * 4 + 3) * 129 + g];
        *(float4*)(of + orow + pc * 4) = v;
    }
#undef ISSUE2
}

// ============================================================================
// launch
// ============================================================================
extern "C" void kernel_launch(void* const* d_in, const int* in_sizes, int n_in,
                              void* d_out, int out_size)
{
    const float* c    = (const float*)d_in[0];
    const float* s    = (const float*)d_in[1];
    const float* grid = (const float*)d_in[2];
    const float* wc1  = (const float*)d_in[3];
    const float* bc1  = (const float*)d_in[4];
    const float* wc2  = (const float*)d_in[5];
    const float* bc2  = (const float*)d_in[6];
    const float* ws1  = (const float*)d_in[7];
    const float* bs1  = (const float*)d_in[8];
    const float* ws2  = (const float*)d_in[9];
    const float* bs2  = (const float*)d_in[10];
    const float* wsr  = (const float*)d_in[11];
    const float* bsr  = (const float*)d_in[12];
    float* out = (float*)d_out;

    float *h1, *c1, *s1;
    cudaGetSymbolAddress((void**)&h1, d_h1);
    cudaGetSymbolAddress((void**)&c1, d_c1);
    cudaGetSymbolAddress((void**)&s1, d_s1);

    cudaFuncSetAttribute(gemm_wino_kernel,
                         cudaFuncAttributeMaxDynamicSharedMemorySize, SMEM_DYN);
    cudaFuncSetAttribute(gemm2_s8_kernel,
                         cudaFuncAttributeMaxDynamicSharedMemorySize, SMEM_DYN);
    cudaFuncSetAttribute(xmax2_kernel,
                         cudaFuncAttributeMaxDynamicSharedMemorySize, SMEM_XM);
    cudaFuncSetAttribute(xq2_kernel,
                         cudaFuncAttributeMaxDynamicSharedMemorySize, SMEM_XQ);

    // branches
    conv16_kernel<<<(2*16*128*128 + 255) / 256, 256>>>(c,  wc1, bc1, h1, 256, 128, 2, 1);
    conv16_kernel<<<(2*16*64*64   + 255) / 256, 256>>>(h1, wc2, bc2, c1, 128, 64,  2, 0);
    conv16_kernel<<<(2*16*128*128 + 255) / 256, 256>>>(s,  ws1, bs1, h1, 256, 128, 2, 1);
    conv16_kernel<<<(2*16*64*64   + 255) / 256, 256>>>(h1, ws2, bs2, s1, 128, 64,  2, 0);

    // fused affinity + softmax + balanced-u16 quantize
    {
        dim3 g(HW / 8, 2);
        affsoft_kernel<<<g, 256>>>(c1, s1);
    }

    // winograd operand prep
    wprep_kernel<<<GC, 256>>>(wsr);
    zeroxsc_kernel<<<(2 * NT * 16 + 255) / 256, 256>>>();
    xmax2_kernel<<<2 * 32 * 34, 256, SMEM_XM>>>(grid);
    xscconv_kernel<<<(2 * NT * 16 + 255) / 256, 256>>>();
    xq2_kernel<<<2 * 32 * 34, 256, SMEM_XQ>>>(grid);

    // GEMM1 + inverse transform / quantize
    {
        dim3 g(GC / 128, NT / 128, 32);
        gemm_wino_kernel<<<g, 512, SMEM_DYN>>>();
    }
    outtrans_q_kernel<<<2 * GC, 256>>>(bsr);

    // GEMM2 -> fp32 out
    {
        dim3 g(GC / 128, HW / 128, 2);
        gemm2_s8_kernel<<<g, 512, SMEM_DYN>>>(out);
    }
}

// round 14
// speedup vs baseline: 7.1930x; 1.1169x over previous
#include <cuda_runtime.h>
#include <math.h>
#include <stdint.h>

// ============================================================================
// AttModule (sm_100-safe PTX, legacy tensor cores) — all-int8 tensor path.
//   GEMM1 via Winograd F(2x2,3x3): int8 two-word split (3 IMMA per k32).
//   GEMM2: cs balanced u16 (Ah u8 / Al s8) x sr q15 (3 IMMA per k32).
//   R14: 4-stage single-barrier cp.async pipeline in both GEMMs; merged
//   branch convs. No numerical changes vs R13.
// ============================================================================

#define HW    4096
#define GC    2176
#define KC1   19584
#define NT    1024
#define QMAX  32512.0f      // 127*256 (signed q15)
#define CSQ   65280.0f      // 255*256 (balanced u16)

#define TILE8 10240         // 128 rows * 80B
#define STG8  (4*TILE8)     // 40960 per stage (Ah,Al,Bh,Bl)
#define NSTG  4
#define SMEM_DYN (NSTG*STG8)     // 163840
#define SMEM_XM  (64*257*4)      // 65792 strip
#define SMEM_XQ  (64*257*4 + 512*4)

// ---------------- scratch ----------------------------------------------------
static __device__ float   d_h1[2*16*128*128];
static __device__ float   d_c1[2*16*HW];
static __device__ float   d_s1[2*16*HW];
// GEMM2 operands
static __device__ int8_t  d_csqh[(size_t)2*HW*HW];   // u8 bits
static __device__ int8_t  d_csql[(size_t)2*HW*HW];   // s8 balanced
static __device__ float   d_cssc[2*HW];
static __device__ int8_t  d_srqh[(size_t)2*GC*HW];
static __device__ int8_t  d_srql[(size_t)2*GC*HW];
static __device__ float   d_srsc[2*GC];
// winograd weights
static __device__ int8_t  d_wqh[(size_t)GC*16*GC];
static __device__ int8_t  d_wql[(size_t)GC*16*GC];
static __device__ float   d_wsc2[GC*16];
// winograd inputs
static __device__ int8_t  d_xqh[(size_t)32*NT*GC];
static __device__ int8_t  d_xql[(size_t)32*NT*GC];
static __device__ float   d_xsc[2*NT*16];
static __device__ int     d_xsci[2*NT*16];
// GEMM1 wino-domain outputs [n][g][uv][tile]
static __device__ float   d_mt[(size_t)2*GC*16*NT];

// ---------------- PTX helpers ------------------------------------------------
__device__ __forceinline__ uint32_t smem_u32(const void* p) {
    uint32_t a;
    asm("{ .reg .u64 t; cvta.to.shared.u64 t, %1; cvt.u32.u64 %0, t; }"
        : "=r"(a) : "l"(p));
    return a;
}

#define CP16(d, s) \
    asm volatile("cp.async.cg.shared.global [%0], [%1], 16;" :: "r"(d), "l"(s))
#define CP_COMMIT() asm volatile("cp.async.commit_group;" ::: "memory")
#define CP_WAIT2()  asm volatile("cp.async.wait_group 2;" ::: "memory")

#define LDSM4(r, addr) \
    asm volatile("ldmatrix.sync.aligned.m8n8.x4.shared.b16 {%0,%1,%2,%3}, [%4];" \
        : "=r"((r)[0]), "=r"((r)[1]), "=r"((r)[2]), "=r"((r)[3]) : "r"(addr))

#define MMAS8(d, a, b0, b1) \
    asm volatile("mma.sync.aligned.m16n8k32.row.col.s32.s8.s8.s32 " \
        "{%0,%1,%2,%3}, {%4,%5,%6,%7}, {%8,%9}, {%0,%1,%2,%3};" \
        : "+r"((d)[0]), "+r"((d)[1]), "+r"((d)[2]), "+r"((d)[3]) \
        : "r"((a)[0]), "r"((a)[1]), "r"((a)[2]), "r"((a)[3]), "r"(b0), "r"(b1))

#define MMAU8(d, a, b0, b1) \
    asm volatile("mma.sync.aligned.m16n8k32.row.col.s32.u8.s8.s32 " \
        "{%0,%1,%2,%3}, {%4,%5,%6,%7}, {%8,%9}, {%0,%1,%2,%3};" \
        : "+r"((d)[0]), "+r"((d)[1]), "+r"((d)[2]), "+r"((d)[3]) \
        : "r"((a)[0]), "r"((a)[1]), "r"((a)[2]), "r"((a)[3]), "r"(b0), "r"(b1))

__device__ __forceinline__ void q15(float v, float inv, int8_t& qh, int8_t& ql)
{
    int q = __float2int_rn(v * inv);
    q = max(-32512, min(32512, q));
    int ah = (q + 128) >> 8;
    qh = (int8_t)ah;
    ql = (int8_t)(q - (ah << 8));
}

__device__ __forceinline__ int refl(int y) { return y < 0 ? 1 : (y > 63 ? 62 : y); }

__device__ __forceinline__ void wino_w(const float* w9, float W[16])
{
    float V[4][3];
#pragma unroll
    for (int j = 0; j < 3; j++) {
        float g0 = w9[j], g1 = w9[3 + j], g2 = w9[6 + j];
        V[0][j] = g0;
        V[1][j] = 0.5f * (g0 + g1 + g2);
        V[2][j] = 0.5f * (g0 - g1 + g2);
        V[3][j] = g2;
    }
#pragma unroll
    for (int i = 0; i < 4; i++) {
        float v0 = V[i][0], v1 = V[i][1], v2 = V[i][2];
        W[i * 4 + 0] = v0;
        W[i * 4 + 1] = 0.5f * (v0 + v1 + v2);
        W[i * 4 + 2] = 0.5f * (v0 - v1 + v2);
        W[i * 4 + 3] = v2;
    }
}

__device__ __forceinline__ void wino_x(const float d[4][4], float X[16])
{
    float U[4][4];
#pragma unroll
    for (int j = 0; j < 4; j++) {
        U[0][j] = d[0][j] - d[2][j];
        U[1][j] = d[1][j] + d[2][j];
        U[2][j] = d[2][j] - d[1][j];
        U[3][j] = d[1][j] - d[3][j];
    }
#pragma unroll
    for (int i = 0; i < 4; i++) {
        X[i * 4 + 0] = U[i][0] - U[i][2];
        X[i * 4 + 1] = U[i][1] + U[i][2];
        X[i * 4 + 2] = U[i][2] - U[i][1];
        X[i * 4 + 3] = U[i][1] - U[i][3];
    }
}

// ============================================================================
// branch convs: both branches in one launch (blockIdx.y selects branch)
// ============================================================================
__global__ void conv16_dual_kernel(const float* __restrict__ in0,
                                   const float* __restrict__ w0,
                                   const float* __restrict__ b0,
                                   float* __restrict__ out0,
                                   const float* __restrict__ in1,
                                   const float* __restrict__ w1,
                                   const float* __restrict__ b1,
                                   float* __restrict__ out1,
                                   int Hin, int Hout, int stride, int relu)
{
    const int br = blockIdx.y;
    const float* in  = br ? in1  : in0;
    const float* w   = br ? w1   : w0;
    const float* b   = br ? b1   : b0;
    float*       out = br ? out1 : out0;

    int idx = blockIdx.x * blockDim.x + threadIdx.x;
    int total = 2 * 16 * Hout * Hout;
    if (idx >= total) return;
    int ox = idx % Hout;
    int oy = (idx / Hout) % Hout;
    int oc = (idx / (Hout * Hout)) % 16;
    int n  = idx / (Hout * Hout * 16);

    const float* wp = w + oc * 16 * 9;
    const float* ip = in + (size_t)n * 16 * Hin * Hin;

    int iy[3], ix[3];
#pragma unroll
    for (int k = 0; k < 3; k++) {
        int y = oy * stride - 1 + k;
        iy[k] = (y < 0) ? 1 : ((y >= Hin) ? Hin - 2 : y);
        int x = ox * stride - 1 + k;
        ix[k] = (x < 0) ? 1 : ((x >= Hin) ? Hin - 2 : x);
    }

    float acc = b[oc];
    for (int ic = 0; ic < 16; ic++) {
        const float* ipc = ip + (size_t)ic * Hin * Hin;
        const float* wpc = wp + ic * 9;
#pragma unroll
        for (int ky = 0; ky < 3; ky++) {
            const float* row = ipc + (size_t)iy[ky] * Hin;
#pragma unroll
            for (int kx = 0; kx < 3; kx++)
                acc += wpc[ky * 3 + kx] * __ldg(row + ix[kx]);
        }
    }
    out[idx] = relu ? fmaxf(acc, 0.f) : acc;
}

// ============================================================================
// fused affinity + softmax + balanced-u16 quantize (unchanged from R13)
// ============================================================================
__global__ __launch_bounds__(256) void affsoft_kernel(const float* __restrict__ c1,
                                                      const float* __restrict__ s1)
{
    const int n  = blockIdx.y;
    const int r0 = blockIdx.x * 8;
    const int t  = threadIdx.x;
    __shared__ float c1s[16][8];
    __shared__ float red[256];
    __shared__ float mrow[8];

    if (t < 128) {
        int c = t >> 3, r = t & 7;
        c1s[c][r] = c1[((size_t)n * 16 + c) * HW + r0 + r];
    }
    __syncthreads();
    const float* s1n = s1 + (size_t)n * 16 * HW;

    float m8[8];
#pragma unroll
    for (int r = 0; r < 8; r++) m8[r] = -INFINITY;

    for (int j = t; j < HW; j += 256) {
        float sv[16];
#pragma unroll
        for (int c = 0; c < 16; c++) sv[c] = s1n[(size_t)c * HW + j];
#pragma unroll
        for (int r = 0; r < 8; r++) {
            float l = 0.f;
#pragma unroll
            for (int c = 0; c < 16; c++) l += c1s[c][r] * sv[c];
            m8[r] = fmaxf(m8[r], l);
        }
    }
#pragma unroll 1
    for (int r = 0; r < 8; r++) {
        red[t] = m8[r]; __syncthreads();
        for (int s = 128; s > 0; s >>= 1) {
            if (t < s) red[t] = fmaxf(red[t], red[t + s]);
            __syncthreads();
        }
        if (t == 0) mrow[r] = red[0];
        __syncthreads();
    }

    float s8v[8];
#pragma unroll
    for (int r = 0; r < 8; r++) s8v[r] = 0.f;

    for (int j = t; j < HW; j += 256) {
        float sv[16];
#pragma unroll
        for (int c = 0; c < 16; c++) sv[c] = s1n[(size_t)c * HW + j];
#pragma unroll
        for (int r = 0; r < 8; r++) {
            float l = 0.f;
#pragma unroll
            for (int c = 0; c < 16; c++) l += c1s[c][r] * sv[c];
            float d = l - mrow[r];
            int8_t qh = 0, ql = 0;
            if (d >= -20.f) {
                float e = __expf(d);
                s8v[r] += e;
                int q = __float2int_rn(e * CSQ);
                q = max(0, min(65280, q));
                int ah = (q + 128) >> 8;
                qh = (int8_t)(uint8_t)ah;
                ql = (int8_t)(q - (ah << 8));
            }
            size_t o = ((size_t)n * HW + r0 + r) * HW + j;
            d_csqh[o] = qh;
            d_csql[o] = ql;
        }
    }
#pragma unroll 1
    for (int r = 0; r < 8; r++) {
        red[t] = s8v[r]; __syncthreads();
        for (int s = 128; s > 0; s >>= 1) {
            if (t < s) red[t] += red[t + s];
            __syncthreads();
        }
        if (t == 0) d_cssc[n * HW + r0 + r] = 1.f / (CSQ * red[0]);
        __syncthreads();
    }
}

// ============================================================================
// winograd weight prep (unchanged)
// ============================================================================
__global__ void wprep_kernel(const float* __restrict__ wsr)
{
    int g = blockIdx.x;
    int t = threadIdx.x;
    __shared__ float redm[16 * 256];
    __shared__ float scinv[16];

    float mx[16];
#pragma unroll
    for (int uv = 0; uv < 16; uv++) mx[uv] = 0.f;

    for (int c = t; c < GC; c += 256) {
        float w9[9], W[16];
        const float* wp = wsr + (size_t)g * KC1 + c * 9;
#pragma unroll
        for (int k = 0; k < 9; k++) w9[k] = wp[k];
        wino_w(w9, W);
#pragma unroll
        for (int uv = 0; uv < 16; uv++) mx[uv] = fmaxf(mx[uv], fabsf(W[uv]));
    }
#pragma unroll
    for (int uv = 0; uv < 16; uv++) redm[uv * 256 + t] = mx[uv];
    __syncthreads();
    for (int s = 128; s > 0; s >>= 1) {
        if (t < s)
#pragma unroll
            for (int uv = 0; uv < 16; uv++)
                redm[uv * 256 + t] = fmaxf(redm[uv * 256 + t], redm[uv * 256 + t + s]);
        __syncthreads();
    }
    if (t < 16) {
        float sc = redm[t * 256] / QMAX;
        d_wsc2[g * 16 + t] = sc;
        scinv[t] = (sc > 0.f) ? 1.f / sc : 0.f;
    }
    __syncthreads();

    for (int c = t; c < GC; c += 256) {
        float w9[9], W[16];
        const float* wp = wsr + (size_t)g * KC1 + c * 9;
#pragma unroll
        for (int k = 0; k < 9; k++) w9[k] = wp[k];
        wino_w(w9, W);
#pragma unroll
        for (int uv = 0; uv < 16; uv++) {
            int8_t qh, ql;
            q15(W[uv], scinv[uv], qh, ql);
            size_t o = ((size_t)g * 16 + uv) * GC + c;
            d_wqh[o] = qh;
            d_wql[o] = ql;
        }
    }
}

// ============================================================================
// winograd input prep (unchanged strip kernels)
// ============================================================================
__global__ void zeroxsc_kernel()
{
    int i = blockIdx.x * blockDim.x + threadIdx.x;
    if (i < 2 * NT * 16) d_xsci[i] = 0;
}

__global__ __launch_bounds__(256) void xmax2_kernel(const float* __restrict__ grid)
{
    extern __shared__ float strip[];          // [64][257]
    int bid = blockIdx.x;
    int cg = bid % 34;
    int ty = (bid / 34) % 32;
    int n  = bid / (34 * 32);
    int c0 = cg * 64;
    int t  = threadIdx.x;

    int ry[4];
#pragma unroll
    for (int k = 0; k < 4; k++) ry[k] = refl(2 * ty - 1 + k);

    for (int idx = t; idx < 64 * 256; idx += 256) {
        int ch = idx >> 8;
        int rpx = idx & 255;
        int r = rpx >> 6, px = rpx & 63;
        strip[ch * 257 + rpx] =
            grid[(((size_t)n * GC + c0 + ch) << 12) + (ry[r] << 6) + px];
    }
    __syncthreads();

    const int tx = t & 31;
    const int w  = t >> 5;
    int rx[4];
#pragma unroll
    for (int k = 0; k < 4; k++) rx[k] = refl(2 * tx - 1 + k);

    float mx[16];
#pragma unroll
    for (int uv = 0; uv < 16; uv++) mx[uv] = 0.f;

#pragma unroll 1
    for (int cc = 0; cc < 8; cc++) {
        int ch = w * 8 + cc;
        float d[4][4], X[16];
#pragma unroll
        for (int r = 0; r < 4; r++)
#pragma unroll
            for (int k = 0; k < 4; k++)
                d[r][k] = strip[ch * 257 + r * 64 + rx[k]];
        wino_x(d, X);
#pragma unroll
        for (int uv = 0; uv < 16; uv++) mx[uv] = fmaxf(mx[uv], fabsf(X[uv]));
    }
    __syncthreads();
#pragma unroll
    for (int uv = 0; uv < 16; uv++) strip[(tx * 8 + w) * 16 + uv] = mx[uv];
    __syncthreads();
    if (t < 32) {
#pragma unroll
        for (int uv = 0; uv < 16; uv++) {
            float m = 0.f;
#pragma unroll
            for (int ww = 0; ww < 8; ww++)
                m = fmaxf(m, strip[(t * 8 + ww) * 16 + uv]);
            atomicMax(&d_xsci[(n * NT + ty * 32 + t) * 16 + uv], __float_as_int(m));
        }
    }
}

__global__ void xscconv_kernel()
{
    int i = blockIdx.x * blockDim.x + threadIdx.x;
    if (i < 2 * NT * 16) d_xsc[i] = __int_as_float(d_xsci[i]) / QMAX;
}

__global__ __launch_bounds__(256) void xq2_kernel(const float* __restrict__ grid)
{
    extern __shared__ float smdyn[];
    float* strip = smdyn;                     // [64][257]
    float* sci   = smdyn + 64 * 257;          // [32][16]
    int bid = blockIdx.x;
    int cg = bid % 34;
    int ty = (bid / 34) % 32;
    int n  = bid / (34 * 32);
    int c0 = cg * 64;
    int t  = threadIdx.x;

    int ry[4];
#pragma unroll
    for (int k = 0; k < 4; k++) ry[k] = refl(2 * ty - 1 + k);

    for (int idx = t; idx < 64 * 256; idx += 256) {
        int ch = idx >> 8;
        int rpx = idx & 255;
        int r = rpx >> 6, px = rpx & 63;
        strip[ch * 257 + rpx] =
            grid[(((size_t)n * GC + c0 + ch) << 12) + (ry[r] << 6) + px];
    }
    for (int i = t; i < 512; i += 256) {
        int tx = i >> 4, uv = i & 15;
        float mxv = __int_as_float(d_xsci[(n * NT + ty * 32 + tx) * 16 + uv]);
        sci[i] = (mxv > 0.f) ? QMAX / mxv : 0.f;
    }
    __syncthreads();

    const int w    = t >> 5;
    const int lane = t & 31;
#pragma unroll 1
    for (int q = 0; q < 4; q++) {
        int tx = w * 4 + q;
        int rx[4];
#pragma unroll
        for (int k = 0; k < 4; k++) rx[k] = refl(2 * tx - 1 + k);
#pragma unroll 1
        for (int h = 0; h < 2; h++) {
            int ch = lane + 32 * h;
            float d[4][4], X[16];
#pragma unroll
            for (int r = 0; r < 4; r++)
#pragma unroll
                for (int k = 0; k < 4; k++)
                    d[r][k] = strip[ch * 257 + r * 64 + rx[k]];
            wino_x(d, X);
#pragma unroll
            for (int uv = 0; uv < 16; uv++) {
                int8_t qh, ql;
                q15(X[uv], sci[tx * 16 + uv], qh, ql);
                size_t o = ((size_t)(uv * 2 + n) * NT + ty * 32 + tx) * GC + c0 + ch;
                d_xqh[o] = qh;
                d_xql[o] = ql;
            }
        }
    }
}

// ============================================================================
// winograd GEMM: 4-stage, single barrier per k-iter.
//   loop: WAIT2; sync; ISSUE(t+3); COMMIT; compute(t)
//   write target of ISSUE(t+3) = stage (t-1)%4, freed by sync_t.
// ============================================================================
__global__ __launch_bounds__(512, 1) void gemm_wino_kernel()
{
    extern __shared__ char smraw[];
    const uint32_t smb = smem_u32(smraw);
    const int tid  = threadIdx.x;
    const int wid  = tid >> 5;
    const int lane = tid & 31;
    const int nn0  = blockIdx.x * 128;
    const int m0   = blockIdx.y * 128;
    const int z    = blockIdx.z;
    const int n    = z & 1, uv = z >> 1;
    const int nk   = GC / 64;

    const int cr = tid >> 2;
    const int cc = (tid & 3) * 16;
    const char* pAh = (const char*)d_xqh;
    const char* pAl = (const char*)d_xql;
    const char* pBh = (const char*)d_wqh;
    const char* pBl = (const char*)d_wql;
    const size_t aoff = ((size_t)z * NT + m0 + cr) * GC + cc;
    const size_t boff = ((size_t)(nn0 + cr) * 16 + uv) * GC + cc;
    const uint32_t dd = (uint32_t)(cr * 80 + cc);

#define ISSUE8(t) do {                                               \
        uint32_t sb_ = smb + ((t) % NSTG) * STG8;                    \
        size_t kb_ = (size_t)(t) * 64;                               \
        CP16(sb_ + dd,             pAh + aoff + kb_);                \
        CP16(sb_ + TILE8 + dd,     pAl + aoff + kb_);                \
        CP16(sb_ + 2*TILE8 + dd,   pBh + boff + kb_);                \
        CP16(sb_ + 3*TILE8 + dd,   pBl + boff + kb_);                \
    } while (0)

    const int wm = wid >> 2;
    const int wn = wid & 3;
    const uint32_t aoffL = (uint32_t)((wm * 32 + (lane & 15)) * 80 + (lane >> 4) * 16);
    const uint32_t boffL = (uint32_t)((wn * 32 + ((lane >> 4) << 3) + (lane & 7)) * 80
                                      + ((lane >> 3) & 1) * 16);

    int acc1[2][4][4], acc2[2][4][4];
#pragma unroll
    for (int i = 0; i < 2; i++)
#pragma unroll
        for (int j = 0; j < 4; j++)
#pragma unroll
            for (int r = 0; r < 4; r++) { acc1[i][j][r] = 0; acc2[i][j][r] = 0; }

    ISSUE8(0); CP_COMMIT();
    ISSUE8(1); CP_COMMIT();
    ISSUE8(2); CP_COMMIT();

    for (int t = 0; t < nk; t++) {
        CP_WAIT2();
        __syncthreads();
        if (t + 3 < nk) ISSUE8(t + 3);
        CP_COMMIT();

        const uint32_t sb  = smb + (t % NSTG) * STG8;
        const uint32_t AhT = sb,             AlT = sb + TILE8;
        const uint32_t BhT = sb + 2 * TILE8, BlT = sb + 3 * TILE8;

#pragma unroll
        for (int ks = 0; ks < 2; ks++) {
            const uint32_t kb = ks * 32;
            uint32_t aH[8], aL[8], bH[8], bL[8];
            LDSM4(aH,     AhT + aoffL + kb);
            LDSM4(aH + 4, AhT + aoffL + 16 * 80 + kb);
            LDSM4(aL,     AlT + aoffL + kb);
            LDSM4(aL + 4, AlT + aoffL + 16 * 80 + kb);
            LDSM4(bH,     BhT + boffL + kb);
            LDSM4(bH + 4, BhT + boffL + 16 * 80 + kb);
            LDSM4(bL,     BlT + boffL + kb);
            LDSM4(bL + 4, BlT + boffL + 16 * 80 + kb);
#pragma unroll
            for (int i = 0; i < 2; i++)
#pragma unroll
                for (int j = 0; j < 4; j++) {
                    MMAS8(acc1[i][j], aH + 4 * i, bH[2 * j], bH[2 * j + 1]);
                    MMAS8(acc2[i][j], aH + 4 * i, bL[2 * j], bL[2 * j + 1]);
                    MMAS8(acc2[i][j], aL + 4 * i, bH[2 * j], bH[2 * j + 1]);
                }
        }
    }
    __syncthreads();                          // protect stages before smf reuse

    float* smf = (float*)smraw;              // [128][129]
    const float* asb = d_xsc + ((size_t)(n * NT + m0)) * 16 + uv;
    const float* wsb = d_wsc2 + (size_t)nn0 * 16 + uv;
#pragma unroll
    for (int i = 0; i < 2; i++) {
        int m = wm * 32 + i * 16 + (lane >> 2);
        float sa0 = asb[m * 16], sa1 = asb[(m + 8) * 16];
#pragma unroll
        for (int j = 0; j < 4; j++) {
            int col = wn * 32 + j * 8 + 2 * (lane & 3);
            float w0 = wsb[col * 16], w1 = wsb[(col + 1) * 16];
            float v0 = fmaf(65536.f, (float)acc1[i][j][0], 256.f * (float)acc2[i][j][0]);
            float v1 = fmaf(65536.f, (float)acc1[i][j][1], 256.f * (float)acc2[i][j][1]);
            float v2 = fmaf(65536.f, (float)acc1[i][j][2], 256.f * (float)acc2[i][j][2]);
            float v3 = fmaf(65536.f, (float)acc1[i][j][3], 256.f * (float)acc2[i][j][3]);
            smf[m * 129 + col]           = sa0 * w0 * v0;
            smf[m * 129 + col + 1]       = sa0 * w1 * v1;
            smf[(m + 8) * 129 + col]     = sa1 * w0 * v2;
            smf[(m + 8) * 129 + col + 1] = sa1 * w1 * v3;
        }
    }
    __syncthreads();

    const int g = tid >> 2;
    const int q = tid & 3;
    const size_t ob = (((size_t)n * GC + nn0 + g) * 16 + uv) * NT + m0 + q * 32;
#pragma unroll 1
    for (int pc = 0; pc < 8; pc++) {
        float4 v;
        v.x = smf[(q * 32 + pc * 4 + 0) * 129 + g];
        v.y = smf[(q * 32 + pc * 4 + 1) * 129 + g];
        v.z = smf[(q * 32 + pc * 4 + 2) * 129 + g];
        v.w = smf[(q * 32 + pc * 4 + 3) * 129 + g];
        *(float4*)(d_mt + ob + pc * 4) = v;
    }
#undef ISSUE8
}

// ============================================================================
// output transform + bias + rowmax + q15 quantize (unchanged)
// ============================================================================
__global__ void outtrans_q_kernel(const float* __restrict__ bias)
{
    int g = blockIdx.x % GC;
    int n = blockIdx.x / GC;
    int t = threadIdx.x;
    __shared__ float y[4096];
    __shared__ float red[256];

    const float* mb = d_mt + (((size_t)n * GC + g) * 16) * NT;
    float bv = bias[g];
    float mx = 0.f;

#pragma unroll 1
    for (int it = 0; it < 4; it++) {
        int tile = t + it * 256;
        float M[16];
#pragma unroll
        for (int uv = 0; uv < 16; uv++) M[uv] = mb[(size_t)uv * NT + tile];

        float T0[4], T1[4];
#pragma unroll
        for (int j = 0; j < 4; j++) {
            T0[j] = M[j] + M[4 + j] + M[8 + j];
            T1[j] = M[4 + j] - M[8 + j] - M[12 + j];
        }
        float y00 = T0[0] + T0[1] + T0[2] + bv;
        float y01 = T0[1] - T0[2] - T0[3] + bv;
        float y10 = T1[0] + T1[1] + T1[2] + bv;
        float y11 = T1[1] - T1[2] - T1[3] + bv;

        int ty = tile >> 5, tx = tile & 31;
        int p0 = (ty << 7) + (tx << 1);
        y[p0]      = y00;
        y[p0 + 1]  = y01;
        y[p0 + 64] = y10;
        y[p0 + 65] = y11;
        mx = fmaxf(mx, fmaxf(fmaxf(fabsf(y00), fabsf(y01)),
                             fmaxf(fabsf(y10), fabsf(y11))));
    }
    red[t] = mx; __syncthreads();
    for (int s = 128; s > 0; s >>= 1) {
        if (t < s) red[t] = fmaxf(red[t], red[t + s]);
        __syncthreads();
    }
    float sc = red[0] / QMAX;
    if (t == 0) d_srsc[n * GC + g] = sc;
    float inv = (sc > 0.f) ? 1.f / sc : 0.f;

    size_t base = ((size_t)n * GC + g) * HW;
#pragma unroll 1
    for (int i = t * 4; i < 4096; i += 1024) {
        char4 h4, l4;
        int8_t qh, ql;
        q15(y[i + 0], inv, qh, ql); h4.x = qh; l4.x = ql;
        q15(y[i + 1], inv, qh, ql); h4.y = qh; l4.y = ql;
        q15(y[i + 2], inv, qh, ql); h4.z = qh; l4.z = ql;
        q15(y[i + 3], inv, qh, ql); h4.w = qh; l4.w = ql;
        *(char4*)(d_srqh + base + i) = h4;
        *(char4*)(d_srql + base + i) = l4;
    }
}

// ============================================================================
// GEMM2: cs (balanced u16) x sr (q15), 4-stage single-barrier pipeline.
// ============================================================================
__global__ __launch_bounds__(512, 1) void gemm2_s8_kernel(float* __restrict__ of)
{
    extern __shared__ char smraw[];
    const uint32_t smb = smem_u32(smraw);
    const int tid  = threadIdx.x;
    const int wid  = tid >> 5;
    const int lane = tid & 31;
    const int nn0  = blockIdx.x * 128;
    const int m0   = blockIdx.y * 128;
    const int nz   = blockIdx.z;
    const int nk   = HW / 64;

    const int cr = tid >> 2;
    const int cc = (tid & 3) * 16;
    const char* pAh = (const char*)d_csqh;
    const char* pAl = (const char*)d_csql;
    const char* pBh = (const char*)d_srqh;
    const char* pBl = (const char*)d_srql;
    const size_t aoff = (size_t)(m0 + cr) * HW + (size_t)nz * HW * HW + cc;
    const size_t boff = (size_t)(nn0 + cr) * HW + (size_t)nz * GC * HW + cc;
    const uint32_t dd = (uint32_t)(cr * 80 + cc);

#define ISSUE2(t) do {                                               \
        uint32_t sb_ = smb + ((t) % NSTG) * STG8;                    \
        size_t kb_ = (size_t)(t) * 64;                               \
        CP16(sb_ + dd,             pAh + aoff + kb_);                \
        CP16(sb_ + TILE8 + dd,     pAl + aoff + kb_);                \
        CP16(sb_ + 2*TILE8 + dd,   pBh + boff + kb_);                \
        CP16(sb_ + 3*TILE8 + dd,   pBl + boff + kb_);                \
    } while (0)

    const int wm = wid >> 2;
    const int wn = wid & 3;
    const uint32_t aoffL = (uint32_t)((wm * 32 + (lane & 15)) * 80 + (lane >> 4) * 16);
    const uint32_t boffL = (uint32_t)((wn * 32 + ((lane >> 4) << 3) + (lane & 7)) * 80
                                      + ((lane >> 3) & 1) * 16);

    int acc1[2][4][4], acc2[2][4][4];
#pragma unroll
    for (int i = 0; i < 2; i++)
#pragma unroll
        for (int j = 0; j < 4; j++)
#pragma unroll
            for (int r = 0; r < 4; r++) { acc1[i][j][r] = 0; acc2[i][j][r] = 0; }

    ISSUE2(0); CP_COMMIT();
    ISSUE2(1); CP_COMMIT();
    ISSUE2(2); CP_COMMIT();

    for (int t = 0; t < nk; t++) {
        CP_WAIT2();
        __syncthreads();
        if (t + 3 < nk) ISSUE2(t + 3);
        CP_COMMIT();

        const uint32_t sb  = smb + (t % NSTG) * STG8;
        const uint32_t AhT = sb,             AlT = sb + TILE8;
        const uint32_t BhT = sb + 2 * TILE8, BlT = sb + 3 * TILE8;

#pragma unroll
        for (int ks = 0; ks < 2; ks++) {
            const uint32_t kb = ks * 32;
            uint32_t aH[8], aL[8], bH[8], bL[8];
            LDSM4(aH,     AhT + aoffL + kb);
            LDSM4(aH + 4, AhT + aoffL + 16 * 80 + kb);
            LDSM4(aL,     AlT + aoffL + kb);
            LDSM4(aL + 4, AlT + aoffL + 16 * 80 + kb);
            LDSM4(bH,     BhT + boffL + kb);
            LDSM4(bH + 4, BhT + boffL + 16 * 80 + kb);
            LDSM4(bL,     BlT + boffL + kb);
            LDSM4(bL + 4, BlT + boffL + 16 * 80 + kb);
#pragma unroll
            for (int i = 0; i < 2; i++)
#pragma unroll
                for (int j = 0; j < 4; j++) {
                    MMAU8(acc1[i][j], aH + 4 * i, bH[2 * j], bH[2 * j + 1]);
                    MMAU8(acc2[i][j], aH + 4 * i, bL[2 * j], bL[2 * j + 1]);
                    MMAS8(acc2[i][j], aL + 4 * i, bH[2 * j], bH[2 * j + 1]);
                }
        }
    }
    __syncthreads();                          // protect stages before smf reuse

    float* smf = (float*)smraw;              // [128][129]
    const float* asb = d_cssc + (size_t)nz * HW + m0;
    const float* wsb = d_srsc + (size_t)nz * GC + nn0;
#pragma unroll
    for (int i = 0; i < 2; i++) {
        int m = wm * 32 + i * 16 + (lane >> 2);
        float sa0 = asb[m], sa1 = asb[m + 8];
#pragma unroll
        for (int j = 0; j < 4; j++) {
            int col = wn * 32 + j * 8 + 2 * (lane & 3);
            float w0 = wsb[col], w1 = wsb[col + 1];
            float v0 = fmaf(65536.f, (float)acc1[i][j][0], 256.f * (float)acc2[i][j][0]);
            float v1 = fmaf(65536.f, (float)acc1[i][j][1], 256.f * (float)acc2[i][j][1]);
            float v2 = fmaf(65536.f, (float)acc1[i][j][2], 256.f * (float)acc2[i][j][2]);
            float v3 = fmaf(65536.f, (float)acc1[i][j][3], 256.f * (float)acc2[i][j][3]);
            smf[m * 129 + col]           = sa0 * w0 * v0;
            smf[m * 129 + col + 1]       = sa0 * w1 * v1;
            smf[(m + 8) * 129 + col]     = sa1 * w0 * v2;
            smf[(m + 8) * 129 + col + 1] = sa1 * w1 * v3;
        }
    }
    __syncthreads();

    const int g = tid >> 2;
    const int q = tid & 3;
    const size_t orow = ((size_t)nz * GC + nn0 + g) * HW + m0 + q * 32;
#pragma unroll 1
    for (int pc = 0; pc < 8; pc++) {
        float4 v;
        v.x = smf[(q * 32 + pc * 4 + 0) * 129 + g];
        v.y = smf[(q * 32 + pc * 4 + 1) * 129 + g];
        v.z = smf[(q * 32 + pc * 4 + 2) * 129 + g];
        v.w = smf[(q * 32 + pc * 4 + 3) * 129 + g];
        *(float4*)(of + orow + pc * 4) = v;
    }
#undef ISSUE2
}

// ============================================================================
// launch
// ============================================================================
extern "C" void kernel_launch(void* const* d_in, const int* in_sizes, int n_in,
                              void* d_out, int out_size)
{
    const float* c    = (const float*)d_in[0];
    const float* s    = (const float*)d_in[1];
    const float* grid = (const float*)d_in[2];
    const float* wc1  = (const float*)d_in[3];
    const float* bc1  = (const float*)d_in[4];
    const float* wc2  = (const float*)d_in[5];
    const float* bc2  = (const float*)d_in[6];
    const float* ws1  = (const float*)d_in[7];
    const float* bs1  = (const float*)d_in[8];
    const float* ws2  = (const float*)d_in[9];
    const float* bs2  = (const float*)d_in[10];
    const float* wsr  = (const float*)d_in[11];
    const float* bsr  = (const float*)d_in[12];
    float* out = (float*)d_out;

    float *h1, *c1, *s1;
    cudaGetSymbolAddress((void**)&h1, d_h1);
    cudaGetSymbolAddress((void**)&c1, d_c1);
    cudaGetSymbolAddress((void**)&s1, d_s1);
    float* h1b = h1 + 16 * 128 * 128;  // second half for style branch temp
    // NOTE: d_h1 sized 2*16*128*128; branch temps use disjoint halves? No —
    // both branches need [2,16,128,128]. Use separate regions:
    // c-branch temp = d_h1 (full), s-branch writes to d_A-free space? Simpler:
    // keep full-size temp per branch via d_h1 for c and reuse d_mt scratch
    // for s (d_mt is 268MB, unused until gemm_wino).
    float* hs;
    cudaGetSymbolAddress((void**)&hs, d_mt);

    cudaFuncSetAttribute(gemm_wino_kernel,
                         cudaFuncAttributeMaxDynamicSharedMemorySize, SMEM_DYN);
    cudaFuncSetAttribute(gemm2_s8_kernel,
                         cudaFuncAttributeMaxDynamicSharedMemorySize, SMEM_DYN);
    cudaFuncSetAttribute(xmax2_kernel,
                         cudaFuncAttributeMaxDynamicSharedMemorySize, SMEM_XM);
    cudaFuncSetAttribute(xq2_kernel,
                         cudaFuncAttributeMaxDynamicSharedMemorySize, SMEM_XQ);

    // branches: both in one launch per layer (blockIdx.y = branch)
    {
        dim3 g1((2*16*128*128 + 255) / 256, 2);
        conv16_dual_kernel<<<g1, 256>>>(c, wc1, bc1, h1, s, ws1, bs1, hs,
                                        256, 128, 2, 1);
        dim3 g2((2*16*64*64 + 255) / 256, 2);
        conv16_dual_kernel<<<g2, 256>>>(h1, wc2, bc2, c1, hs, ws2, bs2, s1,
                                        128, 64, 2, 0);
    }

    // fused affinity + softmax + balanced-u16 quantize
    {
        dim3 g(HW / 8, 2);
        affsoft_kernel<<<g, 256>>>(c1, s1);
    }

    // winograd operand prep
    wprep_kernel<<<GC, 256>>>(wsr);
    zeroxsc_kernel<<<(2 * NT * 16 + 255) / 256, 256>>>();
    xmax2_kernel<<<2 * 32 * 34, 256, SMEM_XM>>>(grid);
    xscconv_kernel<<<(2 * NT * 16 + 255) / 256, 256>>>();
    xq2_kernel<<<2 * 32 * 34, 256, SMEM_XQ>>>(grid);

    // GEMM1 + inverse transform / quantize
    {
        dim3 g(GC / 128, NT / 128, 32);
        gemm_wino_kernel<<<g, 512, SMEM_DYN>>>();
    }
    outtrans_q_kernel<<<2 * GC, 256>>>(bsr);

    // GEMM2 -> fp32 out
    {
        dim3 g(GC / 128, HW / 128, 2);
        gemm2_s8_kernel<<<g, 512, SMEM_DYN>>>(out);
    }
}